// round 6
// baseline (speedup 1.0000x reference)
#include <cuda_runtime.h>
#include <cuda_bf16.h>
#include <cstdint>

#define B_ 4
#define N_ 1024
#define C_ 768
#define H_ 12
#define BN 4096
#define SCALE 0.125f

// ---------------- scratch (static device globals; no allocations) ----------
__device__ __align__(16) __nv_bfloat16 g_Qh[(size_t)B_*H_*N_*128];  // SCALE folded
__device__ __align__(16) __nv_bfloat16 g_Ql[(size_t)B_*H_*N_*128];
__device__ __align__(16) __nv_bfloat16 g_Kh[(size_t)B_*H_*N_*128];
__device__ __align__(16) __nv_bfloat16 g_Kl[(size_t)B_*H_*N_*128];
__device__ __align__(16) __nv_bfloat16 g_Vh[(size_t)B_*H_*N_*128];
__device__ __align__(16) __nv_bfloat16 g_Vl[(size_t)B_*H_*N_*128];

__device__ __align__(16) __nv_bfloat16 g_Xh[(size_t)2*BN*C_];
__device__ __align__(16) __nv_bfloat16 g_Xl[(size_t)2*BN*C_];
__device__ __align__(16) __nv_bfloat16 g_Wqh[(size_t)3*C_*C_];
__device__ __align__(16) __nv_bfloat16 g_Wql[(size_t)3*C_*C_];
__device__ __align__(16) __nv_bfloat16 g_Wph[(size_t)C_*C_];
__device__ __align__(16) __nv_bfloat16 g_Wpl[(size_t)C_*C_];
__device__ __align__(16) __nv_bfloat16 g_Oh[(size_t)2*BN*C_];
__device__ __align__(16) __nv_bfloat16 g_Ol[(size_t)2*BN*C_];

// ---------------- helpers ---------------------------------------------------
__device__ __forceinline__ uint32_t smem_u32(const void* p) {
    uint32_t a;
    asm("{ .reg .u64 t; cvta.to.shared.u64 t, %1; cvt.u32.u64 %0, t; }"
        : "=r"(a) : "l"(p));
    return a;
}
__device__ __forceinline__ uint32_t swz(uint32_t o) {   // SW128 within 128B rows
    return o ^ ((o >> 3) & 0x70);
}
__device__ __forceinline__ void cpa16(uint32_t dst, const void* src) {
    asm volatile("cp.async.cg.shared.global [%0], [%1], 16;" :: "r"(dst), "l"(src));
}
__device__ __forceinline__ void cpa_commit() {
    asm volatile("cp.async.commit_group;" ::: "memory");
}
template<int N>
__device__ __forceinline__ void cpa_wait() {
    asm volatile("cp.async.wait_group %0;" :: "n"(N) : "memory");
}
__device__ __forceinline__ void ldsm_x4(uint32_t* r, uint32_t addr) {
    asm volatile("ldmatrix.sync.aligned.m8n8.x4.shared.b16 {%0,%1,%2,%3}, [%4];"
                 : "=r"(r[0]), "=r"(r[1]), "=r"(r[2]), "=r"(r[3]) : "r"(addr));
}
__device__ __forceinline__ void ldsm_x2(uint32_t* r, uint32_t addr) {
    asm volatile("ldmatrix.sync.aligned.m8n8.x2.shared.b16 {%0,%1}, [%2];"
                 : "=r"(r[0]), "=r"(r[1]) : "r"(addr));
}
__device__ __forceinline__ void ldsm_x2_t(uint32_t* r, uint32_t addr) {
    asm volatile("ldmatrix.sync.aligned.m8n8.x2.trans.shared.b16 {%0,%1}, [%2];"
                 : "=r"(r[0]), "=r"(r[1]) : "r"(addr));
}
__device__ __forceinline__ void mma16816(float* d, const uint32_t* a, const uint32_t* b) {
    asm volatile(
        "mma.sync.aligned.m16n8k16.row.col.f32.bf16.bf16.f32 "
        "{%0,%1,%2,%3}, {%4,%5,%6,%7}, {%8,%9}, {%0,%1,%2,%3};"
        : "+f"(d[0]), "+f"(d[1]), "+f"(d[2]), "+f"(d[3])
        : "r"(a[0]), "r"(a[1]), "r"(a[2]), "r"(a[3]), "r"(b[0]), "r"(b[1]));
}
__device__ __forceinline__ uint32_t pack_bf2(float a, float b) {
    __nv_bfloat162 t = __floats2bfloat162_rn(a, b);
    return *(uint32_t*)&t;
}

// ---------------------------------------------------------------------------
// fused split kernel: fp32 -> (bf16 hi, bf16 lo) for x1, x2, Wqkv, Wproj
// grid = 3072 + 3072 + 1728 + 576 = 8448 blocks x 256 threads
// ---------------------------------------------------------------------------
#define NX4  (BN * C_ / 4)          // 786432 -> 3072 blocks
#define NWQ4 (3 * C_ * C_ / 4)      // 442368 -> 1728 blocks
#define NWP4 (C_ * C_ / 4)          // 147456 -> 576 blocks

__global__ __launch_bounds__(256) void split_all(
    const float* __restrict__ x1, const float* __restrict__ x2,
    const float* __restrict__ Wq, const float* __restrict__ Wp)
{
    int bid = blockIdx.x;
    const float* src;
    __nv_bfloat16 *hi, *lo;
    size_t off4;
    int i;
    if (bid < 3072) {
        src = x1; hi = g_Xh; lo = g_Xl; off4 = 0;
        i = bid * 256 + threadIdx.x;
    } else if (bid < 6144) {
        src = x2; hi = g_Xh; lo = g_Xl; off4 = NX4;
        i = (bid - 3072) * 256 + threadIdx.x;
    } else if (bid < 7872) {
        src = Wq; hi = g_Wqh; lo = g_Wql; off4 = 0;
        i = (bid - 6144) * 256 + threadIdx.x;
    } else {
        src = Wp; hi = g_Wph; lo = g_Wpl; off4 = 0;
        i = (bid - 7872) * 256 + threadIdx.x;
    }
    float4 v = ((const float4*)src)[i];
    __nv_bfloat16 h0 = __float2bfloat16(v.x);
    __nv_bfloat16 h1 = __float2bfloat16(v.y);
    __nv_bfloat16 h2 = __float2bfloat16(v.z);
    __nv_bfloat16 h3 = __float2bfloat16(v.w);
    __nv_bfloat16 l0 = __float2bfloat16(v.x - __bfloat162float(h0));
    __nv_bfloat16 l1 = __float2bfloat16(v.y - __bfloat162float(h1));
    __nv_bfloat16 l2 = __float2bfloat16(v.z - __bfloat162float(h2));
    __nv_bfloat16 l3 = __float2bfloat16(v.w - __bfloat162float(h3));
    size_t o = off4 + (size_t)i;
    ((__nv_bfloat162*)hi)[o*2 + 0] = __halves2bfloat162(h0, h1);
    ((__nv_bfloat162*)hi)[o*2 + 1] = __halves2bfloat162(h2, h3);
    ((__nv_bfloat162*)lo)[o*2 + 0] = __halves2bfloat162(l0, l1);
    ((__nv_bfloat162*)lo)[o*2 + 1] = __halves2bfloat162(l2, l3);
}

// ---------------------------------------------------------------------------
// mma.sync bf16x3 GEMM: 128x128 CTA tile, 512 threads (16 warps, 32x32/warp),
// cp.async 2-stage.  MODE 0: qkv -> Q/K/V hi/lo.  MODE 1: proj -> out.
// smem: 1024 + 2 x 64KB = 132096 B
// ---------------------------------------------------------------------------
__device__ __forceinline__ void gemm_issue_chunk(
    uint32_t sbase,
    const __nv_bfloat16* Ah, const __nv_bfloat16* Al,
    const __nv_bfloat16* Bh, const __nv_bfloat16* Bl,
    int m0, int c0, int kc, int tid)
{
#pragma unroll
    for (int it = 0; it < 2; it++) {
        int idx = tid + it * 512;          // 0..1023 : 16B units of one 16KB plane
        int r = idx >> 3, u = idx & 7;
        uint32_t so = swz((uint32_t)(r * 128 + u * 16));
        cpa16(sbase +     0 + so, Ah + (size_t)(m0 + r) * C_ + kc + u * 8);
        cpa16(sbase + 16384 + so, Al + (size_t)(m0 + r) * C_ + kc + u * 8);
        cpa16(sbase + 32768 + so, Bh + (size_t)(c0 + r) * C_ + kc + u * 8);
        cpa16(sbase + 49152 + so, Bl + (size_t)(c0 + r) * C_ + kc + u * 8);
    }
    cpa_commit();
}

template<int MODE>
__global__ __launch_bounds__(512) void tc_gemm(const float* __restrict__ bias,
                                               float* __restrict__ outp)
{
    extern __shared__ char sm[];
    const uint32_t sb = smem_u32(sm) + 1024;
    const int tid = threadIdx.x;
    const int lane = tid & 31, wid = tid >> 5;
    const int wm = wid & 3, wn = wid >> 2;     // 4 x 4 warp grid, 32x32 each
    const int stream = blockIdx.z;
    const int m0 = blockIdx.y * 128;
    const int c0 = blockIdx.x * 128;

    const __nv_bfloat16* __restrict__ Ah =
        (MODE==0 ? g_Xh : g_Oh) + (size_t)stream * BN * C_;
    const __nv_bfloat16* __restrict__ Al =
        (MODE==0 ? g_Xl : g_Ol) + (size_t)stream * BN * C_;
    const __nv_bfloat16* __restrict__ Bh = MODE==0 ? g_Wqh : g_Wph;
    const __nv_bfloat16* __restrict__ Bl = MODE==0 ? g_Wql : g_Wpl;

    float acc[2][4][4];
#pragma unroll
    for (int i = 0; i < 2; i++)
#pragma unroll
        for (int j = 0; j < 4; j++)
#pragma unroll
            for (int k = 0; k < 4; k++) acc[i][j][k] = 0.f;

    const int a_r  = wm*32 + (lane & 15);
    const int a_cb = (lane >> 4) * 16;
    const int b_r  = wn*32 + (lane & 7);
    const int b_cb = ((lane >> 3) & 1) * 16;

    const int NCH = C_ / 64;   // 12
    gemm_issue_chunk(sb + 0, Ah, Al, Bh, Bl, m0, c0, 0, tid);

    for (int ch = 0; ch < NCH; ch++) {
        const uint32_t stb = (uint32_t)(ch & 1) * 65536u;
        cpa_wait<0>();
        __syncthreads();
        if (ch + 1 < NCH)
            gemm_issue_chunk(sb + ((ch + 1) & 1) * 65536u,
                             Ah, Al, Bh, Bl, m0, c0, (ch + 1) * 64, tid);

#pragma unroll
        for (int k16 = 0; k16 < 4; k16++) {
            uint32_t bh[4][2], bl[4][2];
#pragma unroll
            for (int nf = 0; nf < 4; nf++) {
                uint32_t bo = stb + 32768 + swz((uint32_t)((b_r + nf*8) * 128 + k16*32 + b_cb));
                ldsm_x2(bh[nf], sb + bo);
                ldsm_x2(bl[nf], sb + bo + 16384);
            }
#pragma unroll
            for (int mf = 0; mf < 2; mf++) {
                uint32_t ao = stb + swz((uint32_t)((a_r + mf*16) * 128 + k16*32 + a_cb));
                uint32_t ah[4], al[4];
                ldsm_x4(ah, sb + ao);
                ldsm_x4(al, sb + ao + 16384);
#pragma unroll
                for (int nf = 0; nf < 4; nf++) {
                    mma16816(acc[mf][nf], ah, bh[nf]);
                    mma16816(acc[mf][nf], ah, bl[nf]);
                    mma16816(acc[mf][nf], al, bh[nf]);
                }
            }
        }
    }
    __syncthreads();   // done reading tiles; reuse smem as Osm

    float* Osm = (float*)(sm + 1024);      // [128][132]
#pragma unroll
    for (int mf = 0; mf < 2; mf++) {
#pragma unroll
        for (int nf = 0; nf < 4; nf++) {
            int row = wm*32 + mf*16 + (lane >> 2);
            int col = wn*32 + nf*8 + (lane & 3)*2;
            Osm[row       * 132 + col    ] = acc[mf][nf][0];
            Osm[row       * 132 + col + 1] = acc[mf][nf][1];
            Osm[(row + 8) * 132 + col    ] = acc[mf][nf][2];
            Osm[(row + 8) * 132 + col + 1] = acc[mf][nf][3];
        }
    }
    __syncthreads();

#pragma unroll
    for (int it = 0; it < 8; it++) {
        int idx = tid + it * 512;
        int r = idx >> 5, j4 = idx & 31;
        float4 v = *(float4*)&Osm[r * 132 + j4 * 4];
        float4 bb = *(const float4*)&bias[c0 + j4 * 4];
        v.x += bb.x; v.y += bb.y; v.z += bb.z; v.w += bb.w;
        int m = m0 + r;
        if (MODE == 0) {
            int cg = c0 + j4 * 4;
            int s = cg / C_;
            int rem = cg - s * C_;
            int h = rem >> 6, d = rem & 63;
            if (s == 0) { v.x *= SCALE; v.y *= SCALE; v.z *= SCALE; v.w *= SCALE; }
            __nv_bfloat16 h0 = __float2bfloat16(v.x);
            __nv_bfloat16 h1 = __float2bfloat16(v.y);
            __nv_bfloat16 h2 = __float2bfloat16(v.z);
            __nv_bfloat16 h3 = __float2bfloat16(v.w);
            uint2 hv, lv;
            hv.x = pack_bf2(v.x, v.y); hv.y = pack_bf2(v.z, v.w);
            lv.x = pack_bf2(v.x - __bfloat162float(h0), v.y - __bfloat162float(h1));
            lv.y = pack_bf2(v.z - __bfloat162float(h2), v.w - __bfloat162float(h3));
            __nv_bfloat16* bufh = (s == 0) ? g_Qh : (s == 1) ? g_Kh : g_Vh;
            __nv_bfloat16* bufl = (s == 0) ? g_Ql : (s == 1) ? g_Kl : g_Vl;
            int b = m >> 10, n = m & 1023;
            size_t base = ((size_t)(b * H_ + h) * N_ + n) * 128 + stream * 64 + d;
            *(uint2*)&bufh[base] = hv;
            *(uint2*)&bufl[base] = lv;
        } else {
            float* Y = outp + (size_t)stream * BN * C_;
            *(float4*)&Y[(size_t)m * C_ + c0 + j4 * 4] = v;
        }
    }
}

// ---------------------------------------------------------------------------
// flash attention on HMMA, 512 threads (16 warps), bf16x3, cp.async 2-stage.
// Warp grid: wr = w&3 (16 q-rows), wc = w>>2 (S: 16 cols; PV: 32 d-cols).
// smem: 2 x 64KB K/V stages + Q 32KB + P 16KB... layout below = 182272 B
// ---------------------------------------------------------------------------
#define STG_ 65536u
#define KH_ 0u
#define KL_ 16384u
#define VH_ 32768u
#define VL_ 49152u
#define QH_ 131072u
#define QL_ 147456u
#define PH_ 163840u
#define PL_ 172032u
#define STAT_ 180224u

__device__ __forceinline__ void attn_issue_kv(
    uint32_t sb, uint32_t stb,
    const __nv_bfloat16* kh_g, const __nv_bfloat16* kl_g,
    const __nv_bfloat16* vh_g, const __nv_bfloat16* vl_g, int tid)
{
#pragma unroll
    for (int it = 0; it < 2; it++) {
        int idx = tid + it * 512;
        int row = idx >> 4, ch = idx & 15;
        int src = row * 128 + ch * 8;
        uint32_t dst = stb + (uint32_t)(ch >> 3) * 8192 + swz((uint32_t)(row * 128 + (ch & 7) * 16));
        cpa16(sb + KH_ + dst, kh_g + src);
        cpa16(sb + KL_ + dst, kl_g + src);
        cpa16(sb + VH_ + dst, vh_g + src);
        cpa16(sb + VL_ + dst, vl_g + src);
    }
    cpa_commit();
}

__global__ __launch_bounds__(512, 1) void attn_mma()
{
    extern __shared__ char sm[];
    const uint32_t sb = smem_u32(sm);
    float* pmf = (float*)(sm + STAT_);          // [4][64]
    float* psf = pmf + 256;                     // [4][64]

    const int tid = threadIdx.x;
    const int lane = tid & 31, w = tid >> 5;
    const int wr = w & 3, wc = w >> 2;
    const int qt = blockIdx.x, bh = blockIdx.y;
    const int b = bh / H_, h = bh - b * H_;
    const size_t kvb = (size_t)bh * N_ * 128;
    const int r0 = wr * 16 + (lane >> 2);

    const __nv_bfloat16* kh_g = g_Kh + kvb;
    const __nv_bfloat16* kl_g = g_Kl + kvb;
    const __nv_bfloat16* vh_g = g_Vh + kvb;
    const __nv_bfloat16* vl_g = g_Vl + kvb;

    attn_issue_kv(sb, 0, kh_g, kl_g, vh_g, vl_g, tid);

    // ---- load Q tile ----
    {
        const __nv_bfloat16* qh_g = g_Qh + kvb + (size_t)qt * 64 * 128;
        const __nv_bfloat16* ql_g = g_Ql + kvb + (size_t)qt * 64 * 128;
#pragma unroll
        for (int it = 0; it < 2; it++) {
            int idx = tid + it * 512;
            int row = idx >> 4, ch = idx & 15;
            uint32_t dst = (uint32_t)(ch >> 3) * 8192 + swz((uint32_t)(row * 128 + (ch & 7) * 16));
            *(uint4*)(sm + QH_ + dst) = *(const uint4*)(qh_g + row * 128 + ch * 8);
            *(uint4*)(sm + QL_ + dst) = *(const uint4*)(ql_g + row * 128 + ch * 8);
        }
    }

    float m0r = -1e30f, m1r = -1e30f, l0r = 0.f, l1r = 0.f;
    float o[4][4];
#pragma unroll
    for (int i = 0; i < 4; i++)
#pragma unroll
        for (int j = 0; j < 4; j++) o[i][j] = 0.f;

    for (int kt = 0; kt < 16; kt++) {
        const uint32_t stb = (uint32_t)(kt & 1) * STG_;
        cpa_wait<0>();
        __syncthreads();
        if (kt < 15)
            attn_issue_kv(sb, (uint32_t)((kt + 1) & 1) * STG_,
                          kh_g + (size_t)(kt + 1) * 64 * 128,
                          kl_g + (size_t)(kt + 1) * 64 * 128,
                          vh_g + (size_t)(kt + 1) * 64 * 128,
                          vl_g + (size_t)(kt + 1) * 64 * 128, tid);

        // ---- S = Q K^T : warp computes 16 rows x 16 cols, k=128 ----
        float sacc[2][4];
#pragma unroll
        for (int i = 0; i < 2; i++)
#pragma unroll
            for (int j = 0; j < 4; j++) sacc[i][j] = 0.f;

#pragma unroll
        for (int k16 = 0; k16 < 8; k16++) {
            uint32_t pl = (uint32_t)(k16 >> 2) * 8192;
            uint32_t ao = pl + swz((uint32_t)((wr*16 + (lane & 15)) * 128 + (k16 & 3)*32 + (lane >> 4)*16));
            uint32_t ah[4], al[4];
            ldsm_x4(ah, sb + QH_ + ao);
            ldsm_x4(al, sb + QL_ + ao);
            uint32_t bcb = (uint32_t)((k16 & 3)*32 + ((lane >> 3) & 1)*16);
#pragma unroll
            for (int nf = 0; nf < 2; nf++) {
                uint32_t bo = stb + pl + swz((uint32_t)((wc*16 + nf*8 + (lane & 7)) * 128) + bcb);
                uint32_t bh2[2], bl2[2];
                ldsm_x2(bh2, sb + KH_ + bo);
                ldsm_x2(bl2, sb + KL_ + bo);
                mma16816(sacc[nf], ah, bh2);
                mma16816(sacc[nf], ah, bl2);
                mma16816(sacc[nf], al, bh2);
            }
        }

        // ---- online softmax (register m/l, 2 smem exchanges) ----
        float pm0 = fmaxf(fmaxf(sacc[0][0], sacc[0][1]), fmaxf(sacc[1][0], sacc[1][1]));
        float pm1 = fmaxf(fmaxf(sacc[0][2], sacc[0][3]), fmaxf(sacc[1][2], sacc[1][3]));
        pm0 = fmaxf(pm0, __shfl_xor_sync(0xffffffffu, pm0, 1));
        pm0 = fmaxf(pm0, __shfl_xor_sync(0xffffffffu, pm0, 2));
        pm1 = fmaxf(pm1, __shfl_xor_sync(0xffffffffu, pm1, 1));
        pm1 = fmaxf(pm1, __shfl_xor_sync(0xffffffffu, pm1, 2));
        if ((lane & 3) == 0) {
            pmf[wc*64 + r0]     = pm0;
            pmf[wc*64 + r0 + 8] = pm1;
        }
        __syncthreads();
        float mn0 = fmaxf(fmaxf(m0r, fmaxf(pmf[r0], pmf[64 + r0])),
                          fmaxf(pmf[128 + r0], pmf[192 + r0]));
        float mn1 = fmaxf(fmaxf(m1r, fmaxf(pmf[r0 + 8], pmf[64 + r0 + 8])),
                          fmaxf(pmf[128 + r0 + 8], pmf[192 + r0 + 8]));
        float f0 = __expf(m0r - mn0);
        float f1 = __expf(m1r - mn1);
        m0r = mn0; m1r = mn1;

        float sum0 = 0.f, sum1 = 0.f;
        uint32_t cb2 = (uint32_t)(wc*32 + (lane & 3)*4);
#pragma unroll
        for (int nf = 0; nf < 2; nf++) {
            float p0 = __expf(sacc[nf][0] - mn0);
            float p1 = __expf(sacc[nf][1] - mn0);
            float p2 = __expf(sacc[nf][2] - mn1);
            float p3 = __expf(sacc[nf][3] - mn1);
            sum0 += p0 + p1; sum1 += p2 + p3;
            __nv_bfloat16 h0 = __float2bfloat16(p0);
            __nv_bfloat16 h1 = __float2bfloat16(p1);
            __nv_bfloat16 h2 = __float2bfloat16(p2);
            __nv_bfloat16 h3 = __float2bfloat16(p3);
            uint32_t c = cb2 + (uint32_t)nf*16;
            *(uint32_t*)(sm + PH_ + swz((uint32_t)(r0*128) + c))     = pack_bf2(p0, p1);
            *(uint32_t*)(sm + PL_ + swz((uint32_t)(r0*128) + c))     =
                pack_bf2(p0 - __bfloat162float(h0), p1 - __bfloat162float(h1));
            *(uint32_t*)(sm + PH_ + swz((uint32_t)((r0+8)*128) + c)) = pack_bf2(p2, p3);
            *(uint32_t*)(sm + PL_ + swz((uint32_t)((r0+8)*128) + c)) =
                pack_bf2(p2 - __bfloat162float(h2), p3 - __bfloat162float(h3));
        }
        sum0 += __shfl_xor_sync(0xffffffffu, sum0, 1);
        sum0 += __shfl_xor_sync(0xffffffffu, sum0, 2);
        sum1 += __shfl_xor_sync(0xffffffffu, sum1, 1);
        sum1 += __shfl_xor_sync(0xffffffffu, sum1, 2);
        if ((lane & 3) == 0) {
            psf[wc*64 + r0]     = sum0;
            psf[wc*64 + r0 + 8] = sum1;
        }
        __syncthreads();   // P + psf visible
        l0r = l0r * f0 + psf[r0]     + psf[64 + r0] + psf[128 + r0] + psf[192 + r0];
        l1r = l1r * f1 + psf[r0 + 8] + psf[64 + r0 + 8] + psf[128 + r0 + 8] + psf[192 + r0 + 8];

        // ---- O = O*fac + P V : warp computes 16 rows x 32 d-cols ----
#pragma unroll
        for (int nf = 0; nf < 4; nf++) {
            o[nf][0] *= f0; o[nf][1] *= f0;
            o[nf][2] *= f1; o[nf][3] *= f1;
        }
        uint32_t vplane = (uint32_t)(wc >> 1) * 8192;
        uint32_t vcolb  = (uint32_t)(wc & 1) * 64;
#pragma unroll
        for (int k16p = 0; k16p < 4; k16p++) {
            uint32_t po = swz((uint32_t)((wr*16 + (lane & 15)) * 128 + k16p*32 + (lane >> 4)*16));
            uint32_t pah[4], pal[4];
            ldsm_x4(pah, sb + PH_ + po);
            ldsm_x4(pal, sb + PL_ + po);
            uint32_t vrow = (uint32_t)((k16p*16 + (lane & 15)) * 128);
#pragma unroll
            for (int nf = 0; nf < 4; nf++) {
                uint32_t vo = stb + vplane + swz(vrow + vcolb + (uint32_t)nf*16);
                uint32_t vh2[2], vl2[2];
                ldsm_x2_t(vh2, sb + VH_ + vo);
                ldsm_x2_t(vl2, sb + VL_ + vo);
                mma16816(o[nf], pah, vh2);
                mma16816(o[nf], pah, vl2);
                mma16816(o[nf], pal, vh2);
            }
        }
    }

    // ---- epilogue: normalize, split bf16 hi/lo, write O (stream = wc>>1) ----
    float li0 = 1.f / l0r, li1 = 1.f / l1r;
    const int strm = wc >> 1;
    size_t srow = (size_t)strm * BN * C_ + (size_t)(b * N_ + qt * 64) * C_ + h * 64;
#pragma unroll
    for (int nf = 0; nf < 4; nf++) {
        int hd = (wc & 1)*32 + nf*8 + (lane & 3)*2;
        size_t i0 = srow + (size_t)r0 * C_ + hd;
        size_t i1 = srow + (size_t)(r0 + 8) * C_ + hd;
        float v0 = o[nf][0]*li0, v1 = o[nf][1]*li0;
        float v2 = o[nf][2]*li1, v3 = o[nf][3]*li1;
        __nv_bfloat16 h0 = __float2bfloat16(v0);
        __nv_bfloat16 h1 = __float2bfloat16(v1);
        __nv_bfloat16 h2 = __float2bfloat16(v2);
        __nv_bfloat16 h3 = __float2bfloat16(v3);
        *(uint32_t*)&g_Oh[i0] = pack_bf2(v0, v1);
        *(uint32_t*)&g_Ol[i0] = pack_bf2(v0 - __bfloat162float(h0), v1 - __bfloat162float(h1));
        *(uint32_t*)&g_Oh[i1] = pack_bf2(v2, v3);
        *(uint32_t*)&g_Ol[i1] = pack_bf2(v2 - __bfloat162float(h2), v3 - __bfloat162float(h3));
    }
}

// ---------------------------------------------------------------------------
extern "C" void kernel_launch(void* const* d_in, const int* in_sizes, int n_in,
                              void* d_out, int out_size)
{
    (void)in_sizes; (void)n_in; (void)out_size;
    const float* x1    = (const float*)d_in[0];
    const float* x2    = (const float*)d_in[1];
    const float* Wqkv  = (const float*)d_in[2];
    const float* bqkv  = (const float*)d_in[3];
    const float* Wproj = (const float*)d_in[4];
    const float* bproj = (const float*)d_in[5];
    float* out = (float*)d_out;

    split_all<<<8448, 256>>>(x1, x2, Wqkv, Wproj);

    const int gemm_smem = 1024 + 2 * 65536;   // 132096
    cudaFuncSetAttribute(tc_gemm<0>, cudaFuncAttributeMaxDynamicSharedMemorySize, gemm_smem);
    tc_gemm<0><<<dim3(18, 32, 2), 512, gemm_smem>>>(bqkv, nullptr);

    const int attn_smem = 182272;
    cudaFuncSetAttribute(attn_mma, cudaFuncAttributeMaxDynamicSharedMemorySize, attn_smem);
    attn_mma<<<dim3(16, 48), 512, attn_smem>>>();

    cudaFuncSetAttribute(tc_gemm<1>, cudaFuncAttributeMaxDynamicSharedMemorySize, gemm_smem);
    tc_gemm<1><<<dim3(6, 32, 2), 512, gemm_smem>>>(bproj, out);
}

// round 7
// speedup vs baseline: 1.1576x; 1.1576x over previous
#include <cuda_runtime.h>
#include <cuda_bf16.h>
#include <cstdint>

#define B_ 4
#define N_ 1024
#define C_ 768
#define H_ 12
#define BN 4096
#define SCALE 0.125f

// ---------------- scratch (static device globals; no allocations) ----------
__device__ __align__(16) __nv_bfloat16 g_Qh[(size_t)B_*H_*N_*128];  // SCALE folded
__device__ __align__(16) __nv_bfloat16 g_Ql[(size_t)B_*H_*N_*128];
__device__ __align__(16) __nv_bfloat16 g_Kh[(size_t)B_*H_*N_*128];
__device__ __align__(16) __nv_bfloat16 g_Kl[(size_t)B_*H_*N_*128];
__device__ __align__(16) __nv_bfloat16 g_Vh[(size_t)B_*H_*N_*128];
__device__ __align__(16) __nv_bfloat16 g_Vl[(size_t)B_*H_*N_*128];

__device__ __align__(16) __nv_bfloat16 g_Xh[(size_t)2*BN*C_];
__device__ __align__(16) __nv_bfloat16 g_Xl[(size_t)2*BN*C_];
__device__ __align__(16) __nv_bfloat16 g_Wqh[(size_t)3*C_*C_];
__device__ __align__(16) __nv_bfloat16 g_Wql[(size_t)3*C_*C_];
__device__ __align__(16) __nv_bfloat16 g_Wph[(size_t)C_*C_];
__device__ __align__(16) __nv_bfloat16 g_Wpl[(size_t)C_*C_];
__device__ __align__(16) __nv_bfloat16 g_Oh[(size_t)2*BN*C_];
__device__ __align__(16) __nv_bfloat16 g_Ol[(size_t)2*BN*C_];

// ---------------- helpers ---------------------------------------------------
__device__ __forceinline__ uint32_t smem_u32(const void* p) {
    uint32_t a;
    asm("{ .reg .u64 t; cvta.to.shared.u64 t, %1; cvt.u32.u64 %0, t; }"
        : "=r"(a) : "l"(p));
    return a;
}
__device__ __forceinline__ uint32_t swz(uint32_t o) {   // SW128 within 128B rows
    return o ^ ((o >> 3) & 0x70);
}
__device__ __forceinline__ void cpa16(uint32_t dst, const void* src) {
    asm volatile("cp.async.cg.shared.global [%0], [%1], 16;" :: "r"(dst), "l"(src));
}
__device__ __forceinline__ void cpa_commit() {
    asm volatile("cp.async.commit_group;" ::: "memory");
}
template<int N>
__device__ __forceinline__ void cpa_wait() {
    asm volatile("cp.async.wait_group %0;" :: "n"(N) : "memory");
}
__device__ __forceinline__ void ldsm_x4(uint32_t* r, uint32_t addr) {
    asm volatile("ldmatrix.sync.aligned.m8n8.x4.shared.b16 {%0,%1,%2,%3}, [%4];"
                 : "=r"(r[0]), "=r"(r[1]), "=r"(r[2]), "=r"(r[3]) : "r"(addr));
}
__device__ __forceinline__ void ldsm_x2(uint32_t* r, uint32_t addr) {
    asm volatile("ldmatrix.sync.aligned.m8n8.x2.shared.b16 {%0,%1}, [%2];"
                 : "=r"(r[0]), "=r"(r[1]) : "r"(addr));
}
__device__ __forceinline__ void ldsm_x2_t(uint32_t* r, uint32_t addr) {
    asm volatile("ldmatrix.sync.aligned.m8n8.x2.trans.shared.b16 {%0,%1}, [%2];"
                 : "=r"(r[0]), "=r"(r[1]) : "r"(addr));
}
__device__ __forceinline__ void mma16816(float* d, const uint32_t* a, const uint32_t* b) {
    asm volatile(
        "mma.sync.aligned.m16n8k16.row.col.f32.bf16.bf16.f32 "
        "{%0,%1,%2,%3}, {%4,%5,%6,%7}, {%8,%9}, {%0,%1,%2,%3};"
        : "+f"(d[0]), "+f"(d[1]), "+f"(d[2]), "+f"(d[3])
        : "r"(a[0]), "r"(a[1]), "r"(a[2]), "r"(a[3]), "r"(b[0]), "r"(b[1]));
}
__device__ __forceinline__ uint32_t pack_bf2(float a, float b) {
    __nv_bfloat162 t = __floats2bfloat162_rn(a, b);
    return *(uint32_t*)&t;
}

// ---------------------------------------------------------------------------
// fused split kernel: fp32 -> (bf16 hi, bf16 lo) for x1, x2, Wqkv, Wproj
// ---------------------------------------------------------------------------
#define NX4  (BN * C_ / 4)          // 786432 -> 3072 blocks

__global__ __launch_bounds__(256) void split_all(
    const float* __restrict__ x1, const float* __restrict__ x2,
    const float* __restrict__ Wq, const float* __restrict__ Wp)
{
    int bid = blockIdx.x;
    const float* src;
    __nv_bfloat16 *hi, *lo;
    size_t off4;
    int i;
    if (bid < 3072) {
        src = x1; hi = g_Xh; lo = g_Xl; off4 = 0;
        i = bid * 256 + threadIdx.x;
    } else if (bid < 6144) {
        src = x2; hi = g_Xh; lo = g_Xl; off4 = NX4;
        i = (bid - 3072) * 256 + threadIdx.x;
    } else if (bid < 7872) {
        src = Wq; hi = g_Wqh; lo = g_Wql; off4 = 0;
        i = (bid - 6144) * 256 + threadIdx.x;
    } else {
        src = Wp; hi = g_Wph; lo = g_Wpl; off4 = 0;
        i = (bid - 7872) * 256 + threadIdx.x;
    }
    float4 v = ((const float4*)src)[i];
    __nv_bfloat16 h0 = __float2bfloat16(v.x);
    __nv_bfloat16 h1 = __float2bfloat16(v.y);
    __nv_bfloat16 h2 = __float2bfloat16(v.z);
    __nv_bfloat16 h3 = __float2bfloat16(v.w);
    __nv_bfloat16 l0 = __float2bfloat16(v.x - __bfloat162float(h0));
    __nv_bfloat16 l1 = __float2bfloat16(v.y - __bfloat162float(h1));
    __nv_bfloat16 l2 = __float2bfloat16(v.z - __bfloat162float(h2));
    __nv_bfloat16 l3 = __float2bfloat16(v.w - __bfloat162float(h3));
    size_t o = off4 + (size_t)i;
    ((__nv_bfloat162*)hi)[o*2 + 0] = __halves2bfloat162(h0, h1);
    ((__nv_bfloat162*)hi)[o*2 + 1] = __halves2bfloat162(h2, h3);
    ((__nv_bfloat162*)lo)[o*2 + 0] = __halves2bfloat162(l0, l1);
    ((__nv_bfloat162*)lo)[o*2 + 1] = __halves2bfloat162(l2, l3);
}

// ---------------------------------------------------------------------------
// mma.sync bf16x3 GEMM (round-5 proven config): 128x128 CTA tile, 256 threads
// (8 warps, 64x32 each), cp.async 2-stage.
// MODE 0: qkv -> Q/K/V hi/lo.  MODE 1: proj -> out (fp32).
// ---------------------------------------------------------------------------
__device__ __forceinline__ void gemm_issue_chunk(
    uint32_t sbase,
    const __nv_bfloat16* Ah, const __nv_bfloat16* Al,
    const __nv_bfloat16* Bh, const __nv_bfloat16* Bl,
    int m0, int c0, int kc, int tid)
{
#pragma unroll
    for (int it = 0; it < 4; it++) {
        int idx = tid + it * 256;
        int r = idx >> 3, u = idx & 7;
        uint32_t so = swz((uint32_t)(r * 128 + u * 16));
        cpa16(sbase +     0 + so, Ah + (size_t)(m0 + r) * C_ + kc + u * 8);
        cpa16(sbase + 16384 + so, Al + (size_t)(m0 + r) * C_ + kc + u * 8);
        cpa16(sbase + 32768 + so, Bh + (size_t)(c0 + r) * C_ + kc + u * 8);
        cpa16(sbase + 49152 + so, Bl + (size_t)(c0 + r) * C_ + kc + u * 8);
    }
    cpa_commit();
}

template<int MODE>
__global__ __launch_bounds__(256) void tc_gemm(const float* __restrict__ bias,
                                               float* __restrict__ outp)
{
    extern __shared__ char sm[];
    const uint32_t sb = smem_u32(sm) + 1024;
    const int tid = threadIdx.x;
    const int lane = tid & 31, wid = tid >> 5;
    const int wm = wid & 1, wn = wid >> 1;
    const int stream = blockIdx.z;
    const int m0 = blockIdx.y * 128;
    const int c0 = blockIdx.x * 128;

    const __nv_bfloat16* __restrict__ Ah =
        (MODE==0 ? g_Xh : g_Oh) + (size_t)stream * BN * C_;
    const __nv_bfloat16* __restrict__ Al =
        (MODE==0 ? g_Xl : g_Ol) + (size_t)stream * BN * C_;
    const __nv_bfloat16* __restrict__ Bh = MODE==0 ? g_Wqh : g_Wph;
    const __nv_bfloat16* __restrict__ Bl = MODE==0 ? g_Wql : g_Wpl;

    float acc[4][4][4];
#pragma unroll
    for (int i = 0; i < 4; i++)
#pragma unroll
        for (int j = 0; j < 4; j++)
#pragma unroll
            for (int k = 0; k < 4; k++) acc[i][j][k] = 0.f;

    const int a_r  = wm*64 + (lane & 15);
    const int a_cb = (lane >> 4) * 16;
    const int b_r  = wn*32 + (lane & 7);
    const int b_cb = ((lane >> 3) & 1) * 16;

    const int NCH = C_ / 64;   // 12
    gemm_issue_chunk(sb + 0, Ah, Al, Bh, Bl, m0, c0, 0, tid);

    for (int ch = 0; ch < NCH; ch++) {
        const uint32_t stb = (uint32_t)(ch & 1) * 65536u;
        cpa_wait<0>();
        __syncthreads();
        if (ch + 1 < NCH)
            gemm_issue_chunk(sb + ((ch + 1) & 1) * 65536u,
                             Ah, Al, Bh, Bl, m0, c0, (ch + 1) * 64, tid);

#pragma unroll
        for (int k16 = 0; k16 < 4; k16++) {
            uint32_t bh[4][2], bl[4][2];
#pragma unroll
            for (int nf = 0; nf < 4; nf++) {
                uint32_t bo = stb + 32768 + swz((uint32_t)((b_r + nf*8) * 128 + k16*32 + b_cb));
                ldsm_x2(bh[nf], sb + bo);
                ldsm_x2(bl[nf], sb + bo + 16384);
            }
#pragma unroll
            for (int mf = 0; mf < 4; mf++) {
                uint32_t ao = stb + swz((uint32_t)((a_r + mf*16) * 128 + k16*32 + a_cb));
                uint32_t ah[4], al[4];
                ldsm_x4(ah, sb + ao);
                ldsm_x4(al, sb + ao + 16384);
#pragma unroll
                for (int nf = 0; nf < 4; nf++) {
                    mma16816(acc[mf][nf], ah, bh[nf]);
                    mma16816(acc[mf][nf], ah, bl[nf]);
                    mma16816(acc[mf][nf], al, bh[nf]);
                }
            }
        }
    }
    __syncthreads();   // done reading tiles; reuse smem as Osm

    float* Osm = (float*)(sm + 1024);      // [128][132]
#pragma unroll
    for (int mf = 0; mf < 4; mf++) {
#pragma unroll
        for (int nf = 0; nf < 4; nf++) {
            int row = wm*64 + mf*16 + (lane >> 2);
            int col = wn*32 + nf*8 + (lane & 3)*2;
            Osm[row       * 132 + col    ] = acc[mf][nf][0];
            Osm[row       * 132 + col + 1] = acc[mf][nf][1];
            Osm[(row + 8) * 132 + col    ] = acc[mf][nf][2];
            Osm[(row + 8) * 132 + col + 1] = acc[mf][nf][3];
        }
    }
    __syncthreads();

#pragma unroll
    for (int it = 0; it < 16; it++) {
        int idx = tid + it * 256;
        int r = idx >> 5, j4 = idx & 31;
        float4 v = *(float4*)&Osm[r * 132 + j4 * 4];
        float4 bb = *(const float4*)&bias[c0 + j4 * 4];
        v.x += bb.x; v.y += bb.y; v.z += bb.z; v.w += bb.w;
        int m = m0 + r;
        if (MODE == 0) {
            int cg = c0 + j4 * 4;
            int s = cg / C_;
            int rem = cg - s * C_;
            int h = rem >> 6, d = rem & 63;
            if (s == 0) { v.x *= SCALE; v.y *= SCALE; v.z *= SCALE; v.w *= SCALE; }
            __nv_bfloat16 h0 = __float2bfloat16(v.x);
            __nv_bfloat16 h1 = __float2bfloat16(v.y);
            __nv_bfloat16 h2 = __float2bfloat16(v.z);
            __nv_bfloat16 h3 = __float2bfloat16(v.w);
            uint2 hv, lv;
            hv.x = pack_bf2(v.x, v.y); hv.y = pack_bf2(v.z, v.w);
            lv.x = pack_bf2(v.x - __bfloat162float(h0), v.y - __bfloat162float(h1));
            lv.y = pack_bf2(v.z - __bfloat162float(h2), v.w - __bfloat162float(h3));
            __nv_bfloat16* bufh = (s == 0) ? g_Qh : (s == 1) ? g_Kh : g_Vh;
            __nv_bfloat16* bufl = (s == 0) ? g_Ql : (s == 1) ? g_Kl : g_Vl;
            int b = m >> 10, n = m & 1023;
            size_t base = ((size_t)(b * H_ + h) * N_ + n) * 128 + stream * 64 + d;
            *(uint2*)&bufh[base] = hv;
            *(uint2*)&bufl[base] = lv;
        } else {
            float* Y = outp + (size_t)stream * BN * C_;
            *(float4*)&Y[(size_t)m * C_ + c0 + j4 * 4] = v;
        }
    }
}

// ---------------------------------------------------------------------------
// flash attention, HMMA, 128 q-rows/CTA, 8 warps x 16 rows x 64 kv-cols.
// Softmax warp-local (quad shuffles), P stays in registers (S-acc -> A-frag),
// cp.async 2-stage K/V.  ONE __syncthreads per kv-tile.
// smem: 2 x 64KB K/V stages + Q 64KB = 196608 B
// ---------------------------------------------------------------------------
#define ASTG_ 65536u
#define AKH_ 0u
#define AKL_ 16384u
#define AVH_ 32768u
#define AVL_ 49152u
#define AQH_ 131072u
#define AQL_ 163840u

__device__ __forceinline__ void attn_issue_kv(
    uint32_t sb, uint32_t stb,
    const __nv_bfloat16* kh_g, const __nv_bfloat16* kl_g,
    const __nv_bfloat16* vh_g, const __nv_bfloat16* vl_g, int tid)
{
#pragma unroll
    for (int it = 0; it < 4; it++) {
        int idx = tid + it * 256;          // 0..1023: 64 rows x 16 16B-chunks
        int row = idx >> 4, ch = idx & 15;
        int src = row * 128 + ch * 8;
        uint32_t dst = stb + (uint32_t)(ch >> 3) * 8192 + swz((uint32_t)(row * 128 + (ch & 7) * 16));
        cpa16(sb + AKH_ + dst, kh_g + src);
        cpa16(sb + AKL_ + dst, kl_g + src);
        cpa16(sb + AVH_ + dst, vh_g + src);
        cpa16(sb + AVL_ + dst, vl_g + src);
    }
    cpa_commit();
}

__global__ __launch_bounds__(256, 1) void attn_mma()
{
    extern __shared__ char sm[];
    const uint32_t sb = smem_u32(sm);

    const int tid = threadIdx.x;
    const int lane = tid & 31, wr = tid >> 5;      // warp owns rows wr*16..+15
    const int qt = blockIdx.x, bh = blockIdx.y;
    const int b = bh / H_, h = bh - b * H_;
    const size_t kvb = (size_t)bh * N_ * 128;

    const __nv_bfloat16* kh_g = g_Kh + kvb;
    const __nv_bfloat16* kl_g = g_Kl + kvb;
    const __nv_bfloat16* vh_g = g_Vh + kvb;
    const __nv_bfloat16* vl_g = g_Vl + kvb;

    attn_issue_kv(sb, 0, kh_g, kl_g, vh_g, vl_g, tid);

    // ---- load Q tile: 128 rows x 128 d (hi/lo), two 16KB sub-planes each ----
    {
        const __nv_bfloat16* qh_g = g_Qh + kvb + (size_t)qt * 128 * 128;
        const __nv_bfloat16* ql_g = g_Ql + kvb + (size_t)qt * 128 * 128;
#pragma unroll
        for (int it = 0; it < 8; it++) {
            int idx = tid + it * 256;              // 0..2047
            int row = idx >> 4, ch = idx & 15;
            uint32_t dst = (uint32_t)(ch >> 3) * 16384 + swz((uint32_t)(row * 128 + (ch & 7) * 16));
            *(uint4*)(sm + AQH_ + dst) = *(const uint4*)(qh_g + row * 128 + ch * 8);
            *(uint4*)(sm + AQL_ + dst) = *(const uint4*)(ql_g + row * 128 + ch * 8);
        }
    }

    float m0r = -1e30f, m1r = -1e30f, l0r = 0.f, l1r = 0.f;
    float o[16][4];
#pragma unroll
    for (int i = 0; i < 16; i++)
#pragma unroll
        for (int j = 0; j < 4; j++) o[i][j] = 0.f;

    const int qrow = wr * 16 + (lane & 15);

    for (int kt = 0; kt < 16; kt++) {
        const uint32_t stb = (uint32_t)(kt & 1) * ASTG_;
        cpa_wait<0>();
        __syncthreads();                           // the ONLY barrier per tile
        if (kt < 15)
            attn_issue_kv(sb, (uint32_t)((kt + 1) & 1) * ASTG_,
                          kh_g + (size_t)(kt + 1) * 64 * 128,
                          kl_g + (size_t)(kt + 1) * 64 * 128,
                          vh_g + (size_t)(kt + 1) * 64 * 128,
                          vl_g + (size_t)(kt + 1) * 64 * 128, tid);

        // ---- S = Q K^T : 16 rows x 64 cols per warp, k=128, bf16x3 ----
        float sacc[8][4];
#pragma unroll
        for (int i = 0; i < 8; i++)
#pragma unroll
            for (int j = 0; j < 4; j++) sacc[i][j] = 0.f;

#pragma unroll
        for (int k16 = 0; k16 < 8; k16++) {
            uint32_t qo = (uint32_t)(k16 >> 2) * 16384 +
                          swz((uint32_t)(qrow * 128 + (k16 & 3) * 32 + (lane >> 4) * 16));
            uint32_t ah[4], al[4];
            ldsm_x4(ah, sb + AQH_ + qo);
            ldsm_x4(al, sb + AQL_ + qo);
            uint32_t kpl = stb + (uint32_t)(k16 >> 2) * 8192;
            uint32_t kcb = (uint32_t)((k16 & 3) * 32 + ((lane >> 3) & 1) * 16);
#pragma unroll
            for (int nf = 0; nf < 8; nf++) {
                uint32_t bo = kpl + swz((uint32_t)((nf * 8 + (lane & 7)) * 128) + kcb);
                uint32_t bh2[2], bl2[2];
                ldsm_x2(bh2, sb + AKH_ + bo);
                ldsm_x2(bl2, sb + AKL_ + bo);
                mma16816(sacc[nf], ah, bh2);
                mma16816(sacc[nf], ah, bl2);
                mma16816(sacc[nf], al, bh2);
            }
        }

        // ---- warp-local online softmax (rows fully in-warp) ----
        float pm0 = -1e30f, pm1 = -1e30f;
#pragma unroll
        for (int nf = 0; nf < 8; nf++) {
            pm0 = fmaxf(pm0, fmaxf(sacc[nf][0], sacc[nf][1]));
            pm1 = fmaxf(pm1, fmaxf(sacc[nf][2], sacc[nf][3]));
        }
        pm0 = fmaxf(pm0, __shfl_xor_sync(0xffffffffu, pm0, 1));
        pm0 = fmaxf(pm0, __shfl_xor_sync(0xffffffffu, pm0, 2));
        pm1 = fmaxf(pm1, __shfl_xor_sync(0xffffffffu, pm1, 1));
        pm1 = fmaxf(pm1, __shfl_xor_sync(0xffffffffu, pm1, 2));
        float mn0 = fmaxf(m0r, pm0);
        float mn1 = fmaxf(m1r, pm1);
        float f0 = __expf(m0r - mn0);
        float f1 = __expf(m1r - mn1);
        m0r = mn0; m1r = mn1;

        // exp + pack P directly into A-fragments (hi & lo) — no smem
        uint32_t ph[4][4], plo[4][4];
        float sum0 = 0.f, sum1 = 0.f;
#pragma unroll
        for (int g = 0; g < 4; g++) {
            float q0 = __expf(sacc[2*g][0]   - mn0);
            float q1 = __expf(sacc[2*g][1]   - mn0);
            float q2 = __expf(sacc[2*g][2]   - mn1);
            float q3 = __expf(sacc[2*g][3]   - mn1);
            float s0 = __expf(sacc[2*g+1][0] - mn0);
            float s1 = __expf(sacc[2*g+1][1] - mn0);
            float s2 = __expf(sacc[2*g+1][2] - mn1);
            float s3 = __expf(sacc[2*g+1][3] - mn1);
            sum0 += (q0 + q1) + (s0 + s1);
            sum1 += (q2 + q3) + (s2 + s3);
            ph[g][0] = pack_bf2(q0, q1);
            ph[g][1] = pack_bf2(q2, q3);
            ph[g][2] = pack_bf2(s0, s1);
            ph[g][3] = pack_bf2(s2, s3);
            plo[g][0] = pack_bf2(q0 - __bfloat162float(__float2bfloat16(q0)),
                                 q1 - __bfloat162float(__float2bfloat16(q1)));
            plo[g][1] = pack_bf2(q2 - __bfloat162float(__float2bfloat16(q2)),
                                 q3 - __bfloat162float(__float2bfloat16(q3)));
            plo[g][2] = pack_bf2(s0 - __bfloat162float(__float2bfloat16(s0)),
                                 s1 - __bfloat162float(__float2bfloat16(s1)));
            plo[g][3] = pack_bf2(s2 - __bfloat162float(__float2bfloat16(s2)),
                                 s3 - __bfloat162float(__float2bfloat16(s3)));
        }
        sum0 += __shfl_xor_sync(0xffffffffu, sum0, 1);
        sum0 += __shfl_xor_sync(0xffffffffu, sum0, 2);
        sum1 += __shfl_xor_sync(0xffffffffu, sum1, 1);
        sum1 += __shfl_xor_sync(0xffffffffu, sum1, 2);
        l0r = l0r * f0 + sum0;
        l1r = l1r * f1 + sum1;

        // ---- O = O*fac + P V : 16 rows x 128 d per warp ----
#pragma unroll
        for (int nf = 0; nf < 16; nf++) {
            o[nf][0] *= f0; o[nf][1] *= f0;
            o[nf][2] *= f1; o[nf][3] *= f1;
        }
#pragma unroll
        for (int g = 0; g < 4; g++) {
            uint32_t vrow = (uint32_t)((g * 16 + (lane & 15)) * 128);
#pragma unroll
            for (int nf = 0; nf < 16; nf++) {
                uint32_t vo = stb + (uint32_t)(nf >> 3) * 8192 + swz(vrow + (uint32_t)(nf & 7) * 16);
                uint32_t vh2[2], vl2[2];
                ldsm_x2_t(vh2, sb + AVH_ + vo);
                ldsm_x2_t(vl2, sb + AVL_ + vo);
                mma16816(o[nf], ph[g], vh2);
                mma16816(o[nf], ph[g], vl2);
                mma16816(o[nf], plo[g], vh2);
            }
        }
    }

    // ---- epilogue: normalize, split bf16 hi/lo, write O (stream = nf>>3) ----
    float li0 = 1.f / l0r, li1 = 1.f / l1r;
    const int rr = wr * 16 + (lane >> 2);
#pragma unroll
    for (int nf = 0; nf < 16; nf++) {
        int strm = nf >> 3;
        int dcol = (nf & 7) * 8 + (lane & 3) * 2;
        size_t base = (size_t)strm * BN * C_
                    + ((size_t)(b * N_ + qt * 128 + rr)) * C_ + h * 64 + dcol;
        float v0 = o[nf][0] * li0, v1 = o[nf][1] * li0;
        float v2 = o[nf][2] * li1, v3 = o[nf][3] * li1;
        *(uint32_t*)&g_Oh[base] = pack_bf2(v0, v1);
        *(uint32_t*)&g_Ol[base] =
            pack_bf2(v0 - __bfloat162float(__float2bfloat16(v0)),
                     v1 - __bfloat162float(__float2bfloat16(v1)));
        size_t base8 = base + 8 * C_;
        *(uint32_t*)&g_Oh[base8] = pack_bf2(v2, v3);
        *(uint32_t*)&g_Ol[base8] =
            pack_bf2(v2 - __bfloat162float(__float2bfloat16(v2)),
                     v3 - __bfloat162float(__float2bfloat16(v3)));
    }
}

// ---------------------------------------------------------------------------
extern "C" void kernel_launch(void* const* d_in, const int* in_sizes, int n_in,
                              void* d_out, int out_size)
{
    (void)in_sizes; (void)n_in; (void)out_size;
    const float* x1    = (const float*)d_in[0];
    const float* x2    = (const float*)d_in[1];
    const float* Wqkv  = (const float*)d_in[2];
    const float* bqkv  = (const float*)d_in[3];
    const float* Wproj = (const float*)d_in[4];
    const float* bproj = (const float*)d_in[5];
    float* out = (float*)d_out;

    split_all<<<8448, 256>>>(x1, x2, Wqkv, Wproj);

    const int gemm_smem = 1024 + 2 * 65536;   // 132096
    cudaFuncSetAttribute(tc_gemm<0>, cudaFuncAttributeMaxDynamicSharedMemorySize, gemm_smem);
    tc_gemm<0><<<dim3(18, 32, 2), 256, gemm_smem>>>(bqkv, nullptr);

    const int attn_smem = 196608;
    cudaFuncSetAttribute(attn_mma, cudaFuncAttributeMaxDynamicSharedMemorySize, attn_smem);
    attn_mma<<<dim3(8, 48), 256, attn_smem>>>();

    cudaFuncSetAttribute(tc_gemm<1>, cudaFuncAttributeMaxDynamicSharedMemorySize, gemm_smem);
    tc_gemm<1><<<dim3(6, 32, 2), 256, gemm_smem>>>(bproj, out);
}

// round 8
// speedup vs baseline: 1.1722x; 1.0126x over previous
#include <cuda_runtime.h>
#include <cuda_bf16.h>
#include <cstdint>

#define B_ 4
#define N_ 1024
#define C_ 768
#define H_ 12
#define BN 4096
#define SCALE 0.125f

// ---------------- scratch (static device globals; no allocations) ----------
__device__ __align__(16) __nv_bfloat16 g_Qh[(size_t)B_*H_*N_*128];  // SCALE folded
__device__ __align__(16) __nv_bfloat16 g_Ql[(size_t)B_*H_*N_*128];
__device__ __align__(16) __nv_bfloat16 g_Kh[(size_t)B_*H_*N_*128];
__device__ __align__(16) __nv_bfloat16 g_Kl[(size_t)B_*H_*N_*128];
__device__ __align__(16) __nv_bfloat16 g_Vh[(size_t)B_*H_*N_*128];
__device__ __align__(16) __nv_bfloat16 g_Vl[(size_t)B_*H_*N_*128];

__device__ __align__(16) __nv_bfloat16 g_Xh[(size_t)2*BN*C_];
__device__ __align__(16) __nv_bfloat16 g_Xl[(size_t)2*BN*C_];
__device__ __align__(16) __nv_bfloat16 g_Wqh[(size_t)3*C_*C_];
__device__ __align__(16) __nv_bfloat16 g_Wql[(size_t)3*C_*C_];
__device__ __align__(16) __nv_bfloat16 g_Wph[(size_t)C_*C_];
__device__ __align__(16) __nv_bfloat16 g_Wpl[(size_t)C_*C_];
__device__ __align__(16) __nv_bfloat16 g_Oh[(size_t)2*BN*C_];
__device__ __align__(16) __nv_bfloat16 g_Ol[(size_t)2*BN*C_];

// ---------------- helpers ---------------------------------------------------
__device__ __forceinline__ uint32_t smem_u32(const void* p) {
    uint32_t a;
    asm("{ .reg .u64 t; cvta.to.shared.u64 t, %1; cvt.u32.u64 %0, t; }"
        : "=r"(a) : "l"(p));
    return a;
}
__device__ __forceinline__ uint32_t swz(uint32_t o) {   // 128B-row swizzle
    return o ^ ((o >> 3) & 0x70);
}
__device__ __forceinline__ uint32_t swz64(uint32_t o) { // 64B-row swizzle
    return o ^ ((o >> 3) & 0x30);
}
__device__ __forceinline__ void cpa16(uint32_t dst, const void* src) {
    asm volatile("cp.async.cg.shared.global [%0], [%1], 16;" :: "r"(dst), "l"(src));
}
__device__ __forceinline__ void cpa_commit() {
    asm volatile("cp.async.commit_group;" ::: "memory");
}
template<int N>
__device__ __forceinline__ void cpa_wait() {
    asm volatile("cp.async.wait_group %0;" :: "n"(N) : "memory");
}
__device__ __forceinline__ void ldsm_x4(uint32_t* r, uint32_t addr) {
    asm volatile("ldmatrix.sync.aligned.m8n8.x4.shared.b16 {%0,%1,%2,%3}, [%4];"
                 : "=r"(r[0]), "=r"(r[1]), "=r"(r[2]), "=r"(r[3]) : "r"(addr));
}
__device__ __forceinline__ void ldsm_x2(uint32_t* r, uint32_t addr) {
    asm volatile("ldmatrix.sync.aligned.m8n8.x2.shared.b16 {%0,%1}, [%2];"
                 : "=r"(r[0]), "=r"(r[1]) : "r"(addr));
}
__device__ __forceinline__ void ldsm_x2_t(uint32_t* r, uint32_t addr) {
    asm volatile("ldmatrix.sync.aligned.m8n8.x2.trans.shared.b16 {%0,%1}, [%2];"
                 : "=r"(r[0]), "=r"(r[1]) : "r"(addr));
}
__device__ __forceinline__ void mma16816(float* d, const uint32_t* a, const uint32_t* b) {
    asm volatile(
        "mma.sync.aligned.m16n8k16.row.col.f32.bf16.bf16.f32 "
        "{%0,%1,%2,%3}, {%4,%5,%6,%7}, {%8,%9}, {%0,%1,%2,%3};"
        : "+f"(d[0]), "+f"(d[1]), "+f"(d[2]), "+f"(d[3])
        : "r"(a[0]), "r"(a[1]), "r"(a[2]), "r"(a[3]), "r"(b[0]), "r"(b[1]));
}
__device__ __forceinline__ uint32_t pack_bf2(float a, float b) {
    __nv_bfloat162 t = __floats2bfloat162_rn(a, b);
    return *(uint32_t*)&t;
}

// ---------------------------------------------------------------------------
// fused split kernel: fp32 -> (bf16 hi, bf16 lo) for x1, x2, Wqkv, Wproj
// ---------------------------------------------------------------------------
#define NX4  (BN * C_ / 4)          // 786432 -> 3072 blocks

__global__ __launch_bounds__(256) void split_all(
    const float* __restrict__ x1, const float* __restrict__ x2,
    const float* __restrict__ Wq, const float* __restrict__ Wp)
{
    int bid = blockIdx.x;
    const float* src;
    __nv_bfloat16 *hi, *lo;
    size_t off4;
    int i;
    if (bid < 3072) {
        src = x1; hi = g_Xh; lo = g_Xl; off4 = 0;
        i = bid * 256 + threadIdx.x;
    } else if (bid < 6144) {
        src = x2; hi = g_Xh; lo = g_Xl; off4 = NX4;
        i = (bid - 3072) * 256 + threadIdx.x;
    } else if (bid < 7872) {
        src = Wq; hi = g_Wqh; lo = g_Wql; off4 = 0;
        i = (bid - 6144) * 256 + threadIdx.x;
    } else {
        src = Wp; hi = g_Wph; lo = g_Wpl; off4 = 0;
        i = (bid - 7872) * 256 + threadIdx.x;
    }
    float4 v = ((const float4*)src)[i];
    __nv_bfloat16 h0 = __float2bfloat16(v.x);
    __nv_bfloat16 h1 = __float2bfloat16(v.y);
    __nv_bfloat16 h2 = __float2bfloat16(v.z);
    __nv_bfloat16 h3 = __float2bfloat16(v.w);
    __nv_bfloat16 l0 = __float2bfloat16(v.x - __bfloat162float(h0));
    __nv_bfloat16 l1 = __float2bfloat16(v.y - __bfloat162float(h1));
    __nv_bfloat16 l2 = __float2bfloat16(v.z - __bfloat162float(h2));
    __nv_bfloat16 l3 = __float2bfloat16(v.w - __bfloat162float(h3));
    size_t o = off4 + (size_t)i;
    ((__nv_bfloat162*)hi)[o*2 + 0] = __halves2bfloat162(h0, h1);
    ((__nv_bfloat162*)hi)[o*2 + 1] = __halves2bfloat162(h2, h3);
    ((__nv_bfloat162*)lo)[o*2 + 0] = __halves2bfloat162(l0, l1);
    ((__nv_bfloat162*)lo)[o*2 + 1] = __halves2bfloat162(l2, l3);
}

// ---------------------------------------------------------------------------
// mma.sync bf16x3 GEMM: 128x128 CTA tile, 128 threads (4 warps, 64x64 each),
// K-chunk 32, 2-stage cp.async, 64B-row swizzled tiles -> 2 CTAs/SM.
// MODE 0: qkv -> Q/K/V hi/lo (SCALE folded into Q).  MODE 1: proj -> out.
// smem: 1024 + 2 stages x 32KB (Ah|Al|Bh|Bl 8KB planes); epilogue reuses
// the region as Osm[128][132] fp32.  Alloc = 68608 B.
// ---------------------------------------------------------------------------
__device__ __forceinline__ void gemm_issue_chunk(
    uint32_t sbase,
    const __nv_bfloat16* Ah, const __nv_bfloat16* Al,
    const __nv_bfloat16* Bh, const __nv_bfloat16* Bl,
    int m0, int c0, int kc, int tid)
{
#pragma unroll
    for (int it = 0; it < 4; it++) {
        int u = tid + it * 128;            // 0..511 : 16B chunks of one 8KB plane
        int r = u >> 2, ch = u & 3;
        uint32_t so = swz64((uint32_t)(r * 64 + ch * 16));
        const size_t aoff = (size_t)(m0 + r) * C_ + kc + ch * 8;
        const size_t boff = (size_t)(c0 + r) * C_ + kc + ch * 8;
        cpa16(sbase +     0 + so, Ah + aoff);
        cpa16(sbase +  8192 + so, Al + aoff);
        cpa16(sbase + 16384 + so, Bh + boff);
        cpa16(sbase + 24576 + so, Bl + boff);
    }
    cpa_commit();
}

template<int MODE>
__global__ __launch_bounds__(128, 2) void tc_gemm(const float* __restrict__ bias,
                                                  float* __restrict__ outp)
{
    extern __shared__ char sm[];
    const uint32_t sb = smem_u32(sm) + 1024;
    const int tid = threadIdx.x;
    const int lane = tid & 31, wid = tid >> 5;
    const int wm = wid & 1, wn = wid >> 1;     // 2x2 warp grid, 64x64 each
    const int stream = blockIdx.z;
    const int m0 = blockIdx.y * 128;
    const int c0 = blockIdx.x * 128;

    const __nv_bfloat16* __restrict__ Ah =
        (MODE==0 ? g_Xh : g_Oh) + (size_t)stream * BN * C_;
    const __nv_bfloat16* __restrict__ Al =
        (MODE==0 ? g_Xl : g_Ol) + (size_t)stream * BN * C_;
    const __nv_bfloat16* __restrict__ Bh = MODE==0 ? g_Wqh : g_Wph;
    const __nv_bfloat16* __restrict__ Bl = MODE==0 ? g_Wql : g_Wpl;

    float acc[4][8][4];
#pragma unroll
    for (int i = 0; i < 4; i++)
#pragma unroll
        for (int j = 0; j < 8; j++)
#pragma unroll
            for (int k = 0; k < 4; k++) acc[i][j][k] = 0.f;

    // fragment address components (64B rows, swz64)
    const int a_r  = wm*64 + (lane & 15);                       // A rows
    const int a_cb = (lane >> 4) * 16;                          // A col bytes
    const int b_r  = wn*64 + (lane & 7) + ((lane >> 4) & 1)*8;  // B rows (pair layout)
    const int b_cb = ((lane >> 3) & 1) * 16;                    // B col bytes

    const int NCH = C_ / 32;   // 24 chunks of K=32
    gemm_issue_chunk(sb, Ah, Al, Bh, Bl, m0, c0, 0, tid);

    for (int ch = 0; ch < NCH; ch++) {
        const uint32_t stb = (uint32_t)(ch & 1) * 32768u;
        cpa_wait<0>();
        __syncthreads();
        if (ch + 1 < NCH)
            gemm_issue_chunk(sb + ((ch + 1) & 1) * 32768u,
                             Ah, Al, Bh, Bl, m0, c0, (ch + 1) * 32, tid);

#pragma unroll
        for (int kk = 0; kk < 2; kk++) {
            // B fragments: 4 x4-loads per plane cover nf pairs
            // frag nf=2p -> {bf[4p], bf[4p+1]}, nf=2p+1 -> {bf[4p+2], bf[4p+3]}
            uint32_t bfh[16], bfl[16];
#pragma unroll
            for (int p = 0; p < 4; p++) {
                uint32_t bo = swz64((uint32_t)((b_r + p*16) * 64 + kk*32 + b_cb));
                ldsm_x4(&bfh[p*4], sb + stb + 16384 + bo);
                ldsm_x4(&bfl[p*4], sb + stb + 24576 + bo);
            }
#pragma unroll
            for (int mf = 0; mf < 4; mf++) {
                uint32_t ao = swz64((uint32_t)((a_r + mf*16) * 64 + kk*32 + a_cb));
                uint32_t ah[4], al[4];
                ldsm_x4(ah, sb + stb + ao);
                ldsm_x4(al, sb + stb + 8192 + ao);
#pragma unroll
                for (int p = 0; p < 4; p++) {
                    mma16816(acc[mf][2*p],   ah, &bfh[4*p]);
                    mma16816(acc[mf][2*p],   ah, &bfl[4*p]);
                    mma16816(acc[mf][2*p],   al, &bfh[4*p]);
                    mma16816(acc[mf][2*p+1], ah, &bfh[4*p+2]);
                    mma16816(acc[mf][2*p+1], ah, &bfl[4*p+2]);
                    mma16816(acc[mf][2*p+1], al, &bfh[4*p+2]);
                }
            }
        }
    }
    __syncthreads();   // done reading tiles; reuse smem as Osm

    float* Osm = (float*)(sm + 1024);      // [128][132]
#pragma unroll
    for (int mf = 0; mf < 4; mf++) {
#pragma unroll
        for (int nf = 0; nf < 8; nf++) {
            int row = wm*64 + mf*16 + (lane >> 2);
            int col = wn*64 + nf*8 + (lane & 3)*2;
            Osm[row       * 132 + col    ] = acc[mf][nf][0];
            Osm[row       * 132 + col + 1] = acc[mf][nf][1];
            Osm[(row + 8) * 132 + col    ] = acc[mf][nf][2];
            Osm[(row + 8) * 132 + col + 1] = acc[mf][nf][3];
        }
    }
    __syncthreads();

#pragma unroll
    for (int it = 0; it < 32; it++) {
        int idx = tid + it * 128;             // 0..4095
        int r = idx >> 5, j4 = idx & 31;
        float4 v = *(float4*)&Osm[r * 132 + j4 * 4];
        float4 bb = *(const float4*)&bias[c0 + j4 * 4];
        v.x += bb.x; v.y += bb.y; v.z += bb.z; v.w += bb.w;
        int m = m0 + r;
        if (MODE == 0) {
            int cg = c0 + j4 * 4;
            int s = cg / C_;
            int rem = cg - s * C_;
            int h = rem >> 6, d = rem & 63;
            if (s == 0) { v.x *= SCALE; v.y *= SCALE; v.z *= SCALE; v.w *= SCALE; }
            __nv_bfloat16 h0 = __float2bfloat16(v.x);
            __nv_bfloat16 h1 = __float2bfloat16(v.y);
            __nv_bfloat16 h2 = __float2bfloat16(v.z);
            __nv_bfloat16 h3 = __float2bfloat16(v.w);
            uint2 hv, lv;
            hv.x = pack_bf2(v.x, v.y); hv.y = pack_bf2(v.z, v.w);
            lv.x = pack_bf2(v.x - __bfloat162float(h0), v.y - __bfloat162float(h1));
            lv.y = pack_bf2(v.z - __bfloat162float(h2), v.w - __bfloat162float(h3));
            __nv_bfloat16* bufh = (s == 0) ? g_Qh : (s == 1) ? g_Kh : g_Vh;
            __nv_bfloat16* bufl = (s == 0) ? g_Ql : (s == 1) ? g_Kl : g_Vl;
            int b = m >> 10, n = m & 1023;
            size_t base = ((size_t)(b * H_ + h) * N_ + n) * 128 + stream * 64 + d;
            *(uint2*)&bufh[base] = hv;
            *(uint2*)&bufl[base] = lv;
        } else {
            float* Y = outp + (size_t)stream * BN * C_;
            *(float4*)&Y[(size_t)m * C_ + c0 + j4 * 4] = v;
        }
    }
}

// ---------------------------------------------------------------------------
// flash attention (round-7 proven): HMMA, 128 q-rows/CTA, 8 warps x 16 rows,
// warp-local softmax, register P, cp.async 2-stage K/V, 1 barrier/tile.
// smem: 2 x 64KB K/V stages + Q 64KB = 196608 B
// ---------------------------------------------------------------------------
#define ASTG_ 65536u
#define AKH_ 0u
#define AKL_ 16384u
#define AVH_ 32768u
#define AVL_ 49152u
#define AQH_ 131072u
#define AQL_ 163840u

__device__ __forceinline__ void attn_issue_kv(
    uint32_t sb, uint32_t stb,
    const __nv_bfloat16* kh_g, const __nv_bfloat16* kl_g,
    const __nv_bfloat16* vh_g, const __nv_bfloat16* vl_g, int tid)
{
#pragma unroll
    for (int it = 0; it < 4; it++) {
        int idx = tid + it * 256;          // 0..1023: 64 rows x 16 16B-chunks
        int row = idx >> 4, ch = idx & 15;
        int src = row * 128 + ch * 8;
        uint32_t dst = stb + (uint32_t)(ch >> 3) * 8192 + swz((uint32_t)(row * 128 + (ch & 7) * 16));
        cpa16(sb + AKH_ + dst, kh_g + src);
        cpa16(sb + AKL_ + dst, kl_g + src);
        cpa16(sb + AVH_ + dst, vh_g + src);
        cpa16(sb + AVL_ + dst, vl_g + src);
    }
    cpa_commit();
}

__global__ __launch_bounds__(256, 1) void attn_mma()
{
    extern __shared__ char sm[];
    const uint32_t sb = smem_u32(sm);

    const int tid = threadIdx.x;
    const int lane = tid & 31, wr = tid >> 5;
    const int qt = blockIdx.x, bh = blockIdx.y;
    const int b = bh / H_, h = bh - b * H_;
    const size_t kvb = (size_t)bh * N_ * 128;

    const __nv_bfloat16* kh_g = g_Kh + kvb;
    const __nv_bfloat16* kl_g = g_Kl + kvb;
    const __nv_bfloat16* vh_g = g_Vh + kvb;
    const __nv_bfloat16* vl_g = g_Vl + kvb;

    attn_issue_kv(sb, 0, kh_g, kl_g, vh_g, vl_g, tid);

    {
        const __nv_bfloat16* qh_g = g_Qh + kvb + (size_t)qt * 128 * 128;
        const __nv_bfloat16* ql_g = g_Ql + kvb + (size_t)qt * 128 * 128;
#pragma unroll
        for (int it = 0; it < 8; it++) {
            int idx = tid + it * 256;
            int row = idx >> 4, ch = idx & 15;
            uint32_t dst = (uint32_t)(ch >> 3) * 16384 + swz((uint32_t)(row * 128 + (ch & 7) * 16));
            *(uint4*)(sm + AQH_ + dst) = *(const uint4*)(qh_g + row * 128 + ch * 8);
            *(uint4*)(sm + AQL_ + dst) = *(const uint4*)(ql_g + row * 128 + ch * 8);
        }
    }

    float m0r = -1e30f, m1r = -1e30f, l0r = 0.f, l1r = 0.f;
    float o[16][4];
#pragma unroll
    for (int i = 0; i < 16; i++)
#pragma unroll
        for (int j = 0; j < 4; j++) o[i][j] = 0.f;

    const int qrow = wr * 16 + (lane & 15);

    for (int kt = 0; kt < 16; kt++) {
        const uint32_t stb = (uint32_t)(kt & 1) * ASTG_;
        cpa_wait<0>();
        __syncthreads();
        if (kt < 15)
            attn_issue_kv(sb, (uint32_t)((kt + 1) & 1) * ASTG_,
                          kh_g + (size_t)(kt + 1) * 64 * 128,
                          kl_g + (size_t)(kt + 1) * 64 * 128,
                          vh_g + (size_t)(kt + 1) * 64 * 128,
                          vl_g + (size_t)(kt + 1) * 64 * 128, tid);

        float sacc[8][4];
#pragma unroll
        for (int i = 0; i < 8; i++)
#pragma unroll
            for (int j = 0; j < 4; j++) sacc[i][j] = 0.f;

#pragma unroll
        for (int k16 = 0; k16 < 8; k16++) {
            uint32_t qo = (uint32_t)(k16 >> 2) * 16384 +
                          swz((uint32_t)(qrow * 128 + (k16 & 3) * 32 + (lane >> 4) * 16));
            uint32_t ah[4], al[4];
            ldsm_x4(ah, sb + AQH_ + qo);
            ldsm_x4(al, sb + AQL_ + qo);
            uint32_t kpl = stb + (uint32_t)(k16 >> 2) * 8192;
            uint32_t kcb = (uint32_t)((k16 & 3) * 32 + ((lane >> 3) & 1) * 16);
#pragma unroll
            for (int nf = 0; nf < 8; nf++) {
                uint32_t bo = kpl + swz((uint32_t)((nf * 8 + (lane & 7)) * 128) + kcb);
                uint32_t bh2[2], bl2[2];
                ldsm_x2(bh2, sb + AKH_ + bo);
                ldsm_x2(bl2, sb + AKL_ + bo);
                mma16816(sacc[nf], ah, bh2);
                mma16816(sacc[nf], ah, bl2);
                mma16816(sacc[nf], al, bh2);
            }
        }

        float pm0 = -1e30f, pm1 = -1e30f;
#pragma unroll
        for (int nf = 0; nf < 8; nf++) {
            pm0 = fmaxf(pm0, fmaxf(sacc[nf][0], sacc[nf][1]));
            pm1 = fmaxf(pm1, fmaxf(sacc[nf][2], sacc[nf][3]));
        }
        pm0 = fmaxf(pm0, __shfl_xor_sync(0xffffffffu, pm0, 1));
        pm0 = fmaxf(pm0, __shfl_xor_sync(0xffffffffu, pm0, 2));
        pm1 = fmaxf(pm1, __shfl_xor_sync(0xffffffffu, pm1, 1));
        pm1 = fmaxf(pm1, __shfl_xor_sync(0xffffffffu, pm1, 2));
        float mn0 = fmaxf(m0r, pm0);
        float mn1 = fmaxf(m1r, pm1);
        float f0 = __expf(m0r - mn0);
        float f1 = __expf(m1r - mn1);
        m0r = mn0; m1r = mn1;

        uint32_t ph[4][4], plo[4][4];
        float sum0 = 0.f, sum1 = 0.f;
#pragma unroll
        for (int g = 0; g < 4; g++) {
            float q0 = __expf(sacc[2*g][0]   - mn0);
            float q1 = __expf(sacc[2*g][1]   - mn0);
            float q2 = __expf(sacc[2*g][2]   - mn1);
            float q3 = __expf(sacc[2*g][3]   - mn1);
            float s0 = __expf(sacc[2*g+1][0] - mn0);
            float s1 = __expf(sacc[2*g+1][1] - mn0);
            float s2 = __expf(sacc[2*g+1][2] - mn1);
            float s3 = __expf(sacc[2*g+1][3] - mn1);
            sum0 += (q0 + q1) + (s0 + s1);
            sum1 += (q2 + q3) + (s2 + s3);
            ph[g][0] = pack_bf2(q0, q1);
            ph[g][1] = pack_bf2(q2, q3);
            ph[g][2] = pack_bf2(s0, s1);
            ph[g][3] = pack_bf2(s2, s3);
            plo[g][0] = pack_bf2(q0 - __bfloat162float(__float2bfloat16(q0)),
                                 q1 - __bfloat162float(__float2bfloat16(q1)));
            plo[g][1] = pack_bf2(q2 - __bfloat162float(__float2bfloat16(q2)),
                                 q3 - __bfloat162float(__float2bfloat16(q3)));
            plo[g][2] = pack_bf2(s0 - __bfloat162float(__float2bfloat16(s0)),
                                 s1 - __bfloat162float(__float2bfloat16(s1)));
            plo[g][3] = pack_bf2(s2 - __bfloat162float(__float2bfloat16(s2)),
                                 s3 - __bfloat162float(__float2bfloat16(s3)));
        }
        sum0 += __shfl_xor_sync(0xffffffffu, sum0, 1);
        sum0 += __shfl_xor_sync(0xffffffffu, sum0, 2);
        sum1 += __shfl_xor_sync(0xffffffffu, sum1, 1);
        sum1 += __shfl_xor_sync(0xffffffffu, sum1, 2);
        l0r = l0r * f0 + sum0;
        l1r = l1r * f1 + sum1;

#pragma unroll
        for (int nf = 0; nf < 16; nf++) {
            o[nf][0] *= f0; o[nf][1] *= f0;
            o[nf][2] *= f1; o[nf][3] *= f1;
        }
#pragma unroll
        for (int g = 0; g < 4; g++) {
            uint32_t vrow = (uint32_t)((g * 16 + (lane & 15)) * 128);
#pragma unroll
            for (int nf = 0; nf < 16; nf++) {
                uint32_t vo = stb + (uint32_t)(nf >> 3) * 8192 + swz(vrow + (uint32_t)(nf & 7) * 16);
                uint32_t vh2[2], vl2[2];
                ldsm_x2_t(vh2, sb + AVH_ + vo);
                ldsm_x2_t(vl2, sb + AVL_ + vo);
                mma16816(o[nf], ph[g], vh2);
                mma16816(o[nf], ph[g], vl2);
                mma16816(o[nf], plo[g], vh2);
            }
        }
    }

    float li0 = 1.f / l0r, li1 = 1.f / l1r;
    const int rr = wr * 16 + (lane >> 2);
#pragma unroll
    for (int nf = 0; nf < 16; nf++) {
        int strm = nf >> 3;
        int dcol = (nf & 7) * 8 + (lane & 3) * 2;
        size_t base = (size_t)strm * BN * C_
                    + ((size_t)(b * N_ + qt * 128 + rr)) * C_ + h * 64 + dcol;
        float v0 = o[nf][0] * li0, v1 = o[nf][1] * li0;
        float v2 = o[nf][2] * li1, v3 = o[nf][3] * li1;
        *(uint32_t*)&g_Oh[base] = pack_bf2(v0, v1);
        *(uint32_t*)&g_Ol[base] =
            pack_bf2(v0 - __bfloat162float(__float2bfloat16(v0)),
                     v1 - __bfloat162float(__float2bfloat16(v1)));
        size_t base8 = base + 8 * C_;
        *(uint32_t*)&g_Oh[base8] = pack_bf2(v2, v3);
        *(uint32_t*)&g_Ol[base8] =
            pack_bf2(v2 - __bfloat162float(__float2bfloat16(v2)),
                     v3 - __bfloat162float(__float2bfloat16(v3)));
    }
}

// ---------------------------------------------------------------------------
extern "C" void kernel_launch(void* const* d_in, const int* in_sizes, int n_in,
                              void* d_out, int out_size)
{
    (void)in_sizes; (void)n_in; (void)out_size;
    const float* x1    = (const float*)d_in[0];
    const float* x2    = (const float*)d_in[1];
    const float* Wqkv  = (const float*)d_in[2];
    const float* bqkv  = (const float*)d_in[3];
    const float* Wproj = (const float*)d_in[4];
    const float* bproj = (const float*)d_in[5];
    float* out = (float*)d_out;

    split_all<<<8448, 256>>>(x1, x2, Wqkv, Wproj);

    const int gemm_smem = 68608;   // 1024 + 2x32KB stages; Osm fits too
    cudaFuncSetAttribute(tc_gemm<0>, cudaFuncAttributeMaxDynamicSharedMemorySize, gemm_smem);
    tc_gemm<0><<<dim3(18, 32, 2), 128, gemm_smem>>>(bqkv, nullptr);

    const int attn_smem = 196608;
    cudaFuncSetAttribute(attn_mma, cudaFuncAttributeMaxDynamicSharedMemorySize, attn_smem);
    attn_mma<<<dim3(8, 48), 256, attn_smem>>>();

    cudaFuncSetAttribute(tc_gemm<1>, cudaFuncAttributeMaxDynamicSharedMemorySize, gemm_smem);
    tc_gemm<1><<<dim3(6, 32, 2), 128, gemm_smem>>>(bproj, out);
}

// round 9
// speedup vs baseline: 1.3680x; 1.1671x over previous
#include <cuda_runtime.h>
#include <cuda_fp16.h>
#include <cstdint>

#define B_ 4
#define N_ 1024
#define C_ 768
#define H_ 12
#define BN 4096
#define SCALE 0.125f

// ---------------- scratch (static device globals; no allocations) ----------
__device__ __align__(16) __half g_Qh[(size_t)B_*H_*N_*128];  // SCALE folded
__device__ __align__(16) __half g_Ql[(size_t)B_*H_*N_*128];
__device__ __align__(16) __half g_Kh[(size_t)B_*H_*N_*128];
__device__ __align__(16) __half g_Kl[(size_t)B_*H_*N_*128];
__device__ __align__(16) __half g_Vh[(size_t)B_*H_*N_*128];
__device__ __align__(16) __half g_Vl[(size_t)B_*H_*N_*128];

__device__ __align__(16) __half g_Xh[(size_t)2*BN*C_];
__device__ __align__(16) __half g_Xl[(size_t)2*BN*C_];
__device__ __align__(16) __half g_Wqh[(size_t)3*C_*C_];
__device__ __align__(16) __half g_Wql[(size_t)3*C_*C_];
__device__ __align__(16) __half g_Wph[(size_t)C_*C_];
__device__ __align__(16) __half g_Wpl[(size_t)C_*C_];
__device__ __align__(16) __half g_Oh[(size_t)2*BN*C_];   // single fp16 (no lo)

// ---------------- helpers ---------------------------------------------------
__device__ __forceinline__ uint32_t smem_u32(const void* p) {
    uint32_t a;
    asm("{ .reg .u64 t; cvta.to.shared.u64 t, %1; cvt.u32.u64 %0, t; }"
        : "=r"(a) : "l"(p));
    return a;
}
__device__ __forceinline__ uint32_t swz(uint32_t o) {   // 128B-row swizzle
    return o ^ ((o >> 3) & 0x70);
}
__device__ __forceinline__ uint32_t swz64(uint32_t o) { // 64B-row swizzle
    return o ^ ((o >> 3) & 0x30);
}
__device__ __forceinline__ void cpa16(uint32_t dst, const void* src) {
    asm volatile("cp.async.cg.shared.global [%0], [%1], 16;" :: "r"(dst), "l"(src));
}
__device__ __forceinline__ void cpa_commit() {
    asm volatile("cp.async.commit_group;" ::: "memory");
}
template<int N>
__device__ __forceinline__ void cpa_wait() {
    asm volatile("cp.async.wait_group %0;" :: "n"(N) : "memory");
}
__device__ __forceinline__ void ldsm_x4(uint32_t* r, uint32_t addr) {
    asm volatile("ldmatrix.sync.aligned.m8n8.x4.shared.b16 {%0,%1,%2,%3}, [%4];"
                 : "=r"(r[0]), "=r"(r[1]), "=r"(r[2]), "=r"(r[3]) : "r"(addr));
}
__device__ __forceinline__ void ldsm_x4_t(uint32_t* r, uint32_t addr) {
    asm volatile("ldmatrix.sync.aligned.m8n8.x4.trans.shared.b16 {%0,%1,%2,%3}, [%4];"
                 : "=r"(r[0]), "=r"(r[1]), "=r"(r[2]), "=r"(r[3]) : "r"(addr));
}
__device__ __forceinline__ void mma16816(float* d, const uint32_t* a, const uint32_t* b) {
    asm volatile(
        "mma.sync.aligned.m16n8k16.row.col.f32.f16.f16.f32 "
        "{%0,%1,%2,%3}, {%4,%5,%6,%7}, {%8,%9}, {%0,%1,%2,%3};"
        : "+f"(d[0]), "+f"(d[1]), "+f"(d[2]), "+f"(d[3])
        : "r"(a[0]), "r"(a[1]), "r"(a[2]), "r"(a[3]), "r"(b[0]), "r"(b[1]));
}
__device__ __forceinline__ uint32_t pack_h2(float a, float b) {
    __half2 t = __floats2half2_rn(a, b);
    return *(uint32_t*)&t;
}

// ---------------------------------------------------------------------------
// fused split kernel: fp32 -> (fp16 hi, fp16 lo) for x1, x2, Wqkv, Wproj
// ---------------------------------------------------------------------------
#define NX4  (BN * C_ / 4)          // 786432 -> 3072 blocks

__global__ __launch_bounds__(256) void split_all(
    const float* __restrict__ x1, const float* __restrict__ x2,
    const float* __restrict__ Wq, const float* __restrict__ Wp)
{
    int bid = blockIdx.x;
    const float* src;
    __half *hi, *lo;
    size_t off4;
    int i;
    if (bid < 3072) {
        src = x1; hi = g_Xh; lo = g_Xl; off4 = 0;
        i = bid * 256 + threadIdx.x;
    } else if (bid < 6144) {
        src = x2; hi = g_Xh; lo = g_Xl; off4 = NX4;
        i = (bid - 3072) * 256 + threadIdx.x;
    } else if (bid < 7872) {
        src = Wq; hi = g_Wqh; lo = g_Wql; off4 = 0;
        i = (bid - 6144) * 256 + threadIdx.x;
    } else {
        src = Wp; hi = g_Wph; lo = g_Wpl; off4 = 0;
        i = (bid - 7872) * 256 + threadIdx.x;
    }
    float4 v = ((const float4*)src)[i];
    __half h0 = __float2half(v.x);
    __half h1 = __float2half(v.y);
    __half h2 = __float2half(v.z);
    __half h3 = __float2half(v.w);
    size_t o = off4 + (size_t)i;
    ((uint32_t*)hi)[o*2 + 0] = pack_h2(v.x, v.y);
    ((uint32_t*)hi)[o*2 + 1] = pack_h2(v.z, v.w);
    ((uint32_t*)lo)[o*2 + 0] = pack_h2(v.x - __half2float(h0), v.y - __half2float(h1));
    ((uint32_t*)lo)[o*2 + 1] = pack_h2(v.z - __half2float(h2), v.w - __half2float(h3));
}

// ---------------------------------------------------------------------------
// mma.sync fp16-split GEMM: 128x128 CTA tile, 128 threads (4 warps, 64x64),
// K-chunk 32, 2-stage cp.async, 64B-row swizzle, 2 CTAs/SM.
// 3-term (AhBh+AhBl+AlBh) for Q/K tiles; 2-term (AhBh+AhBl) for V tiles and proj.
// MODE 0: qkv -> Q/K/V fp16 hi/lo.  MODE 1: proj (A = g_Oh single) -> out fp32.
// ---------------------------------------------------------------------------
__device__ __forceinline__ void gemm_issue_chunk(
    uint32_t sbase,
    const __half* Ah, const __half* Al,
    const __half* Bh, const __half* Bl,
    int m0, int c0, int kc, int tid, bool loadAl)
{
#pragma unroll
    for (int it = 0; it < 4; it++) {
        int u = tid + it * 128;            // 0..511 : 16B chunks of one 8KB plane
        int r = u >> 2, ch = u & 3;
        uint32_t so = swz64((uint32_t)(r * 64 + ch * 16));
        const size_t aoff = (size_t)(m0 + r) * C_ + kc + ch * 8;
        const size_t boff = (size_t)(c0 + r) * C_ + kc + ch * 8;
        cpa16(sbase +     0 + so, Ah + aoff);
        if (loadAl) cpa16(sbase + 8192 + so, Al + aoff);
        cpa16(sbase + 16384 + so, Bh + boff);
        cpa16(sbase + 24576 + so, Bl + boff);
    }
    cpa_commit();
}

template<int MODE>
__global__ __launch_bounds__(128, 2) void tc_gemm(const float* __restrict__ bias,
                                                  float* __restrict__ outp)
{
    extern __shared__ char sm[];
    const uint32_t sb = smem_u32(sm) + 1024;
    const int tid = threadIdx.x;
    const int lane = tid & 31, wid = tid >> 5;
    const int wm = wid & 1, wn = wid >> 1;     // 2x2 warp grid, 64x64 each
    const int stream = blockIdx.z;
    const int m0 = blockIdx.y * 128;
    const int c0 = blockIdx.x * 128;
    // V tiles (s==2) and proj use 2-term; Q/K tiles use 3-term
    const bool use3 = (MODE == 0) && (blockIdx.x < 12);

    const __half* __restrict__ Ah =
        (MODE==0 ? g_Xh : g_Oh) + (size_t)stream * BN * C_;
    const __half* __restrict__ Al =
        (MODE==0 ? g_Xl : g_Xl) + (size_t)stream * BN * C_;   // unused when !use3
    const __half* __restrict__ Bh = MODE==0 ? g_Wqh : g_Wph;
    const __half* __restrict__ Bl = MODE==0 ? g_Wql : g_Wpl;

    float acc[4][8][4];
#pragma unroll
    for (int i = 0; i < 4; i++)
#pragma unroll
        for (int j = 0; j < 8; j++)
#pragma unroll
            for (int k = 0; k < 4; k++) acc[i][j][k] = 0.f;

    const int a_r  = wm*64 + (lane & 15);
    const int a_cb = (lane >> 4) * 16;
    const int b_r  = wn*64 + (lane & 7) + ((lane >> 4) & 1)*8;
    const int b_cb = ((lane >> 3) & 1) * 16;

    const int NCH = C_ / 32;   // 24 chunks of K=32
    gemm_issue_chunk(sb, Ah, Al, Bh, Bl, m0, c0, 0, tid, use3);

    for (int ch = 0; ch < NCH; ch++) {
        const uint32_t stb = (uint32_t)(ch & 1) * 32768u;
        cpa_wait<0>();
        __syncthreads();
        if (ch + 1 < NCH)
            gemm_issue_chunk(sb + ((ch + 1) & 1) * 32768u,
                             Ah, Al, Bh, Bl, m0, c0, (ch + 1) * 32, tid, use3);

#pragma unroll
        for (int kk = 0; kk < 2; kk++) {
            uint32_t bfh[16], bfl[16];
#pragma unroll
            for (int p = 0; p < 4; p++) {
                uint32_t bo = swz64((uint32_t)((b_r + p*16) * 64 + kk*32 + b_cb));
                ldsm_x4(&bfh[p*4], sb + stb + 16384 + bo);
                ldsm_x4(&bfl[p*4], sb + stb + 24576 + bo);
            }
#pragma unroll
            for (int mf = 0; mf < 4; mf++) {
                uint32_t ao = swz64((uint32_t)((a_r + mf*16) * 64 + kk*32 + a_cb));
                uint32_t ah[4], al[4];
                ldsm_x4(ah, sb + stb + ao);
                if (use3) ldsm_x4(al, sb + stb + 8192 + ao);
                // term-major ordering: independent accumulators between
                // dependent MMAs
#pragma unroll
                for (int p = 0; p < 4; p++) {
                    mma16816(acc[mf][2*p],   ah, &bfh[4*p]);
                    mma16816(acc[mf][2*p+1], ah, &bfh[4*p+2]);
                }
#pragma unroll
                for (int p = 0; p < 4; p++) {
                    mma16816(acc[mf][2*p],   ah, &bfl[4*p]);
                    mma16816(acc[mf][2*p+1], ah, &bfl[4*p+2]);
                }
                if (use3) {
#pragma unroll
                    for (int p = 0; p < 4; p++) {
                        mma16816(acc[mf][2*p],   al, &bfh[4*p]);
                        mma16816(acc[mf][2*p+1], al, &bfh[4*p+2]);
                    }
                }
            }
        }
    }
    __syncthreads();   // done reading tiles; reuse smem as Osm

    float* Osm = (float*)(sm + 1024);      // [128][132]
#pragma unroll
    for (int mf = 0; mf < 4; mf++) {
#pragma unroll
        for (int nf = 0; nf < 8; nf++) {
            int row = wm*64 + mf*16 + (lane >> 2);
            int col = wn*64 + nf*8 + (lane & 3)*2;
            Osm[row       * 132 + col    ] = acc[mf][nf][0];
            Osm[row       * 132 + col + 1] = acc[mf][nf][1];
            Osm[(row + 8) * 132 + col    ] = acc[mf][nf][2];
            Osm[(row + 8) * 132 + col + 1] = acc[mf][nf][3];
        }
    }
    __syncthreads();

#pragma unroll
    for (int it = 0; it < 32; it++) {
        int idx = tid + it * 128;             // 0..4095
        int r = idx >> 5, j4 = idx & 31;
        float4 v = *(float4*)&Osm[r * 132 + j4 * 4];
        float4 bb = *(const float4*)&bias[c0 + j4 * 4];
        v.x += bb.x; v.y += bb.y; v.z += bb.z; v.w += bb.w;
        int m = m0 + r;
        if (MODE == 0) {
            int cg = c0 + j4 * 4;
            int s = cg / C_;
            int rem = cg - s * C_;
            int h = rem >> 6, d = rem & 63;
            if (s == 0) { v.x *= SCALE; v.y *= SCALE; v.z *= SCALE; v.w *= SCALE; }
            __half h0 = __float2half(v.x);
            __half h1 = __float2half(v.y);
            __half h2 = __float2half(v.z);
            __half h3 = __float2half(v.w);
            uint2 hv, lv;
            hv.x = pack_h2(v.x, v.y); hv.y = pack_h2(v.z, v.w);
            lv.x = pack_h2(v.x - __half2float(h0), v.y - __half2float(h1));
            lv.y = pack_h2(v.z - __half2float(h2), v.w - __half2float(h3));
            __half* bufh = (s == 0) ? g_Qh : (s == 1) ? g_Kh : g_Vh;
            __half* bufl = (s == 0) ? g_Ql : (s == 1) ? g_Kl : g_Vl;
            int b = m >> 10, n = m & 1023;
            size_t base = ((size_t)(b * H_ + h) * N_ + n) * 128 + stream * 64 + d;
            *(uint2*)&bufh[base] = hv;
            *(uint2*)&bufl[base] = lv;
        } else {
            float* Y = outp + (size_t)stream * BN * C_;
            *(float4*)&Y[(size_t)m * C_ + c0 + j4 * 4] = v;
        }
    }
}

// ---------------------------------------------------------------------------
// flash attention: HMMA fp16, 128 q-rows/CTA, 8 warps x 16 rows x 64 kv-cols.
// S = QK^T 3-term (Q,K fp16 hi/lo); PV 2-term (P fp16, V fp16 hi/lo).
// Warp-local softmax, register P, cp.async 2-stage K/V, 1 barrier/tile.
// smem: 2 x 64KB K/V stages + Q 64KB = 196608 B
// ---------------------------------------------------------------------------
#define ASTG_ 65536u
#define AKH_ 0u
#define AKL_ 16384u
#define AVH_ 32768u
#define AVL_ 49152u
#define AQH_ 131072u
#define AQL_ 163840u

__device__ __forceinline__ void attn_issue_kv(
    uint32_t sb, uint32_t stb,
    const __half* kh_g, const __half* kl_g,
    const __half* vh_g, const __half* vl_g, int tid)
{
#pragma unroll
    for (int it = 0; it < 4; it++) {
        int idx = tid + it * 256;          // 0..1023: 64 rows x 16 16B-chunks
        int row = idx >> 4, ch = idx & 15;
        int src = row * 128 + ch * 8;
        uint32_t dst = stb + (uint32_t)(ch >> 3) * 8192 + swz((uint32_t)(row * 128 + (ch & 7) * 16));
        cpa16(sb + AKH_ + dst, kh_g + src);
        cpa16(sb + AKL_ + dst, kl_g + src);
        cpa16(sb + AVH_ + dst, vh_g + src);
        cpa16(sb + AVL_ + dst, vl_g + src);
    }
    cpa_commit();
}

__global__ __launch_bounds__(256, 1) void attn_mma()
{
    extern __shared__ char sm[];
    const uint32_t sb = smem_u32(sm);

    const int tid = threadIdx.x;
    const int lane = tid & 31, wr = tid >> 5;
    const int qt = blockIdx.x, bh = blockIdx.y;
    const int b = bh / H_, h = bh - b * H_;
    const size_t kvb = (size_t)bh * N_ * 128;

    const __half* kh_g = g_Kh + kvb;
    const __half* kl_g = g_Kl + kvb;
    const __half* vh_g = g_Vh + kvb;
    const __half* vl_g = g_Vl + kvb;

    attn_issue_kv(sb, 0, kh_g, kl_g, vh_g, vl_g, tid);

    {
        const __half* qh_g = g_Qh + kvb + (size_t)qt * 128 * 128;
        const __half* ql_g = g_Ql + kvb + (size_t)qt * 128 * 128;
#pragma unroll
        for (int it = 0; it < 8; it++) {
            int idx = tid + it * 256;
            int row = idx >> 4, ch = idx & 15;
            uint32_t dst = (uint32_t)(ch >> 3) * 16384 + swz((uint32_t)(row * 128 + (ch & 7) * 16));
            *(uint4*)(sm + AQH_ + dst) = *(const uint4*)(qh_g + row * 128 + ch * 8);
            *(uint4*)(sm + AQL_ + dst) = *(const uint4*)(ql_g + row * 128 + ch * 8);
        }
    }

    float m0r = -1e30f, m1r = -1e30f, l0r = 0.f, l1r = 0.f;
    float o[16][4];
#pragma unroll
    for (int i = 0; i < 16; i++)
#pragma unroll
        for (int j = 0; j < 4; j++) o[i][j] = 0.f;

    const int qrow = wr * 16 + (lane & 15);
    const int k_r  = (lane & 7) + ((lane >> 4) & 1) * 8;   // K pair-frag rows
    const int k_cb = ((lane >> 3) & 1) * 16;

    for (int kt = 0; kt < 16; kt++) {
        const uint32_t stb = (uint32_t)(kt & 1) * ASTG_;
        cpa_wait<0>();
        __syncthreads();
        if (kt < 15)
            attn_issue_kv(sb, (uint32_t)((kt + 1) & 1) * ASTG_,
                          kh_g + (size_t)(kt + 1) * 64 * 128,
                          kl_g + (size_t)(kt + 1) * 64 * 128,
                          vh_g + (size_t)(kt + 1) * 64 * 128,
                          vl_g + (size_t)(kt + 1) * 64 * 128, tid);

        // ---- S = Q K^T : 16 rows x 64 cols per warp, k=128, fp16 3-term ----
        float sacc[8][4];
#pragma unroll
        for (int i = 0; i < 8; i++)
#pragma unroll
            for (int j = 0; j < 4; j++) sacc[i][j] = 0.f;

#pragma unroll
        for (int k16 = 0; k16 < 8; k16++) {
            uint32_t qo = (uint32_t)(k16 >> 2) * 16384 +
                          swz((uint32_t)(qrow * 128 + (k16 & 3) * 32 + (lane >> 4) * 16));
            uint32_t ah[4], al[4];
            ldsm_x4(ah, sb + AQH_ + qo);
            ldsm_x4(al, sb + AQL_ + qo);
            uint32_t kpl = stb + (uint32_t)(k16 >> 2) * 8192;
            uint32_t kcb = (uint32_t)((k16 & 3) * 32) + k_cb;
            uint32_t kfh[16], kfl[16];
#pragma unroll
            for (int p = 0; p < 4; p++) {
                uint32_t ko = kpl + swz((uint32_t)((k_r + p*16) * 128) + kcb);
                ldsm_x4(&kfh[4*p], sb + AKH_ + ko);
                ldsm_x4(&kfl[4*p], sb + AKL_ + ko);
            }
#pragma unroll
            for (int p = 0; p < 4; p++) {
                mma16816(sacc[2*p],   ah, &kfh[4*p]);
                mma16816(sacc[2*p+1], ah, &kfh[4*p+2]);
            }
#pragma unroll
            for (int p = 0; p < 4; p++) {
                mma16816(sacc[2*p],   ah, &kfl[4*p]);
                mma16816(sacc[2*p+1], ah, &kfl[4*p+2]);
            }
#pragma unroll
            for (int p = 0; p < 4; p++) {
                mma16816(sacc[2*p],   al, &kfh[4*p]);
                mma16816(sacc[2*p+1], al, &kfh[4*p+2]);
            }
        }

        // ---- warp-local online softmax ----
        float pm0 = -1e30f, pm1 = -1e30f;
#pragma unroll
        for (int nf = 0; nf < 8; nf++) {
            pm0 = fmaxf(pm0, fmaxf(sacc[nf][0], sacc[nf][1]));
            pm1 = fmaxf(pm1, fmaxf(sacc[nf][2], sacc[nf][3]));
        }
        pm0 = fmaxf(pm0, __shfl_xor_sync(0xffffffffu, pm0, 1));
        pm0 = fmaxf(pm0, __shfl_xor_sync(0xffffffffu, pm0, 2));
        pm1 = fmaxf(pm1, __shfl_xor_sync(0xffffffffu, pm1, 1));
        pm1 = fmaxf(pm1, __shfl_xor_sync(0xffffffffu, pm1, 2));
        float mn0 = fmaxf(m0r, pm0);
        float mn1 = fmaxf(m1r, pm1);
        float f0 = __expf(m0r - mn0);
        float f1 = __expf(m1r - mn1);
        m0r = mn0; m1r = mn1;

        // exp + pack P (fp16, single precision plane) into A-fragments
        uint32_t ph[4][4];
        float sum0 = 0.f, sum1 = 0.f;
#pragma unroll
        for (int g = 0; g < 4; g++) {
            float q0 = __expf(sacc[2*g][0]   - mn0);
            float q1 = __expf(sacc[2*g][1]   - mn0);
            float q2 = __expf(sacc[2*g][2]   - mn1);
            float q3 = __expf(sacc[2*g][3]   - mn1);
            float s0 = __expf(sacc[2*g+1][0] - mn0);
            float s1 = __expf(sacc[2*g+1][1] - mn0);
            float s2 = __expf(sacc[2*g+1][2] - mn1);
            float s3 = __expf(sacc[2*g+1][3] - mn1);
            sum0 += (q0 + q1) + (s0 + s1);
            sum1 += (q2 + q3) + (s2 + s3);
            ph[g][0] = pack_h2(q0, q1);
            ph[g][1] = pack_h2(q2, q3);
            ph[g][2] = pack_h2(s0, s1);
            ph[g][3] = pack_h2(s2, s3);
        }
        sum0 += __shfl_xor_sync(0xffffffffu, sum0, 1);
        sum0 += __shfl_xor_sync(0xffffffffu, sum0, 2);
        sum1 += __shfl_xor_sync(0xffffffffu, sum1, 1);
        sum1 += __shfl_xor_sync(0xffffffffu, sum1, 2);
        l0r = l0r * f0 + sum0;
        l1r = l1r * f1 + sum1;

        // ---- O = O*fac + P V : 16 rows x 128 d per warp, fp16 2-term ----
#pragma unroll
        for (int nf = 0; nf < 16; nf++) {
            o[nf][0] *= f0; o[nf][1] *= f0;
            o[nf][2] *= f1; o[nf][3] *= f1;
        }
#pragma unroll
        for (int g = 0; g < 4; g++) {
            uint32_t vrow = (uint32_t)((g * 16 + (lane & 15)) * 128);
            uint32_t vcb  = (uint32_t)(lane >> 4) * 16;
#pragma unroll
            for (int p = 0; p < 8; p++) {
                uint32_t vo = stb + (uint32_t)(p >> 2) * 8192 +
                              swz(vrow + (uint32_t)((2*p) & 7) * 16 + vcb);
                uint32_t vh4[4], vl4[4];
                ldsm_x4_t(vh4, sb + AVH_ + vo);
                ldsm_x4_t(vl4, sb + AVL_ + vo);
                mma16816(o[2*p],   ph[g], &vh4[0]);
                mma16816(o[2*p+1], ph[g], &vh4[2]);
                mma16816(o[2*p],   ph[g], &vl4[0]);
                mma16816(o[2*p+1], ph[g], &vl4[2]);
            }
        }
    }

    // ---- epilogue: normalize, write O as single fp16 (stream = nf>>3) ----
    float li0 = 1.f / l0r, li1 = 1.f / l1r;
    const int rr = wr * 16 + (lane >> 2);
#pragma unroll
    for (int nf = 0; nf < 16; nf++) {
        int strm = nf >> 3;
        int dcol = (nf & 7) * 8 + (lane & 3) * 2;
        size_t base = (size_t)strm * BN * C_
                    + ((size_t)(b * N_ + qt * 128 + rr)) * C_ + h * 64 + dcol;
        *(uint32_t*)&g_Oh[base] = pack_h2(o[nf][0] * li0, o[nf][1] * li0);
        *(uint32_t*)&g_Oh[base + 8 * C_] = pack_h2(o[nf][2] * li1, o[nf][3] * li1);
    }
}

// ---------------------------------------------------------------------------
extern "C" void kernel_launch(void* const* d_in, const int* in_sizes, int n_in,
                              void* d_out, int out_size)
{
    (void)in_sizes; (void)n_in; (void)out_size;
    const float* x1    = (const float*)d_in[0];
    const float* x2    = (const float*)d_in[1];
    const float* Wqkv  = (const float*)d_in[2];
    const float* bqkv  = (const float*)d_in[3];
    const float* Wproj = (const float*)d_in[4];
    const float* bproj = (const float*)d_in[5];
    float* out = (float*)d_out;

    split_all<<<8448, 256>>>(x1, x2, Wqkv, Wproj);

    const int gemm_smem = 68608;   // 1024 + 2x32KB stages; Osm fits too
    cudaFuncSetAttribute(tc_gemm<0>, cudaFuncAttributeMaxDynamicSharedMemorySize, gemm_smem);
    tc_gemm<0><<<dim3(18, 32, 2), 128, gemm_smem>>>(bqkv, nullptr);

    const int attn_smem = 196608;
    cudaFuncSetAttribute(attn_mma, cudaFuncAttributeMaxDynamicSharedMemorySize, attn_smem);
    attn_mma<<<dim3(8, 48), 256, attn_smem>>>();

    cudaFuncSetAttribute(tc_gemm<1>, cudaFuncAttributeMaxDynamicSharedMemorySize, gemm_smem);
    tc_gemm<1><<<dim3(6, 32, 2), 128, gemm_smem>>>(bproj, out);
}

// round 10
// speedup vs baseline: 1.4351x; 1.0490x over previous
#include <cuda_runtime.h>
#include <cuda_fp16.h>
#include <cstdint>

#define B_ 4
#define N_ 1024
#define C_ 768
#define H_ 12
#define BN 4096
#define SCALE 0.125f

// ---------------- scratch (static device globals; no allocations) ----------
__device__ __align__(16) __half g_Qh[(size_t)B_*H_*N_*128];  // SCALE folded
__device__ __align__(16) __half g_Ql[(size_t)B_*H_*N_*128];
__device__ __align__(16) __half g_Kh[(size_t)B_*H_*N_*128];
__device__ __align__(16) __half g_Kl[(size_t)B_*H_*N_*128];
__device__ __align__(16) __half g_Vh[(size_t)B_*H_*N_*128];  // single plane

__device__ __align__(16) __half g_Xh[(size_t)2*BN*C_];
__device__ __align__(16) __half g_Xl[(size_t)2*BN*C_];
__device__ __align__(16) __half g_Wqh[(size_t)3*C_*C_];
__device__ __align__(16) __half g_Wql[(size_t)3*C_*C_];
__device__ __align__(16) __half g_Wph[(size_t)C_*C_];
__device__ __align__(16) __half g_Wpl[(size_t)C_*C_];
__device__ __align__(16) __half g_Oh[(size_t)2*BN*C_];   // single fp16

// ---------------- helpers ---------------------------------------------------
__device__ __forceinline__ uint32_t smem_u32(const void* p) {
    uint32_t a;
    asm("{ .reg .u64 t; cvta.to.shared.u64 t, %1; cvt.u32.u64 %0, t; }"
        : "=r"(a) : "l"(p));
    return a;
}
__device__ __forceinline__ uint32_t swz(uint32_t o) {   // 128B-row swizzle
    return o ^ ((o >> 3) & 0x70);
}
__device__ __forceinline__ uint32_t swz64(uint32_t o) { // 64B-row swizzle
    return o ^ ((o >> 3) & 0x30);
}
__device__ __forceinline__ void cpa16(uint32_t dst, const void* src) {
    asm volatile("cp.async.cg.shared.global [%0], [%1], 16;" :: "r"(dst), "l"(src));
}
__device__ __forceinline__ void cpa_commit() {
    asm volatile("cp.async.commit_group;" ::: "memory");
}
template<int N>
__device__ __forceinline__ void cpa_wait() {
    asm volatile("cp.async.wait_group %0;" :: "n"(N) : "memory");
}
__device__ __forceinline__ void ldsm_x4(uint32_t* r, uint32_t addr) {
    asm volatile("ldmatrix.sync.aligned.m8n8.x4.shared.b16 {%0,%1,%2,%3}, [%4];"
                 : "=r"(r[0]), "=r"(r[1]), "=r"(r[2]), "=r"(r[3]) : "r"(addr));
}
__device__ __forceinline__ void ldsm_x4_t(uint32_t* r, uint32_t addr) {
    asm volatile("ldmatrix.sync.aligned.m8n8.x4.trans.shared.b16 {%0,%1,%2,%3}, [%4];"
                 : "=r"(r[0]), "=r"(r[1]), "=r"(r[2]), "=r"(r[3]) : "r"(addr));
}
__device__ __forceinline__ void mma16816(float* d, const uint32_t* a, const uint32_t* b) {
    asm volatile(
        "mma.sync.aligned.m16n8k16.row.col.f32.f16.f16.f32 "
        "{%0,%1,%2,%3}, {%4,%5,%6,%7}, {%8,%9}, {%0,%1,%2,%3};"
        : "+f"(d[0]), "+f"(d[1]), "+f"(d[2]), "+f"(d[3])
        : "r"(a[0]), "r"(a[1]), "r"(a[2]), "r"(a[3]), "r"(b[0]), "r"(b[1]));
}
__device__ __forceinline__ uint32_t pack_h2(float a, float b) {
    __half2 t = __floats2half2_rn(a, b);
    return *(uint32_t*)&t;
}

// ---------------------------------------------------------------------------
// fused split kernel: fp32 -> (fp16 hi, fp16 lo) for x1, x2, Wqkv, Wproj
// ---------------------------------------------------------------------------
#define NX4  (BN * C_ / 4)          // 786432 -> 3072 blocks

__global__ __launch_bounds__(256) void split_all(
    const float* __restrict__ x1, const float* __restrict__ x2,
    const float* __restrict__ Wq, const float* __restrict__ Wp)
{
    int bid = blockIdx.x;
    const float* src;
    __half *hi, *lo;
    size_t off4;
    int i;
    if (bid < 3072) {
        src = x1; hi = g_Xh; lo = g_Xl; off4 = 0;
        i = bid * 256 + threadIdx.x;
    } else if (bid < 6144) {
        src = x2; hi = g_Xh; lo = g_Xl; off4 = NX4;
        i = (bid - 3072) * 256 + threadIdx.x;
    } else if (bid < 7872) {
        src = Wq; hi = g_Wqh; lo = g_Wql; off4 = 0;
        i = (bid - 6144) * 256 + threadIdx.x;
    } else {
        src = Wp; hi = g_Wph; lo = g_Wpl; off4 = 0;
        i = (bid - 7872) * 256 + threadIdx.x;
    }
    float4 v = ((const float4*)src)[i];
    __half h0 = __float2half(v.x);
    __half h1 = __float2half(v.y);
    __half h2 = __float2half(v.z);
    __half h3 = __float2half(v.w);
    size_t o = off4 + (size_t)i;
    ((uint32_t*)hi)[o*2 + 0] = pack_h2(v.x, v.y);
    ((uint32_t*)hi)[o*2 + 1] = pack_h2(v.z, v.w);
    ((uint32_t*)lo)[o*2 + 0] = pack_h2(v.x - __half2float(h0), v.y - __half2float(h1));
    ((uint32_t*)lo)[o*2 + 1] = pack_h2(v.z - __half2float(h2), v.w - __half2float(h3));
}

// ---------------------------------------------------------------------------
// qkv GEMM: 128x128 CTA tile, 128 threads (4 warps, 64x64), K-chunk 32,
// 2-stage cp.async, 2 CTAs/SM.  Q/K tiles 3-term, V tiles 2-term.
// V epilogue writes single fp16 plane.
// ---------------------------------------------------------------------------
__device__ __forceinline__ void gemm_issue_chunk(
    uint32_t sbase,
    const __half* Ah, const __half* Al,
    const __half* Bh, const __half* Bl,
    int m0, int c0, int kc, int tid, bool loadAl)
{
#pragma unroll
    for (int it = 0; it < 4; it++) {
        int u = tid + it * 128;
        int r = u >> 2, ch = u & 3;
        uint32_t so = swz64((uint32_t)(r * 64 + ch * 16));
        const size_t aoff = (size_t)(m0 + r) * C_ + kc + ch * 8;
        const size_t boff = (size_t)(c0 + r) * C_ + kc + ch * 8;
        cpa16(sbase +     0 + so, Ah + aoff);
        if (loadAl) cpa16(sbase + 8192 + so, Al + aoff);
        cpa16(sbase + 16384 + so, Bh + boff);
        cpa16(sbase + 24576 + so, Bl + boff);
    }
    cpa_commit();
}

__global__ __launch_bounds__(128, 2) void qkv_gemm(const float* __restrict__ bias)
{
    extern __shared__ char sm[];
    const uint32_t sb = smem_u32(sm) + 1024;
    const int tid = threadIdx.x;
    const int lane = tid & 31, wid = tid >> 5;
    const int wm = wid & 1, wn = wid >> 1;
    const int stream = blockIdx.z;
    const int m0 = blockIdx.y * 128;
    const int c0 = blockIdx.x * 128;
    const int s_tile = c0 / C_;                 // uniform per CTA
    const bool use3 = (s_tile < 2);             // Q,K 3-term; V 2-term

    const __half* __restrict__ Ah = g_Xh + (size_t)stream * BN * C_;
    const __half* __restrict__ Al = g_Xl + (size_t)stream * BN * C_;
    const __half* __restrict__ Bh = g_Wqh;
    const __half* __restrict__ Bl = g_Wql;

    float acc[4][8][4];
#pragma unroll
    for (int i = 0; i < 4; i++)
#pragma unroll
        for (int j = 0; j < 8; j++)
#pragma unroll
            for (int k = 0; k < 4; k++) acc[i][j][k] = 0.f;

    const int a_r  = wm*64 + (lane & 15);
    const int a_cb = (lane >> 4) * 16;
    const int b_r  = wn*64 + (lane & 7) + ((lane >> 4) & 1)*8;
    const int b_cb = ((lane >> 3) & 1) * 16;

    const int NCH = C_ / 32;   // 24
    gemm_issue_chunk(sb, Ah, Al, Bh, Bl, m0, c0, 0, tid, use3);

    for (int ch = 0; ch < NCH; ch++) {
        const uint32_t stb = (uint32_t)(ch & 1) * 32768u;
        cpa_wait<0>();
        __syncthreads();
        if (ch + 1 < NCH)
            gemm_issue_chunk(sb + ((ch + 1) & 1) * 32768u,
                             Ah, Al, Bh, Bl, m0, c0, (ch + 1) * 32, tid, use3);

#pragma unroll
        for (int kk = 0; kk < 2; kk++) {
            uint32_t bfh[16], bfl[16];
#pragma unroll
            for (int p = 0; p < 4; p++) {
                uint32_t bo = swz64((uint32_t)((b_r + p*16) * 64 + kk*32 + b_cb));
                ldsm_x4(&bfh[p*4], sb + stb + 16384 + bo);
                ldsm_x4(&bfl[p*4], sb + stb + 24576 + bo);
            }
#pragma unroll
            for (int mf = 0; mf < 4; mf++) {
                uint32_t ao = swz64((uint32_t)((a_r + mf*16) * 64 + kk*32 + a_cb));
                uint32_t ah[4], al[4];
                ldsm_x4(ah, sb + stb + ao);
                if (use3) ldsm_x4(al, sb + stb + 8192 + ao);
#pragma unroll
                for (int p = 0; p < 4; p++) {
                    mma16816(acc[mf][2*p],   ah, &bfh[4*p]);
                    mma16816(acc[mf][2*p+1], ah, &bfh[4*p+2]);
                }
#pragma unroll
                for (int p = 0; p < 4; p++) {
                    mma16816(acc[mf][2*p],   ah, &bfl[4*p]);
                    mma16816(acc[mf][2*p+1], ah, &bfl[4*p+2]);
                }
                if (use3) {
#pragma unroll
                    for (int p = 0; p < 4; p++) {
                        mma16816(acc[mf][2*p],   al, &bfh[4*p]);
                        mma16816(acc[mf][2*p+1], al, &bfh[4*p+2]);
                    }
                }
            }
        }
    }
    __syncthreads();

    float* Osm = (float*)(sm + 1024);      // [128][132]
#pragma unroll
    for (int mf = 0; mf < 4; mf++) {
#pragma unroll
        for (int nf = 0; nf < 8; nf++) {
            int row = wm*64 + mf*16 + (lane >> 2);
            int col = wn*64 + nf*8 + (lane & 3)*2;
            Osm[row       * 132 + col    ] = acc[mf][nf][0];
            Osm[row       * 132 + col + 1] = acc[mf][nf][1];
            Osm[(row + 8) * 132 + col    ] = acc[mf][nf][2];
            Osm[(row + 8) * 132 + col + 1] = acc[mf][nf][3];
        }
    }
    __syncthreads();

#pragma unroll
    for (int it = 0; it < 32; it++) {
        int idx = tid + it * 128;
        int r = idx >> 5, j4 = idx & 31;
        float4 v = *(float4*)&Osm[r * 132 + j4 * 4];
        float4 bb = *(const float4*)&bias[c0 + j4 * 4];
        v.x += bb.x; v.y += bb.y; v.z += bb.z; v.w += bb.w;
        int m = m0 + r;
        int cg = c0 + j4 * 4;
        int rem = cg - s_tile * C_;
        int h = rem >> 6, d = rem & 63;
        if (s_tile == 0) { v.x *= SCALE; v.y *= SCALE; v.z *= SCALE; v.w *= SCALE; }
        uint2 hv;
        hv.x = pack_h2(v.x, v.y); hv.y = pack_h2(v.z, v.w);
        int b = m >> 10, n = m & 1023;
        size_t base = ((size_t)(b * H_ + h) * N_ + n) * 128 + stream * 64 + d;
        if (s_tile == 2) {
            *(uint2*)&g_Vh[base] = hv;
        } else {
            __half h0 = __float2half(v.x);
            __half h1 = __float2half(v.y);
            __half h2 = __float2half(v.z);
            __half h3 = __float2half(v.w);
            uint2 lv;
            lv.x = pack_h2(v.x - __half2float(h0), v.y - __half2float(h1));
            lv.y = pack_h2(v.z - __half2float(h2), v.w - __half2float(h3));
            __half* bufh = (s_tile == 0) ? g_Qh : g_Kh;
            __half* bufl = (s_tile == 0) ? g_Ql : g_Kl;
            *(uint2*)&bufh[base] = hv;
            *(uint2*)&bufl[base] = lv;
        }
    }
}

// ---------------------------------------------------------------------------
// proj GEMM: 64x128 CTA tile (M64 for wave-fill), 128 threads (4 warps,
// 32x64 each), K-chunk 32, 2-stage cp.async, 2-term (Oh*Wh + Oh*Wl).
// smem: 1024 + 2 x 20480 = 41984 B -> 3+ CTAs/SM.
// ---------------------------------------------------------------------------
__device__ __forceinline__ void proj_issue_chunk(
    uint32_t sbase, const __half* Ah, const __half* Bh, const __half* Bl,
    int m0, int c0, int kc, int tid)
{
#pragma unroll
    for (int it = 0; it < 2; it++) {       // A: 64 rows x 4 chunks = 256
        int u = tid + it * 128;
        int r = u >> 2, ch = u & 3;
        uint32_t so = swz64((uint32_t)(r * 64 + ch * 16));
        cpa16(sbase + so, Ah + (size_t)(m0 + r) * C_ + kc + ch * 8);
    }
#pragma unroll
    for (int it = 0; it < 4; it++) {       // B: 128 rows x 4 chunks = 512 x2
        int u = tid + it * 128;
        int r = u >> 2, ch = u & 3;
        uint32_t so = swz64((uint32_t)(r * 64 + ch * 16));
        const size_t boff = (size_t)(c0 + r) * C_ + kc + ch * 8;
        cpa16(sbase +  4096 + so, Bh + boff);
        cpa16(sbase + 12288 + so, Bl + boff);
    }
    cpa_commit();
}

__global__ __launch_bounds__(128, 3) void proj_gemm(const float* __restrict__ bias,
                                                    float* __restrict__ outp)
{
    extern __shared__ char sm[];
    const uint32_t sb = smem_u32(sm) + 1024;
    const int tid = threadIdx.x;
    const int lane = tid & 31, wid = tid >> 5;
    const int wm = wid & 1, wn = wid >> 1;    // 2x2 grid: warp = 32 x 64
    const int stream = blockIdx.z;
    const int m0 = blockIdx.y * 64;
    const int c0 = blockIdx.x * 128;

    const __half* __restrict__ Ah = g_Oh + (size_t)stream * BN * C_;
    const __half* __restrict__ Bh = g_Wph;
    const __half* __restrict__ Bl = g_Wpl;

    float acc[2][8][4];
#pragma unroll
    for (int i = 0; i < 2; i++)
#pragma unroll
        for (int j = 0; j < 8; j++)
#pragma unroll
            for (int k = 0; k < 4; k++) acc[i][j][k] = 0.f;

    const int a_r  = wm*32 + (lane & 15);
    const int a_cb = (lane >> 4) * 16;
    const int b_r  = wn*64 + (lane & 7) + ((lane >> 4) & 1)*8;
    const int b_cb = ((lane >> 3) & 1) * 16;

    const int NCH = C_ / 32;   // 24
    proj_issue_chunk(sb, Ah, Bh, Bl, m0, c0, 0, tid);

    for (int ch = 0; ch < NCH; ch++) {
        const uint32_t stb = (uint32_t)(ch & 1) * 20480u;
        cpa_wait<0>();
        __syncthreads();
        if (ch + 1 < NCH)
            proj_issue_chunk(sb + ((ch + 1) & 1) * 20480u,
                             Ah, Bh, Bl, m0, c0, (ch + 1) * 32, tid);

#pragma unroll
        for (int kk = 0; kk < 2; kk++) {
            uint32_t bfh[16], bfl[16];
#pragma unroll
            for (int p = 0; p < 4; p++) {
                uint32_t bo = swz64((uint32_t)((b_r + p*16) * 64 + kk*32 + b_cb));
                ldsm_x4(&bfh[p*4], sb + stb +  4096 + bo);
                ldsm_x4(&bfl[p*4], sb + stb + 12288 + bo);
            }
#pragma unroll
            for (int mf = 0; mf < 2; mf++) {
                uint32_t ao = swz64((uint32_t)((a_r + mf*16) * 64 + kk*32 + a_cb));
                uint32_t ah[4];
                ldsm_x4(ah, sb + stb + ao);
#pragma unroll
                for (int p = 0; p < 4; p++) {
                    mma16816(acc[mf][2*p],   ah, &bfh[4*p]);
                    mma16816(acc[mf][2*p+1], ah, &bfh[4*p+2]);
                }
#pragma unroll
                for (int p = 0; p < 4; p++) {
                    mma16816(acc[mf][2*p],   ah, &bfl[4*p]);
                    mma16816(acc[mf][2*p+1], ah, &bfl[4*p+2]);
                }
            }
        }
    }
    __syncthreads();

    float* Osm = (float*)(sm + 1024);      // [64][132] = 33792 B, fits
#pragma unroll
    for (int mf = 0; mf < 2; mf++) {
#pragma unroll
        for (int nf = 0; nf < 8; nf++) {
            int row = wm*32 + mf*16 + (lane >> 2);
            int col = wn*64 + nf*8 + (lane & 3)*2;
            Osm[row       * 132 + col    ] = acc[mf][nf][0];
            Osm[row       * 132 + col + 1] = acc[mf][nf][1];
            Osm[(row + 8) * 132 + col    ] = acc[mf][nf][2];
            Osm[(row + 8) * 132 + col + 1] = acc[mf][nf][3];
        }
    }
    __syncthreads();

    float* Y = outp + (size_t)stream * BN * C_;
#pragma unroll
    for (int it = 0; it < 16; it++) {
        int idx = tid + it * 128;             // 0..2047
        int r = idx >> 5, j4 = idx & 31;
        float4 v = *(float4*)&Osm[r * 132 + j4 * 4];
        float4 bb = *(const float4*)&bias[c0 + j4 * 4];
        v.x += bb.x; v.y += bb.y; v.z += bb.z; v.w += bb.w;
        *(float4*)&Y[(size_t)(m0 + r) * C_ + c0 + j4 * 4] = v;
    }
}

// ---------------------------------------------------------------------------
// flash attention: HMMA fp16, 128 q-rows/CTA, 8 warps x 16 rows x 64 kv-cols.
// S = QK^T 3-term; PV 1-term (P fp16, V single fp16).
// Warp-local softmax, register P, cp.async 2-stage K/V, 1 barrier/tile.
// smem: 2 stages x 48KB (Kh,Kl,Vh) + Q 64KB = 163840 B
// ---------------------------------------------------------------------------
#define ASTG_ 49152u
#define AKH_ 0u
#define AKL_ 16384u
#define AVH_ 32768u
#define AQH_ 98304u
#define AQL_ 131072u

__device__ __forceinline__ void attn_issue_kv(
    uint32_t sb, uint32_t stb,
    const __half* kh_g, const __half* kl_g, const __half* vh_g, int tid)
{
#pragma unroll
    for (int it = 0; it < 4; it++) {
        int idx = tid + it * 256;          // 0..1023: 64 rows x 16 16B-chunks
        int row = idx >> 4, ch = idx & 15;
        int src = row * 128 + ch * 8;
        uint32_t dst = stb + (uint32_t)(ch >> 3) * 8192 + swz((uint32_t)(row * 128 + (ch & 7) * 16));
        cpa16(sb + AKH_ + dst, kh_g + src);
        cpa16(sb + AKL_ + dst, kl_g + src);
        cpa16(sb + AVH_ + dst, vh_g + src);
    }
    cpa_commit();
}

__global__ __launch_bounds__(256, 1) void attn_mma()
{
    extern __shared__ char sm[];
    const uint32_t sb = smem_u32(sm);

    const int tid = threadIdx.x;
    const int lane = tid & 31, wr = tid >> 5;
    const int qt = blockIdx.x, bh = blockIdx.y;
    const int b = bh / H_, h = bh - b * H_;
    const size_t kvb = (size_t)bh * N_ * 128;

    const __half* kh_g = g_Kh + kvb;
    const __half* kl_g = g_Kl + kvb;
    const __half* vh_g = g_Vh + kvb;

    attn_issue_kv(sb, 0, kh_g, kl_g, vh_g, tid);

    {
        const __half* qh_g = g_Qh + kvb + (size_t)qt * 128 * 128;
        const __half* ql_g = g_Ql + kvb + (size_t)qt * 128 * 128;
#pragma unroll
        for (int it = 0; it < 8; it++) {
            int idx = tid + it * 256;
            int row = idx >> 4, ch = idx & 15;
            uint32_t dst = (uint32_t)(ch >> 3) * 16384 + swz((uint32_t)(row * 128 + (ch & 7) * 16));
            *(uint4*)(sm + AQH_ + dst) = *(const uint4*)(qh_g + row * 128 + ch * 8);
            *(uint4*)(sm + AQL_ + dst) = *(const uint4*)(ql_g + row * 128 + ch * 8);
        }
    }

    float m0r = -1e30f, m1r = -1e30f, l0r = 0.f, l1r = 0.f;
    float o[16][4];
#pragma unroll
    for (int i = 0; i < 16; i++)
#pragma unroll
        for (int j = 0; j < 4; j++) o[i][j] = 0.f;

    const int qrow = wr * 16 + (lane & 15);
    const int k_r  = (lane & 7) + ((lane >> 4) & 1) * 8;
    const int k_cb = ((lane >> 3) & 1) * 16;

    for (int kt = 0; kt < 16; kt++) {
        const uint32_t stb = (uint32_t)(kt & 1) * ASTG_;
        cpa_wait<0>();
        __syncthreads();
        if (kt < 15)
            attn_issue_kv(sb, (uint32_t)((kt + 1) & 1) * ASTG_,
                          kh_g + (size_t)(kt + 1) * 64 * 128,
                          kl_g + (size_t)(kt + 1) * 64 * 128,
                          vh_g + (size_t)(kt + 1) * 64 * 128, tid);

        // ---- S = Q K^T : 16 rows x 64 cols per warp, k=128, fp16 3-term ----
        float sacc[8][4];
#pragma unroll
        for (int i = 0; i < 8; i++)
#pragma unroll
            for (int j = 0; j < 4; j++) sacc[i][j] = 0.f;

#pragma unroll
        for (int k16 = 0; k16 < 8; k16++) {
            uint32_t qo = (uint32_t)(k16 >> 2) * 16384 +
                          swz((uint32_t)(qrow * 128 + (k16 & 3) * 32 + (lane >> 4) * 16));
            uint32_t ah[4], al[4];
            ldsm_x4(ah, sb + AQH_ + qo);
            ldsm_x4(al, sb + AQL_ + qo);
            uint32_t kpl = stb + (uint32_t)(k16 >> 2) * 8192;
            uint32_t kcb = (uint32_t)((k16 & 3) * 32) + k_cb;
            uint32_t kfh[16], kfl[16];
#pragma unroll
            for (int p = 0; p < 4; p++) {
                uint32_t ko = kpl + swz((uint32_t)((k_r + p*16) * 128) + kcb);
                ldsm_x4(&kfh[4*p], sb + AKH_ + ko);
                ldsm_x4(&kfl[4*p], sb + AKL_ + ko);
            }
#pragma unroll
            for (int p = 0; p < 4; p++) {
                mma16816(sacc[2*p],   ah, &kfh[4*p]);
                mma16816(sacc[2*p+1], ah, &kfh[4*p+2]);
            }
#pragma unroll
            for (int p = 0; p < 4; p++) {
                mma16816(sacc[2*p],   ah, &kfl[4*p]);
                mma16816(sacc[2*p+1], ah, &kfl[4*p+2]);
            }
#pragma unroll
            for (int p = 0; p < 4; p++) {
                mma16816(sacc[2*p],   al, &kfh[4*p]);
                mma16816(sacc[2*p+1], al, &kfh[4*p+2]);
            }
        }

        // ---- warp-local online softmax ----
        float pm0 = -1e30f, pm1 = -1e30f;
#pragma unroll
        for (int nf = 0; nf < 8; nf++) {
            pm0 = fmaxf(pm0, fmaxf(sacc[nf][0], sacc[nf][1]));
            pm1 = fmaxf(pm1, fmaxf(sacc[nf][2], sacc[nf][3]));
        }
        pm0 = fmaxf(pm0, __shfl_xor_sync(0xffffffffu, pm0, 1));
        pm0 = fmaxf(pm0, __shfl_xor_sync(0xffffffffu, pm0, 2));
        pm1 = fmaxf(pm1, __shfl_xor_sync(0xffffffffu, pm1, 1));
        pm1 = fmaxf(pm1, __shfl_xor_sync(0xffffffffu, pm1, 2));
        float mn0 = fmaxf(m0r, pm0);
        float mn1 = fmaxf(m1r, pm1);
        float f0 = __expf(m0r - mn0);
        float f1 = __expf(m1r - mn1);
        m0r = mn0; m1r = mn1;

        uint32_t ph[4][4];
        float sum0 = 0.f, sum1 = 0.f;
#pragma unroll
        for (int g = 0; g < 4; g++) {
            float q0 = __expf(sacc[2*g][0]   - mn0);
            float q1 = __expf(sacc[2*g][1]   - mn0);
            float q2 = __expf(sacc[2*g][2]   - mn1);
            float q3 = __expf(sacc[2*g][3]   - mn1);
            float s0 = __expf(sacc[2*g+1][0] - mn0);
            float s1 = __expf(sacc[2*g+1][1] - mn0);
            float s2 = __expf(sacc[2*g+1][2] - mn1);
            float s3 = __expf(sacc[2*g+1][3] - mn1);
            sum0 += (q0 + q1) + (s0 + s1);
            sum1 += (q2 + q3) + (s2 + s3);
            ph[g][0] = pack_h2(q0, q1);
            ph[g][1] = pack_h2(q2, q3);
            ph[g][2] = pack_h2(s0, s1);
            ph[g][3] = pack_h2(s2, s3);
        }
        sum0 += __shfl_xor_sync(0xffffffffu, sum0, 1);
        sum0 += __shfl_xor_sync(0xffffffffu, sum0, 2);
        sum1 += __shfl_xor_sync(0xffffffffu, sum1, 1);
        sum1 += __shfl_xor_sync(0xffffffffu, sum1, 2);
        l0r = l0r * f0 + sum0;
        l1r = l1r * f1 + sum1;

        // ---- O = O*fac + P V : 16 rows x 128 d per warp, 1-term ----
#pragma unroll
        for (int nf = 0; nf < 16; nf++) {
            o[nf][0] *= f0; o[nf][1] *= f0;
            o[nf][2] *= f1; o[nf][3] *= f1;
        }
#pragma unroll
        for (int g = 0; g < 4; g++) {
            uint32_t vrow = (uint32_t)((g * 16 + (lane & 15)) * 128);
            uint32_t vcb  = (uint32_t)(lane >> 4) * 16;
#pragma unroll
            for (int p = 0; p < 8; p++) {
                uint32_t vo = stb + (uint32_t)(p >> 2) * 8192 +
                              swz(vrow + (uint32_t)((2*p) & 7) * 16 + vcb);
                uint32_t vh4[4];
                ldsm_x4_t(vh4, sb + AVH_ + vo);
                mma16816(o[2*p],   ph[g], &vh4[0]);
                mma16816(o[2*p+1], ph[g], &vh4[2]);
            }
        }
    }

    // ---- epilogue: normalize, write O as single fp16 (stream = nf>>3) ----
    float li0 = 1.f / l0r, li1 = 1.f / l1r;
    const int rr = wr * 16 + (lane >> 2);
#pragma unroll
    for (int nf = 0; nf < 16; nf++) {
        int strm = nf >> 3;
        int dcol = (nf & 7) * 8 + (lane & 3) * 2;
        size_t base = (size_t)strm * BN * C_
                    + ((size_t)(b * N_ + qt * 128 + rr)) * C_ + h * 64 + dcol;
        *(uint32_t*)&g_Oh[base] = pack_h2(o[nf][0] * li0, o[nf][1] * li0);
        *(uint32_t*)&g_Oh[base + 8 * C_] = pack_h2(o[nf][2] * li1, o[nf][3] * li1);
    }
}

// ---------------------------------------------------------------------------
extern "C" void kernel_launch(void* const* d_in, const int* in_sizes, int n_in,
                              void* d_out, int out_size)
{
    (void)in_sizes; (void)n_in; (void)out_size;
    const float* x1    = (const float*)d_in[0];
    const float* x2    = (const float*)d_in[1];
    const float* Wqkv  = (const float*)d_in[2];
    const float* bqkv  = (const float*)d_in[3];
    const float* Wproj = (const float*)d_in[4];
    const float* bproj = (const float*)d_in[5];
    float* out = (float*)d_out;

    split_all<<<8448, 256>>>(x1, x2, Wqkv, Wproj);

    const int qkv_smem = 68608;
    cudaFuncSetAttribute(qkv_gemm, cudaFuncAttributeMaxDynamicSharedMemorySize, qkv_smem);
    qkv_gemm<<<dim3(18, 32, 2), 128, qkv_smem>>>(bqkv);

    const int attn_smem = 163840;
    cudaFuncSetAttribute(attn_mma, cudaFuncAttributeMaxDynamicSharedMemorySize, attn_smem);
    attn_mma<<<dim3(8, 48), 256, attn_smem>>>();

    const int proj_smem = 41984;
    cudaFuncSetAttribute(proj_gemm, cudaFuncAttributeMaxDynamicSharedMemorySize, proj_smem);
    proj_gemm<<<dim3(6, 64, 2), 128, proj_smem>>>(bproj, out);
}

// round 11
// speedup vs baseline: 1.5398x; 1.0730x over previous
#include <cuda_runtime.h>
#include <cuda_fp16.h>
#include <cstdint>

#define B_ 4
#define N_ 1024
#define C_ 768
#define H_ 12
#define BN 4096
#define SCALE 0.125f

// ---------------- scratch (static device globals; no allocations) ----------
__device__ __align__(16) __half g_Qh[(size_t)B_*H_*N_*128];  // SCALE folded
__device__ __align__(16) __half g_Ql[(size_t)B_*H_*N_*128];
__device__ __align__(16) __half g_Kh[(size_t)B_*H_*N_*128];  // single plane
__device__ __align__(16) __half g_Vh[(size_t)B_*H_*N_*128];  // single plane

__device__ __align__(16) __half g_Xh[(size_t)2*BN*C_];
__device__ __align__(16) __half g_Xl[(size_t)2*BN*C_];
__device__ __align__(16) __half g_Wqh[(size_t)3*C_*C_];
__device__ __align__(16) __half g_Wql[(size_t)3*C_*C_];
__device__ __align__(16) __half g_Wph[(size_t)C_*C_];
__device__ __align__(16) __half g_Wpl[(size_t)C_*C_];
__device__ __align__(16) __half g_Oh[(size_t)2*BN*C_];   // single fp16

// ---------------- helpers ---------------------------------------------------
__device__ __forceinline__ uint32_t smem_u32(const void* p) {
    uint32_t a;
    asm("{ .reg .u64 t; cvta.to.shared.u64 t, %1; cvt.u32.u64 %0, t; }"
        : "=r"(a) : "l"(p));
    return a;
}
__device__ __forceinline__ uint32_t swz(uint32_t o) {   // 128B-row swizzle
    return o ^ ((o >> 3) & 0x70);
}
__device__ __forceinline__ uint32_t swz64(uint32_t o) { // 64B-row swizzle
    return o ^ ((o >> 3) & 0x30);
}
__device__ __forceinline__ void cpa16(uint32_t dst, const void* src) {
    asm volatile("cp.async.cg.shared.global [%0], [%1], 16;" :: "r"(dst), "l"(src));
}
__device__ __forceinline__ void cpa_commit() {
    asm volatile("cp.async.commit_group;" ::: "memory");
}
template<int N>
__device__ __forceinline__ void cpa_wait() {
    asm volatile("cp.async.wait_group %0;" :: "n"(N) : "memory");
}
__device__ __forceinline__ void ldsm_x4(uint32_t* r, uint32_t addr) {
    asm volatile("ldmatrix.sync.aligned.m8n8.x4.shared.b16 {%0,%1,%2,%3}, [%4];"
                 : "=r"(r[0]), "=r"(r[1]), "=r"(r[2]), "=r"(r[3]) : "r"(addr));
}
__device__ __forceinline__ void ldsm_x4_t(uint32_t* r, uint32_t addr) {
    asm volatile("ldmatrix.sync.aligned.m8n8.x4.trans.shared.b16 {%0,%1,%2,%3}, [%4];"
                 : "=r"(r[0]), "=r"(r[1]), "=r"(r[2]), "=r"(r[3]) : "r"(addr));
}
__device__ __forceinline__ void mma16816(float* d, const uint32_t* a, const uint32_t* b) {
    asm volatile(
        "mma.sync.aligned.m16n8k16.row.col.f32.f16.f16.f32 "
        "{%0,%1,%2,%3}, {%4,%5,%6,%7}, {%8,%9}, {%0,%1,%2,%3};"
        : "+f"(d[0]), "+f"(d[1]), "+f"(d[2]), "+f"(d[3])
        : "r"(a[0]), "r"(a[1]), "r"(a[2]), "r"(a[3]), "r"(b[0]), "r"(b[1]));
}
__device__ __forceinline__ uint32_t pack_h2(float a, float b) {
    __half2 t = __floats2half2_rn(a, b);
    return *(uint32_t*)&t;
}

// ---------------------------------------------------------------------------
// fused split kernel: fp32 -> (fp16 hi, fp16 lo) for x1, x2, Wqkv, Wproj
// ---------------------------------------------------------------------------
#define NX4  (BN * C_ / 4)          // 786432 -> 3072 blocks

__global__ __launch_bounds__(256) void split_all(
    const float* __restrict__ x1, const float* __restrict__ x2,
    const float* __restrict__ Wq, const float* __restrict__ Wp)
{
    int bid = blockIdx.x;
    const float* src;
    __half *hi, *lo;
    size_t off4;
    int i;
    if (bid < 3072) {
        src = x1; hi = g_Xh; lo = g_Xl; off4 = 0;
        i = bid * 256 + threadIdx.x;
    } else if (bid < 6144) {
        src = x2; hi = g_Xh; lo = g_Xl; off4 = NX4;
        i = (bid - 3072) * 256 + threadIdx.x;
    } else if (bid < 7872) {
        src = Wq; hi = g_Wqh; lo = g_Wql; off4 = 0;
        i = (bid - 6144) * 256 + threadIdx.x;
    } else {
        src = Wp; hi = g_Wph; lo = g_Wpl; off4 = 0;
        i = (bid - 7872) * 256 + threadIdx.x;
    }
    float4 v = ((const float4*)src)[i];
    __half h0 = __float2half(v.x);
    __half h1 = __float2half(v.y);
    __half h2 = __float2half(v.z);
    __half h3 = __float2half(v.w);
    size_t o = off4 + (size_t)i;
    ((uint32_t*)hi)[o*2 + 0] = pack_h2(v.x, v.y);
    ((uint32_t*)hi)[o*2 + 1] = pack_h2(v.z, v.w);
    ((uint32_t*)lo)[o*2 + 0] = pack_h2(v.x - __half2float(h0), v.y - __half2float(h1));
    ((uint32_t*)lo)[o*2 + 1] = pack_h2(v.z - __half2float(h2), v.w - __half2float(h3));
}

// ---------------------------------------------------------------------------
// qkv GEMM: 128x128 CTA tile, 128 threads (4 warps, 64x64), K-chunk 32,
// 2-stage cp.async, 2 CTAs/SM.  Q/K tiles 3-term, V tiles 2-term.
// Epilogue: Q -> hi/lo planes (SCALE folded); K,V -> single fp16 plane.
// ---------------------------------------------------------------------------
__device__ __forceinline__ void gemm_issue_chunk(
    uint32_t sbase,
    const __half* Ah, const __half* Al,
    const __half* Bh, const __half* Bl,
    int m0, int c0, int kc, int tid, bool loadAl)
{
#pragma unroll
    for (int it = 0; it < 4; it++) {
        int u = tid + it * 128;
        int r = u >> 2, ch = u & 3;
        uint32_t so = swz64((uint32_t)(r * 64 + ch * 16));
        const size_t aoff = (size_t)(m0 + r) * C_ + kc + ch * 8;
        const size_t boff = (size_t)(c0 + r) * C_ + kc + ch * 8;
        cpa16(sbase +     0 + so, Ah + aoff);
        if (loadAl) cpa16(sbase + 8192 + so, Al + aoff);
        cpa16(sbase + 16384 + so, Bh + boff);
        cpa16(sbase + 24576 + so, Bl + boff);
    }
    cpa_commit();
}

__global__ __launch_bounds__(128, 2) void qkv_gemm(const float* __restrict__ bias)
{
    extern __shared__ char sm[];
    const uint32_t sb = smem_u32(sm) + 1024;
    const int tid = threadIdx.x;
    const int lane = tid & 31, wid = tid >> 5;
    const int wm = wid & 1, wn = wid >> 1;
    const int stream = blockIdx.z;
    const int m0 = blockIdx.y * 128;
    const int c0 = blockIdx.x * 128;
    const int s_tile = c0 / C_;                 // uniform per CTA
    const bool use3 = (s_tile < 2);             // Q,K 3-term; V 2-term

    const __half* __restrict__ Ah = g_Xh + (size_t)stream * BN * C_;
    const __half* __restrict__ Al = g_Xl + (size_t)stream * BN * C_;
    const __half* __restrict__ Bh = g_Wqh;
    const __half* __restrict__ Bl = g_Wql;

    float acc[4][8][4];
#pragma unroll
    for (int i = 0; i < 4; i++)
#pragma unroll
        for (int j = 0; j < 8; j++)
#pragma unroll
            for (int k = 0; k < 4; k++) acc[i][j][k] = 0.f;

    const int a_r  = wm*64 + (lane & 15);
    const int a_cb = (lane >> 4) * 16;
    const int b_r  = wn*64 + (lane & 7) + ((lane >> 4) & 1)*8;
    const int b_cb = ((lane >> 3) & 1) * 16;

    const int NCH = C_ / 32;   // 24
    gemm_issue_chunk(sb, Ah, Al, Bh, Bl, m0, c0, 0, tid, use3);

    for (int ch = 0; ch < NCH; ch++) {
        const uint32_t stb = (uint32_t)(ch & 1) * 32768u;
        cpa_wait<0>();
        __syncthreads();
        if (ch + 1 < NCH)
            gemm_issue_chunk(sb + ((ch + 1) & 1) * 32768u,
                             Ah, Al, Bh, Bl, m0, c0, (ch + 1) * 32, tid, use3);

#pragma unroll
        for (int kk = 0; kk < 2; kk++) {
            uint32_t bfh[16], bfl[16];
#pragma unroll
            for (int p = 0; p < 4; p++) {
                uint32_t bo = swz64((uint32_t)((b_r + p*16) * 64 + kk*32 + b_cb));
                ldsm_x4(&bfh[p*4], sb + stb + 16384 + bo);
                ldsm_x4(&bfl[p*4], sb + stb + 24576 + bo);
            }
#pragma unroll
            for (int mf = 0; mf < 4; mf++) {
                uint32_t ao = swz64((uint32_t)((a_r + mf*16) * 64 + kk*32 + a_cb));
                uint32_t ah[4], al[4];
                ldsm_x4(ah, sb + stb + ao);
                if (use3) ldsm_x4(al, sb + stb + 8192 + ao);
#pragma unroll
                for (int p = 0; p < 4; p++) {
                    mma16816(acc[mf][2*p],   ah, &bfh[4*p]);
                    mma16816(acc[mf][2*p+1], ah, &bfh[4*p+2]);
                }
#pragma unroll
                for (int p = 0; p < 4; p++) {
                    mma16816(acc[mf][2*p],   ah, &bfl[4*p]);
                    mma16816(acc[mf][2*p+1], ah, &bfl[4*p+2]);
                }
                if (use3) {
#pragma unroll
                    for (int p = 0; p < 4; p++) {
                        mma16816(acc[mf][2*p],   al, &bfh[4*p]);
                        mma16816(acc[mf][2*p+1], al, &bfh[4*p+2]);
                    }
                }
            }
        }
    }
    __syncthreads();

    float* Osm = (float*)(sm + 1024);      // [128][132]
#pragma unroll
    for (int mf = 0; mf < 4; mf++) {
#pragma unroll
        for (int nf = 0; nf < 8; nf++) {
            int row = wm*64 + mf*16 + (lane >> 2);
            int col = wn*64 + nf*8 + (lane & 3)*2;
            Osm[row       * 132 + col    ] = acc[mf][nf][0];
            Osm[row       * 132 + col + 1] = acc[mf][nf][1];
            Osm[(row + 8) * 132 + col    ] = acc[mf][nf][2];
            Osm[(row + 8) * 132 + col + 1] = acc[mf][nf][3];
        }
    }
    __syncthreads();

#pragma unroll
    for (int it = 0; it < 32; it++) {
        int idx = tid + it * 128;
        int r = idx >> 5, j4 = idx & 31;
        float4 v = *(float4*)&Osm[r * 132 + j4 * 4];
        float4 bb = *(const float4*)&bias[c0 + j4 * 4];
        v.x += bb.x; v.y += bb.y; v.z += bb.z; v.w += bb.w;
        int m = m0 + r;
        int cg = c0 + j4 * 4;
        int rem = cg - s_tile * C_;
        int h = rem >> 6, d = rem & 63;
        if (s_tile == 0) { v.x *= SCALE; v.y *= SCALE; v.z *= SCALE; v.w *= SCALE; }
        uint2 hv;
        hv.x = pack_h2(v.x, v.y); hv.y = pack_h2(v.z, v.w);
        int b = m >> 10, n = m & 1023;
        size_t base = ((size_t)(b * H_ + h) * N_ + n) * 128 + stream * 64 + d;
        if (s_tile == 0) {
            __half h0 = __float2half(v.x);
            __half h1 = __float2half(v.y);
            __half h2 = __float2half(v.z);
            __half h3 = __float2half(v.w);
            uint2 lv;
            lv.x = pack_h2(v.x - __half2float(h0), v.y - __half2float(h1));
            lv.y = pack_h2(v.z - __half2float(h2), v.w - __half2float(h3));
            *(uint2*)&g_Qh[base] = hv;
            *(uint2*)&g_Ql[base] = lv;
        } else if (s_tile == 1) {
            *(uint2*)&g_Kh[base] = hv;
        } else {
            *(uint2*)&g_Vh[base] = hv;
        }
    }
}

// ---------------------------------------------------------------------------
// proj GEMM: 64x128 CTA tile, 128 threads (4 warps, 32x64 each), K-chunk 32,
// 2-stage cp.async, 2-term (Oh*Wh + Oh*Wl).
// ---------------------------------------------------------------------------
__device__ __forceinline__ void proj_issue_chunk(
    uint32_t sbase, const __half* Ah, const __half* Bh, const __half* Bl,
    int m0, int c0, int kc, int tid)
{
#pragma unroll
    for (int it = 0; it < 2; it++) {
        int u = tid + it * 128;
        int r = u >> 2, ch = u & 3;
        uint32_t so = swz64((uint32_t)(r * 64 + ch * 16));
        cpa16(sbase + so, Ah + (size_t)(m0 + r) * C_ + kc + ch * 8);
    }
#pragma unroll
    for (int it = 0; it < 4; it++) {
        int u = tid + it * 128;
        int r = u >> 2, ch = u & 3;
        uint32_t so = swz64((uint32_t)(r * 64 + ch * 16));
        const size_t boff = (size_t)(c0 + r) * C_ + kc + ch * 8;
        cpa16(sbase +  4096 + so, Bh + boff);
        cpa16(sbase + 12288 + so, Bl + boff);
    }
    cpa_commit();
}

__global__ __launch_bounds__(128, 3) void proj_gemm(const float* __restrict__ bias,
                                                    float* __restrict__ outp)
{
    extern __shared__ char sm[];
    const uint32_t sb = smem_u32(sm) + 1024;
    const int tid = threadIdx.x;
    const int lane = tid & 31, wid = tid >> 5;
    const int wm = wid & 1, wn = wid >> 1;
    const int stream = blockIdx.z;
    const int m0 = blockIdx.y * 64;
    const int c0 = blockIdx.x * 128;

    const __half* __restrict__ Ah = g_Oh + (size_t)stream * BN * C_;
    const __half* __restrict__ Bh = g_Wph;
    const __half* __restrict__ Bl = g_Wpl;

    float acc[2][8][4];
#pragma unroll
    for (int i = 0; i < 2; i++)
#pragma unroll
        for (int j = 0; j < 8; j++)
#pragma unroll
            for (int k = 0; k < 4; k++) acc[i][j][k] = 0.f;

    const int a_r  = wm*32 + (lane & 15);
    const int a_cb = (lane >> 4) * 16;
    const int b_r  = wn*64 + (lane & 7) + ((lane >> 4) & 1)*8;
    const int b_cb = ((lane >> 3) & 1) * 16;

    const int NCH = C_ / 32;   // 24
    proj_issue_chunk(sb, Ah, Bh, Bl, m0, c0, 0, tid);

    for (int ch = 0; ch < NCH; ch++) {
        const uint32_t stb = (uint32_t)(ch & 1) * 20480u;
        cpa_wait<0>();
        __syncthreads();
        if (ch + 1 < NCH)
            proj_issue_chunk(sb + ((ch + 1) & 1) * 20480u,
                             Ah, Bh, Bl, m0, c0, (ch + 1) * 32, tid);

#pragma unroll
        for (int kk = 0; kk < 2; kk++) {
            uint32_t bfh[16], bfl[16];
#pragma unroll
            for (int p = 0; p < 4; p++) {
                uint32_t bo = swz64((uint32_t)((b_r + p*16) * 64 + kk*32 + b_cb));
                ldsm_x4(&bfh[p*4], sb + stb +  4096 + bo);
                ldsm_x4(&bfl[p*4], sb + stb + 12288 + bo);
            }
#pragma unroll
            for (int mf = 0; mf < 2; mf++) {
                uint32_t ao = swz64((uint32_t)((a_r + mf*16) * 64 + kk*32 + a_cb));
                uint32_t ah[4];
                ldsm_x4(ah, sb + stb + ao);
#pragma unroll
                for (int p = 0; p < 4; p++) {
                    mma16816(acc[mf][2*p],   ah, &bfh[4*p]);
                    mma16816(acc[mf][2*p+1], ah, &bfh[4*p+2]);
                }
#pragma unroll
                for (int p = 0; p < 4; p++) {
                    mma16816(acc[mf][2*p],   ah, &bfl[4*p]);
                    mma16816(acc[mf][2*p+1], ah, &bfl[4*p+2]);
                }
            }
        }
    }
    __syncthreads();

    float* Osm = (float*)(sm + 1024);      // [64][132]
#pragma unroll
    for (int mf = 0; mf < 2; mf++) {
#pragma unroll
        for (int nf = 0; nf < 8; nf++) {
            int row = wm*32 + mf*16 + (lane >> 2);
            int col = wn*64 + nf*8 + (lane & 3)*2;
            Osm[row       * 132 + col    ] = acc[mf][nf][0];
            Osm[row       * 132 + col + 1] = acc[mf][nf][1];
            Osm[(row + 8) * 132 + col    ] = acc[mf][nf][2];
            Osm[(row + 8) * 132 + col + 1] = acc[mf][nf][3];
        }
    }
    __syncthreads();

    float* Y = outp + (size_t)stream * BN * C_;
#pragma unroll
    for (int it = 0; it < 16; it++) {
        int idx = tid + it * 128;
        int r = idx >> 5, j4 = idx & 31;
        float4 v = *(float4*)&Osm[r * 132 + j4 * 4];
        float4 bb = *(const float4*)&bias[c0 + j4 * 4];
        v.x += bb.x; v.y += bb.y; v.z += bb.z; v.w += bb.w;
        *(float4*)&Y[(size_t)(m0 + r) * C_ + c0 + j4 * 4] = v;
    }
}

// ---------------------------------------------------------------------------
// flash attention: HMMA fp16, 128 q-rows/CTA, 8 warps x 16 rows x 64 kv-cols.
// S = Qh*Kh + Ql*Kh (2-term; K single plane).  PV 1-term (V single plane).
// Warp-local softmax, register P, cp.async 2-stage K/V, 1 barrier/tile.
// smem: 2 stages x 32KB (Kh,Vh) + Q hi/lo 64KB = 131072 B
// ---------------------------------------------------------------------------
#define ASTG_ 32768u
#define AKH_ 0u
#define AVH_ 16384u
#define AQH_ 65536u
#define AQL_ 98304u

__device__ __forceinline__ void attn_issue_kv(
    uint32_t sb, uint32_t stb,
    const __half* kh_g, const __half* vh_g, int tid)
{
#pragma unroll
    for (int it = 0; it < 4; it++) {
        int idx = tid + it * 256;          // 0..1023: 64 rows x 16 16B-chunks
        int row = idx >> 4, ch = idx & 15;
        int src = row * 128 + ch * 8;
        uint32_t dst = stb + (uint32_t)(ch >> 3) * 8192 + swz((uint32_t)(row * 128 + (ch & 7) * 16));
        cpa16(sb + AKH_ + dst, kh_g + src);
        cpa16(sb + AVH_ + dst, vh_g + src);
    }
    cpa_commit();
}

__global__ __launch_bounds__(256, 1) void attn_mma()
{
    extern __shared__ char sm[];
    const uint32_t sb = smem_u32(sm);

    const int tid = threadIdx.x;
    const int lane = tid & 31, wr = tid >> 5;
    const int qt = blockIdx.x, bh = blockIdx.y;
    const int b = bh / H_, h = bh - b * H_;
    const size_t kvb = (size_t)bh * N_ * 128;

    const __half* kh_g = g_Kh + kvb;
    const __half* vh_g = g_Vh + kvb;

    attn_issue_kv(sb, 0, kh_g, vh_g, tid);

    {
        const __half* qh_g = g_Qh + kvb + (size_t)qt * 128 * 128;
        const __half* ql_g = g_Ql + kvb + (size_t)qt * 128 * 128;
#pragma unroll
        for (int it = 0; it < 8; it++) {
            int idx = tid + it * 256;
            int row = idx >> 4, ch = idx & 15;
            uint32_t dst = (uint32_t)(ch >> 3) * 16384 + swz((uint32_t)(row * 128 + (ch & 7) * 16));
            *(uint4*)(sm + AQH_ + dst) = *(const uint4*)(qh_g + row * 128 + ch * 8);
            *(uint4*)(sm + AQL_ + dst) = *(const uint4*)(ql_g + row * 128 + ch * 8);
        }
    }

    float m0r = -1e30f, m1r = -1e30f, l0r = 0.f, l1r = 0.f;
    float o[16][4];
#pragma unroll
    for (int i = 0; i < 16; i++)
#pragma unroll
        for (int j = 0; j < 4; j++) o[i][j] = 0.f;

    const int qrow = wr * 16 + (lane & 15);
    const int k_r  = (lane & 7) + ((lane >> 4) & 1) * 8;
    const int k_cb = ((lane >> 3) & 1) * 16;

    for (int kt = 0; kt < 16; kt++) {
        const uint32_t stb = (uint32_t)(kt & 1) * ASTG_;
        cpa_wait<0>();
        __syncthreads();
        if (kt < 15)
            attn_issue_kv(sb, (uint32_t)((kt + 1) & 1) * ASTG_,
                          kh_g + (size_t)(kt + 1) * 64 * 128,
                          vh_g + (size_t)(kt + 1) * 64 * 128, tid);

        // ---- S = Q K^T : 16 rows x 64 cols per warp, k=128, 2-term ----
        float sacc[8][4];
#pragma unroll
        for (int i = 0; i < 8; i++)
#pragma unroll
            for (int j = 0; j < 4; j++) sacc[i][j] = 0.f;

#pragma unroll
        for (int k16 = 0; k16 < 8; k16++) {
            uint32_t qo = (uint32_t)(k16 >> 2) * 16384 +
                          swz((uint32_t)(qrow * 128 + (k16 & 3) * 32 + (lane >> 4) * 16));
            uint32_t ah[4], al[4];
            ldsm_x4(ah, sb + AQH_ + qo);
            ldsm_x4(al, sb + AQL_ + qo);
            uint32_t kpl = stb + (uint32_t)(k16 >> 2) * 8192;
            uint32_t kcb = (uint32_t)((k16 & 3) * 32) + k_cb;
            uint32_t kfh[16];
#pragma unroll
            for (int p = 0; p < 4; p++) {
                uint32_t ko = kpl + swz((uint32_t)((k_r + p*16) * 128) + kcb);
                ldsm_x4(&kfh[4*p], sb + AKH_ + ko);
            }
#pragma unroll
            for (int p = 0; p < 4; p++) {
                mma16816(sacc[2*p],   ah, &kfh[4*p]);
                mma16816(sacc[2*p+1], ah, &kfh[4*p+2]);
            }
#pragma unroll
            for (int p = 0; p < 4; p++) {
                mma16816(sacc[2*p],   al, &kfh[4*p]);
                mma16816(sacc[2*p+1], al, &kfh[4*p+2]);
            }
        }

        // ---- warp-local online softmax ----
        float pm0 = -1e30f, pm1 = -1e30f;
#pragma unroll
        for (int nf = 0; nf < 8; nf++) {
            pm0 = fmaxf(pm0, fmaxf(sacc[nf][0], sacc[nf][1]));
            pm1 = fmaxf(pm1, fmaxf(sacc[nf][2], sacc[nf][3]));
        }
        pm0 = fmaxf(pm0, __shfl_xor_sync(0xffffffffu, pm0, 1));
        pm0 = fmaxf(pm0, __shfl_xor_sync(0xffffffffu, pm0, 2));
        pm1 = fmaxf(pm1, __shfl_xor_sync(0xffffffffu, pm1, 1));
        pm1 = fmaxf(pm1, __shfl_xor_sync(0xffffffffu, pm1, 2));
        float mn0 = fmaxf(m0r, pm0);
        float mn1 = fmaxf(m1r, pm1);
        float f0 = __expf(m0r - mn0);
        float f1 = __expf(m1r - mn1);
        m0r = mn0; m1r = mn1;

        uint32_t ph[4][4];
        float sum0 = 0.f, sum1 = 0.f;
#pragma unroll
        for (int g = 0; g < 4; g++) {
            float q0 = __expf(sacc[2*g][0]   - mn0);
            float q1 = __expf(sacc[2*g][1]   - mn0);
            float q2 = __expf(sacc[2*g][2]   - mn1);
            float q3 = __expf(sacc[2*g][3]   - mn1);
            float s0 = __expf(sacc[2*g+1][0] - mn0);
            float s1 = __expf(sacc[2*g+1][1] - mn0);
            float s2 = __expf(sacc[2*g+1][2] - mn1);
            float s3 = __expf(sacc[2*g+1][3] - mn1);
            sum0 += (q0 + q1) + (s0 + s1);
            sum1 += (q2 + q3) + (s2 + s3);
            ph[g][0] = pack_h2(q0, q1);
            ph[g][1] = pack_h2(q2, q3);
            ph[g][2] = pack_h2(s0, s1);
            ph[g][3] = pack_h2(s2, s3);
        }
        sum0 += __shfl_xor_sync(0xffffffffu, sum0, 1);
        sum0 += __shfl_xor_sync(0xffffffffu, sum0, 2);
        sum1 += __shfl_xor_sync(0xffffffffu, sum1, 1);
        sum1 += __shfl_xor_sync(0xffffffffu, sum1, 2);
        l0r = l0r * f0 + sum0;
        l1r = l1r * f1 + sum1;

        // ---- O = O*fac + P V : 16 rows x 128 d per warp, 1-term ----
#pragma unroll
        for (int nf = 0; nf < 16; nf++) {
            o[nf][0] *= f0; o[nf][1] *= f0;
            o[nf][2] *= f1; o[nf][3] *= f1;
        }
#pragma unroll
        for (int g = 0; g < 4; g++) {
            uint32_t vrow = (uint32_t)((g * 16 + (lane & 15)) * 128);
            uint32_t vcb  = (uint32_t)(lane >> 4) * 16;
#pragma unroll
            for (int p = 0; p < 8; p++) {
                uint32_t vo = stb + (uint32_t)(p >> 2) * 8192 +
                              swz(vrow + (uint32_t)((2*p) & 7) * 16 + vcb);
                uint32_t vh4[4];
                ldsm_x4_t(vh4, sb + AVH_ + vo);
                mma16816(o[2*p],   ph[g], &vh4[0]);
                mma16816(o[2*p+1], ph[g], &vh4[2]);
            }
        }
    }

    // ---- epilogue: normalize, write O as single fp16 (stream = nf>>3) ----
    float li0 = 1.f / l0r, li1 = 1.f / l1r;
    const int rr = wr * 16 + (lane >> 2);
#pragma unroll
    for (int nf = 0; nf < 16; nf++) {
        int strm = nf >> 3;
        int dcol = (nf & 7) * 8 + (lane & 3) * 2;
        size_t base = (size_t)strm * BN * C_
                    + ((size_t)(b * N_ + qt * 128 + rr)) * C_ + h * 64 + dcol;
        *(uint32_t*)&g_Oh[base] = pack_h2(o[nf][0] * li0, o[nf][1] * li0);
        *(uint32_t*)&g_Oh[base + 8 * C_] = pack_h2(o[nf][2] * li1, o[nf][3] * li1);
    }
}

// ---------------------------------------------------------------------------
extern "C" void kernel_launch(void* const* d_in, const int* in_sizes, int n_in,
                              void* d_out, int out_size)
{
    (void)in_sizes; (void)n_in; (void)out_size;
    const float* x1    = (const float*)d_in[0];
    const float* x2    = (const float*)d_in[1];
    const float* Wqkv  = (const float*)d_in[2];
    const float* bqkv  = (const float*)d_in[3];
    const float* Wproj = (const float*)d_in[4];
    const float* bproj = (const float*)d_in[5];
    float* out = (float*)d_out;

    split_all<<<8448, 256>>>(x1, x2, Wqkv, Wproj);

    const int qkv_smem = 68608;
    cudaFuncSetAttribute(qkv_gemm, cudaFuncAttributeMaxDynamicSharedMemorySize, qkv_smem);
    qkv_gemm<<<dim3(18, 32, 2), 128, qkv_smem>>>(bqkv);

    const int attn_smem = 131072;
    cudaFuncSetAttribute(attn_mma, cudaFuncAttributeMaxDynamicSharedMemorySize, attn_smem);
    attn_mma<<<dim3(8, 48), 256, attn_smem>>>();

    const int proj_smem = 41984;
    cudaFuncSetAttribute(proj_gemm, cudaFuncAttributeMaxDynamicSharedMemorySize, proj_smem);
    proj_gemm<<<dim3(6, 64, 2), 128, proj_smem>>>(bproj, out);
}

// round 12
// speedup vs baseline: 1.6132x; 1.0477x over previous
#include <cuda_runtime.h>
#include <cuda_fp16.h>
#include <cstdint>

#define B_ 4
#define N_ 1024
#define C_ 768
#define H_ 12
#define BN 4096
#define SCALE 0.125f

// ---------------- scratch (static device globals; no allocations) ----------
__device__ __align__(16) __half g_Qh[(size_t)B_*H_*N_*128];  // SCALE folded
__device__ __align__(16) __half g_Ql[(size_t)B_*H_*N_*128];
__device__ __align__(16) __half g_Kh[(size_t)B_*H_*N_*128];  // single plane
__device__ __align__(16) __half g_Vh[(size_t)B_*H_*N_*128];  // single plane

__device__ __align__(16) __half g_Xh[(size_t)2*BN*C_];
__device__ __align__(16) __half g_Xl[(size_t)2*BN*C_];
__device__ __align__(16) __half g_Wqh[(size_t)3*C_*C_];
__device__ __align__(16) __half g_Wql[(size_t)3*C_*C_];
__device__ __align__(16) __half g_Wph[(size_t)C_*C_];
__device__ __align__(16) __half g_Wpl[(size_t)C_*C_];
__device__ __align__(16) __half g_Oh[(size_t)2*BN*C_];   // single fp16

// ---------------- helpers ---------------------------------------------------
__device__ __forceinline__ uint32_t smem_u32(const void* p) {
    uint32_t a;
    asm("{ .reg .u64 t; cvta.to.shared.u64 t, %1; cvt.u32.u64 %0, t; }"
        : "=r"(a) : "l"(p));
    return a;
}
__device__ __forceinline__ uint32_t swz(uint32_t o) {   // 128B-row swizzle
    return o ^ ((o >> 3) & 0x70);
}
__device__ __forceinline__ uint32_t swz64(uint32_t o) { // 64B-row swizzle
    return o ^ ((o >> 3) & 0x30);
}
__device__ __forceinline__ void cpa16(uint32_t dst, const void* src) {
    asm volatile("cp.async.cg.shared.global [%0], [%1], 16;" :: "r"(dst), "l"(src));
}
__device__ __forceinline__ void cpa_commit() {
    asm volatile("cp.async.commit_group;" ::: "memory");
}
template<int N>
__device__ __forceinline__ void cpa_wait() {
    asm volatile("cp.async.wait_group %0;" :: "n"(N) : "memory");
}
__device__ __forceinline__ void ldsm_x4(uint32_t* r, uint32_t addr) {
    asm volatile("ldmatrix.sync.aligned.m8n8.x4.shared.b16 {%0,%1,%2,%3}, [%4];"
                 : "=r"(r[0]), "=r"(r[1]), "=r"(r[2]), "=r"(r[3]) : "r"(addr));
}
__device__ __forceinline__ void ldsm_x4_t(uint32_t* r, uint32_t addr) {
    asm volatile("ldmatrix.sync.aligned.m8n8.x4.trans.shared.b16 {%0,%1,%2,%3}, [%4];"
                 : "=r"(r[0]), "=r"(r[1]), "=r"(r[2]), "=r"(r[3]) : "r"(addr));
}
__device__ __forceinline__ void mma16816(float* d, const uint32_t* a, const uint32_t* b) {
    asm volatile(
        "mma.sync.aligned.m16n8k16.row.col.f32.f16.f16.f32 "
        "{%0,%1,%2,%3}, {%4,%5,%6,%7}, {%8,%9}, {%0,%1,%2,%3};"
        : "+f"(d[0]), "+f"(d[1]), "+f"(d[2]), "+f"(d[3])
        : "r"(a[0]), "r"(a[1]), "r"(a[2]), "r"(a[3]), "r"(b[0]), "r"(b[1]));
}
__device__ __forceinline__ uint32_t pack_h2(float a, float b) {
    __half2 t = __floats2half2_rn(a, b);
    return *(uint32_t*)&t;
}

// ---------------------------------------------------------------------------
// fused split kernel: fp32 -> (fp16 hi, fp16 lo) for x1, x2, Wqkv, Wproj
// ---------------------------------------------------------------------------
#define NX4  (BN * C_ / 4)          // 786432 -> 3072 blocks

__global__ __launch_bounds__(256) void split_all(
    const float* __restrict__ x1, const float* __restrict__ x2,
    const float* __restrict__ Wq, const float* __restrict__ Wp)
{
    int bid = blockIdx.x;
    const float* src;
    __half *hi, *lo;
    size_t off4;
    int i;
    if (bid < 3072) {
        src = x1; hi = g_Xh; lo = g_Xl; off4 = 0;
        i = bid * 256 + threadIdx.x;
    } else if (bid < 6144) {
        src = x2; hi = g_Xh; lo = g_Xl; off4 = NX4;
        i = (bid - 3072) * 256 + threadIdx.x;
    } else if (bid < 7872) {
        src = Wq; hi = g_Wqh; lo = g_Wql; off4 = 0;
        i = (bid - 6144) * 256 + threadIdx.x;
    } else {
        src = Wp; hi = g_Wph; lo = g_Wpl; off4 = 0;
        i = (bid - 7872) * 256 + threadIdx.x;
    }
    float4 v = ((const float4*)src)[i];
    __half h0 = __float2half(v.x);
    __half h1 = __float2half(v.y);
    __half h2 = __float2half(v.z);
    __half h3 = __float2half(v.w);
    size_t o = off4 + (size_t)i;
    ((uint32_t*)hi)[o*2 + 0] = pack_h2(v.x, v.y);
    ((uint32_t*)hi)[o*2 + 1] = pack_h2(v.z, v.w);
    ((uint32_t*)lo)[o*2 + 0] = pack_h2(v.x - __half2float(h0), v.y - __half2float(h1));
    ((uint32_t*)lo)[o*2 + 1] = pack_h2(v.z - __half2float(h2), v.w - __half2float(h3));
}

// ---------------------------------------------------------------------------
// qkv GEMM: 128x128 CTA tile, 128 threads (4 warps, 64x64), K-chunk 32,
// 2-stage cp.async, 2 CTAs/SM.  Q tiles 3-term; K,V tiles 2-term
// (K,V are stored single-fp16, so the Xl*Wh polish is below storage rounding).
// Epilogue: Q -> hi/lo planes (SCALE folded); K,V -> single fp16 plane.
// ---------------------------------------------------------------------------
__device__ __forceinline__ void gemm_issue_chunk(
    uint32_t sbase,
    const __half* Ah, const __half* Al,
    const __half* Bh, const __half* Bl,
    int m0, int c0, int kc, int tid, bool loadAl)
{
#pragma unroll
    for (int it = 0; it < 4; it++) {
        int u = tid + it * 128;
        int r = u >> 2, ch = u & 3;
        uint32_t so = swz64((uint32_t)(r * 64 + ch * 16));
        const size_t aoff = (size_t)(m0 + r) * C_ + kc + ch * 8;
        const size_t boff = (size_t)(c0 + r) * C_ + kc + ch * 8;
        cpa16(sbase +     0 + so, Ah + aoff);
        if (loadAl) cpa16(sbase + 8192 + so, Al + aoff);
        cpa16(sbase + 16384 + so, Bh + boff);
        cpa16(sbase + 24576 + so, Bl + boff);
    }
    cpa_commit();
}

__global__ __launch_bounds__(128, 2) void qkv_gemm(const float* __restrict__ bias)
{
    extern __shared__ char sm[];
    const uint32_t sb = smem_u32(sm) + 1024;
    const int tid = threadIdx.x;
    const int lane = tid & 31, wid = tid >> 5;
    const int wm = wid & 1, wn = wid >> 1;
    const int stream = blockIdx.z;
    const int m0 = blockIdx.y * 128;
    const int c0 = blockIdx.x * 128;
    const int s_tile = c0 / C_;                 // uniform per CTA
    const bool use3 = (s_tile == 0);            // Q 3-term; K,V 2-term

    const __half* __restrict__ Ah = g_Xh + (size_t)stream * BN * C_;
    const __half* __restrict__ Al = g_Xl + (size_t)stream * BN * C_;
    const __half* __restrict__ Bh = g_Wqh;
    const __half* __restrict__ Bl = g_Wql;

    float acc[4][8][4];
#pragma unroll
    for (int i = 0; i < 4; i++)
#pragma unroll
        for (int j = 0; j < 8; j++)
#pragma unroll
            for (int k = 0; k < 4; k++) acc[i][j][k] = 0.f;

    const int a_r  = wm*64 + (lane & 15);
    const int a_cb = (lane >> 4) * 16;
    const int b_r  = wn*64 + (lane & 7) + ((lane >> 4) & 1)*8;
    const int b_cb = ((lane >> 3) & 1) * 16;

    const int NCH = C_ / 32;   // 24
    gemm_issue_chunk(sb, Ah, Al, Bh, Bl, m0, c0, 0, tid, use3);

    for (int ch = 0; ch < NCH; ch++) {
        const uint32_t stb = (uint32_t)(ch & 1) * 32768u;
        cpa_wait<0>();
        __syncthreads();
        if (ch + 1 < NCH)
            gemm_issue_chunk(sb + ((ch + 1) & 1) * 32768u,
                             Ah, Al, Bh, Bl, m0, c0, (ch + 1) * 32, tid, use3);

#pragma unroll
        for (int kk = 0; kk < 2; kk++) {
            uint32_t bfh[16], bfl[16];
#pragma unroll
            for (int p = 0; p < 4; p++) {
                uint32_t bo = swz64((uint32_t)((b_r + p*16) * 64 + kk*32 + b_cb));
                ldsm_x4(&bfh[p*4], sb + stb + 16384 + bo);
                ldsm_x4(&bfl[p*4], sb + stb + 24576 + bo);
            }
#pragma unroll
            for (int mf = 0; mf < 4; mf++) {
                uint32_t ao = swz64((uint32_t)((a_r + mf*16) * 64 + kk*32 + a_cb));
                uint32_t ah[4], al[4];
                ldsm_x4(ah, sb + stb + ao);
                if (use3) ldsm_x4(al, sb + stb + 8192 + ao);
#pragma unroll
                for (int p = 0; p < 4; p++) {
                    mma16816(acc[mf][2*p],   ah, &bfh[4*p]);
                    mma16816(acc[mf][2*p+1], ah, &bfh[4*p+2]);
                }
#pragma unroll
                for (int p = 0; p < 4; p++) {
                    mma16816(acc[mf][2*p],   ah, &bfl[4*p]);
                    mma16816(acc[mf][2*p+1], ah, &bfl[4*p+2]);
                }
                if (use3) {
#pragma unroll
                    for (int p = 0; p < 4; p++) {
                        mma16816(acc[mf][2*p],   al, &bfh[4*p]);
                        mma16816(acc[mf][2*p+1], al, &bfh[4*p+2]);
                    }
                }
            }
        }
    }
    __syncthreads();

    float* Osm = (float*)(sm + 1024);      // [128][132]
#pragma unroll
    for (int mf = 0; mf < 4; mf++) {
#pragma unroll
        for (int nf = 0; nf < 8; nf++) {
            int row = wm*64 + mf*16 + (lane >> 2);
            int col = wn*64 + nf*8 + (lane & 3)*2;
            Osm[row       * 132 + col    ] = acc[mf][nf][0];
            Osm[row       * 132 + col + 1] = acc[mf][nf][1];
            Osm[(row + 8) * 132 + col    ] = acc[mf][nf][2];
            Osm[(row + 8) * 132 + col + 1] = acc[mf][nf][3];
        }
    }
    __syncthreads();

#pragma unroll
    for (int it = 0; it < 32; it++) {
        int idx = tid + it * 128;
        int r = idx >> 5, j4 = idx & 31;
        float4 v = *(float4*)&Osm[r * 132 + j4 * 4];
        float4 bb = *(const float4*)&bias[c0 + j4 * 4];
        v.x += bb.x; v.y += bb.y; v.z += bb.z; v.w += bb.w;
        int m = m0 + r;
        int cg = c0 + j4 * 4;
        int rem = cg - s_tile * C_;
        int h = rem >> 6, d = rem & 63;
        if (s_tile == 0) { v.x *= SCALE; v.y *= SCALE; v.z *= SCALE; v.w *= SCALE; }
        uint2 hv;
        hv.x = pack_h2(v.x, v.y); hv.y = pack_h2(v.z, v.w);
        int b = m >> 10, n = m & 1023;
        size_t base = ((size_t)(b * H_ + h) * N_ + n) * 128 + stream * 64 + d;
        if (s_tile == 0) {
            __half h0 = __float2half(v.x);
            __half h1 = __float2half(v.y);
            __half h2 = __float2half(v.z);
            __half h3 = __float2half(v.w);
            uint2 lv;
            lv.x = pack_h2(v.x - __half2float(h0), v.y - __half2float(h1));
            lv.y = pack_h2(v.z - __half2float(h2), v.w - __half2float(h3));
            *(uint2*)&g_Qh[base] = hv;
            *(uint2*)&g_Ql[base] = lv;
        } else if (s_tile == 1) {
            *(uint2*)&g_Kh[base] = hv;
        } else {
            *(uint2*)&g_Vh[base] = hv;
        }
    }
}

// ---------------------------------------------------------------------------
// proj GEMM: 64x128 CTA tile, 128 threads (4 warps, 32x64 each), K-chunk 32,
// 2-stage cp.async, 2-term (Oh*Wh + Oh*Wl).
// ---------------------------------------------------------------------------
__device__ __forceinline__ void proj_issue_chunk(
    uint32_t sbase, const __half* Ah, const __half* Bh, const __half* Bl,
    int m0, int c0, int kc, int tid)
{
#pragma unroll
    for (int it = 0; it < 2; it++) {
        int u = tid + it * 128;
        int r = u >> 2, ch = u & 3;
        uint32_t so = swz64((uint32_t)(r * 64 + ch * 16));
        cpa16(sbase + so, Ah + (size_t)(m0 + r) * C_ + kc + ch * 8);
    }
#pragma unroll
    for (int it = 0; it < 4; it++) {
        int u = tid + it * 128;
        int r = u >> 2, ch = u & 3;
        uint32_t so = swz64((uint32_t)(r * 64 + ch * 16));
        const size_t boff = (size_t)(c0 + r) * C_ + kc + ch * 8;
        cpa16(sbase +  4096 + so, Bh + boff);
        cpa16(sbase + 12288 + so, Bl + boff);
    }
    cpa_commit();
}

__global__ __launch_bounds__(128, 3) void proj_gemm(const float* __restrict__ bias,
                                                    float* __restrict__ outp)
{
    extern __shared__ char sm[];
    const uint32_t sb = smem_u32(sm) + 1024;
    const int tid = threadIdx.x;
    const int lane = tid & 31, wid = tid >> 5;
    const int wm = wid & 1, wn = wid >> 1;
    const int stream = blockIdx.z;
    const int m0 = blockIdx.y * 64;
    const int c0 = blockIdx.x * 128;

    const __half* __restrict__ Ah = g_Oh + (size_t)stream * BN * C_;
    const __half* __restrict__ Bh = g_Wph;
    const __half* __restrict__ Bl = g_Wpl;

    float acc[2][8][4];
#pragma unroll
    for (int i = 0; i < 2; i++)
#pragma unroll
        for (int j = 0; j < 8; j++)
#pragma unroll
            for (int k = 0; k < 4; k++) acc[i][j][k] = 0.f;

    const int a_r  = wm*32 + (lane & 15);
    const int a_cb = (lane >> 4) * 16;
    const int b_r  = wn*64 + (lane & 7) + ((lane >> 4) & 1)*8;
    const int b_cb = ((lane >> 3) & 1) * 16;

    const int NCH = C_ / 32;   // 24
    proj_issue_chunk(sb, Ah, Bh, Bl, m0, c0, 0, tid);

    for (int ch = 0; ch < NCH; ch++) {
        const uint32_t stb = (uint32_t)(ch & 1) * 20480u;
        cpa_wait<0>();
        __syncthreads();
        if (ch + 1 < NCH)
            proj_issue_chunk(sb + ((ch + 1) & 1) * 20480u,
                             Ah, Bh, Bl, m0, c0, (ch + 1) * 32, tid);

#pragma unroll
        for (int kk = 0; kk < 2; kk++) {
            uint32_t bfh[16], bfl[16];
#pragma unroll
            for (int p = 0; p < 4; p++) {
                uint32_t bo = swz64((uint32_t)((b_r + p*16) * 64 + kk*32 + b_cb));
                ldsm_x4(&bfh[p*4], sb + stb +  4096 + bo);
                ldsm_x4(&bfl[p*4], sb + stb + 12288 + bo);
            }
#pragma unroll
            for (int mf = 0; mf < 2; mf++) {
                uint32_t ao = swz64((uint32_t)((a_r + mf*16) * 64 + kk*32 + a_cb));
                uint32_t ah[4];
                ldsm_x4(ah, sb + stb + ao);
#pragma unroll
                for (int p = 0; p < 4; p++) {
                    mma16816(acc[mf][2*p],   ah, &bfh[4*p]);
                    mma16816(acc[mf][2*p+1], ah, &bfh[4*p+2]);
                }
#pragma unroll
                for (int p = 0; p < 4; p++) {
                    mma16816(acc[mf][2*p],   ah, &bfl[4*p]);
                    mma16816(acc[mf][2*p+1], ah, &bfl[4*p+2]);
                }
            }
        }
    }
    __syncthreads();

    float* Osm = (float*)(sm + 1024);      // [64][132]
#pragma unroll
    for (int mf = 0; mf < 2; mf++) {
#pragma unroll
        for (int nf = 0; nf < 8; nf++) {
            int row = wm*32 + mf*16 + (lane >> 2);
            int col = wn*64 + nf*8 + (lane & 3)*2;
            Osm[row       * 132 + col    ] = acc[mf][nf][0];
            Osm[row       * 132 + col + 1] = acc[mf][nf][1];
            Osm[(row + 8) * 132 + col    ] = acc[mf][nf][2];
            Osm[(row + 8) * 132 + col + 1] = acc[mf][nf][3];
        }
    }
    __syncthreads();

    float* Y = outp + (size_t)stream * BN * C_;
#pragma unroll
    for (int it = 0; it < 16; it++) {
        int idx = tid + it * 128;
        int r = idx >> 5, j4 = idx & 31;
        float4 v = *(float4*)&Osm[r * 132 + j4 * 4];
        float4 bb = *(const float4*)&bias[c0 + j4 * 4];
        v.x += bb.x; v.y += bb.y; v.z += bb.z; v.w += bb.w;
        *(float4*)&Y[(size_t)(m0 + r) * C_ + c0 + j4 * 4] = v;
    }
}

// ---------------------------------------------------------------------------
// flash attention: HMMA fp16, 128 q-rows/CTA, 8 warps x 16 rows x 64 kv-cols.
// S = Qh*Kh + Ql*Kh (2-term; K single plane).  PV 1-term (V single plane).
// Warp-local softmax, register P, cp.async 2-stage K/V, 1 barrier/tile.
// smem: 2 stages x 32KB (Kh,Vh) + Q hi/lo 64KB = 131072 B
// ---------------------------------------------------------------------------
#define ASTG_ 32768u
#define AKH_ 0u
#define AVH_ 16384u
#define AQH_ 65536u
#define AQL_ 98304u

__device__ __forceinline__ void attn_issue_kv(
    uint32_t sb, uint32_t stb,
    const __half* kh_g, const __half* vh_g, int tid)
{
#pragma unroll
    for (int it = 0; it < 4; it++) {
        int idx = tid + it * 256;          // 0..1023: 64 rows x 16 16B-chunks
        int row = idx >> 4, ch = idx & 15;
        int src = row * 128 + ch * 8;
        uint32_t dst = stb + (uint32_t)(ch >> 3) * 8192 + swz((uint32_t)(row * 128 + (ch & 7) * 16));
        cpa16(sb + AKH_ + dst, kh_g + src);
        cpa16(sb + AVH_ + dst, vh_g + src);
    }
    cpa_commit();
}

__global__ __launch_bounds__(256, 1) void attn_mma()
{
    extern __shared__ char sm[];
    const uint32_t sb = smem_u32(sm);

    const int tid = threadIdx.x;
    const int lane = tid & 31, wr = tid >> 5;
    const int qt = blockIdx.x, bh = blockIdx.y;
    const int b = bh / H_, h = bh - b * H_;
    const size_t kvb = (size_t)bh * N_ * 128;

    const __half* kh_g = g_Kh + kvb;
    const __half* vh_g = g_Vh + kvb;

    attn_issue_kv(sb, 0, kh_g, vh_g, tid);

    {
        const __half* qh_g = g_Qh + kvb + (size_t)qt * 128 * 128;
        const __half* ql_g = g_Ql + kvb + (size_t)qt * 128 * 128;
#pragma unroll
        for (int it = 0; it < 8; it++) {
            int idx = tid + it * 256;
            int row = idx >> 4, ch = idx & 15;
            uint32_t dst = (uint32_t)(ch >> 3) * 16384 + swz((uint32_t)(row * 128 + (ch & 7) * 16));
            *(uint4*)(sm + AQH_ + dst) = *(const uint4*)(qh_g + row * 128 + ch * 8);
            *(uint4*)(sm + AQL_ + dst) = *(const uint4*)(ql_g + row * 128 + ch * 8);
        }
    }

    float m0r = -1e30f, m1r = -1e30f, l0r = 0.f, l1r = 0.f;
    float o[16][4];
#pragma unroll
    for (int i = 0; i < 16; i++)
#pragma unroll
        for (int j = 0; j < 4; j++) o[i][j] = 0.f;

    const int qrow = wr * 16 + (lane & 15);
    const int k_r  = (lane & 7) + ((lane >> 4) & 1) * 8;
    const int k_cb = ((lane >> 3) & 1) * 16;

    for (int kt = 0; kt < 16; kt++) {
        const uint32_t stb = (uint32_t)(kt & 1) * ASTG_;
        cpa_wait<0>();
        __syncthreads();
        if (kt < 15)
            attn_issue_kv(sb, (uint32_t)((kt + 1) & 1) * ASTG_,
                          kh_g + (size_t)(kt + 1) * 64 * 128,
                          vh_g + (size_t)(kt + 1) * 64 * 128, tid);

        // ---- S = Q K^T : 16 rows x 64 cols per warp, k=128, 2-term ----
        float sacc[8][4];
#pragma unroll
        for (int i = 0; i < 8; i++)
#pragma unroll
            for (int j = 0; j < 4; j++) sacc[i][j] = 0.f;

#pragma unroll
        for (int k16 = 0; k16 < 8; k16++) {
            uint32_t qo = (uint32_t)(k16 >> 2) * 16384 +
                          swz((uint32_t)(qrow * 128 + (k16 & 3) * 32 + (lane >> 4) * 16));
            uint32_t ah[4], al[4];
            ldsm_x4(ah, sb + AQH_ + qo);
            ldsm_x4(al, sb + AQL_ + qo);
            uint32_t kpl = stb + (uint32_t)(k16 >> 2) * 8192;
            uint32_t kcb = (uint32_t)((k16 & 3) * 32) + k_cb;
            uint32_t kfh[16];
#pragma unroll
            for (int p = 0; p < 4; p++) {
                uint32_t ko = kpl + swz((uint32_t)((k_r + p*16) * 128) + kcb);
                ldsm_x4(&kfh[4*p], sb + AKH_ + ko);
            }
#pragma unroll
            for (int p = 0; p < 4; p++) {
                mma16816(sacc[2*p],   ah, &kfh[4*p]);
                mma16816(sacc[2*p+1], ah, &kfh[4*p+2]);
            }
#pragma unroll
            for (int p = 0; p < 4; p++) {
                mma16816(sacc[2*p],   al, &kfh[4*p]);
                mma16816(sacc[2*p+1], al, &kfh[4*p+2]);
            }
        }

        // ---- warp-local online softmax ----
        float pm0 = -1e30f, pm1 = -1e30f;
#pragma unroll
        for (int nf = 0; nf < 8; nf++) {
            pm0 = fmaxf(pm0, fmaxf(sacc[nf][0], sacc[nf][1]));
            pm1 = fmaxf(pm1, fmaxf(sacc[nf][2], sacc[nf][3]));
        }
        pm0 = fmaxf(pm0, __shfl_xor_sync(0xffffffffu, pm0, 1));
        pm0 = fmaxf(pm0, __shfl_xor_sync(0xffffffffu, pm0, 2));
        pm1 = fmaxf(pm1, __shfl_xor_sync(0xffffffffu, pm1, 1));
        pm1 = fmaxf(pm1, __shfl_xor_sync(0xffffffffu, pm1, 2));
        float mn0 = fmaxf(m0r, pm0);
        float mn1 = fmaxf(m1r, pm1);
        float f0 = __expf(m0r - mn0);
        float f1 = __expf(m1r - mn1);
        m0r = mn0; m1r = mn1;

        uint32_t ph[4][4];
        float sum0 = 0.f, sum1 = 0.f;
#pragma unroll
        for (int g = 0; g < 4; g++) {
            float q0 = __expf(sacc[2*g][0]   - mn0);
            float q1 = __expf(sacc[2*g][1]   - mn0);
            float q2 = __expf(sacc[2*g][2]   - mn1);
            float q3 = __expf(sacc[2*g][3]   - mn1);
            float s0 = __expf(sacc[2*g+1][0] - mn0);
            float s1 = __expf(sacc[2*g+1][1] - mn0);
            float s2 = __expf(sacc[2*g+1][2] - mn1);
            float s3 = __expf(sacc[2*g+1][3] - mn1);
            sum0 += (q0 + q1) + (s0 + s1);
            sum1 += (q2 + q3) + (s2 + s3);
            ph[g][0] = pack_h2(q0, q1);
            ph[g][1] = pack_h2(q2, q3);
            ph[g][2] = pack_h2(s0, s1);
            ph[g][3] = pack_h2(s2, s3);
        }
        sum0 += __shfl_xor_sync(0xffffffffu, sum0, 1);
        sum0 += __shfl_xor_sync(0xffffffffu, sum0, 2);
        sum1 += __shfl_xor_sync(0xffffffffu, sum1, 1);
        sum1 += __shfl_xor_sync(0xffffffffu, sum1, 2);
        l0r = l0r * f0 + sum0;
        l1r = l1r * f1 + sum1;

        // ---- O = O*fac + P V : 16 rows x 128 d per warp, 1-term ----
#pragma unroll
        for (int nf = 0; nf < 16; nf++) {
            o[nf][0] *= f0; o[nf][1] *= f0;
            o[nf][2] *= f1; o[nf][3] *= f1;
        }
#pragma unroll
        for (int g = 0; g < 4; g++) {
            uint32_t vrow = (uint32_t)((g * 16 + (lane & 15)) * 128);
            uint32_t vcb  = (uint32_t)(lane >> 4) * 16;
#pragma unroll
            for (int p = 0; p < 8; p++) {
                uint32_t vo = stb + (uint32_t)(p >> 2) * 8192 +
                              swz(vrow + (uint32_t)((2*p) & 7) * 16 + vcb);
                uint32_t vh4[4];
                ldsm_x4_t(vh4, sb + AVH_ + vo);
                mma16816(o[2*p],   ph[g], &vh4[0]);
                mma16816(o[2*p+1], ph[g], &vh4[2]);
            }
        }
    }

    // ---- epilogue: normalize, write O as single fp16 (stream = nf>>3) ----
    float li0 = 1.f / l0r, li1 = 1.f / l1r;
    const int rr = wr * 16 + (lane >> 2);
#pragma unroll
    for (int nf = 0; nf < 16; nf++) {
        int strm = nf >> 3;
        int dcol = (nf & 7) * 8 + (lane & 3) * 2;
        size_t base = (size_t)strm * BN * C_
                    + ((size_t)(b * N_ + qt * 128 + rr)) * C_ + h * 64 + dcol;
        *(uint32_t*)&g_Oh[base] = pack_h2(o[nf][0] * li0, o[nf][1] * li0);
        *(uint32_t*)&g_Oh[base + 8 * C_] = pack_h2(o[nf][2] * li1, o[nf][3] * li1);
    }
}

// ---------------------------------------------------------------------------
extern "C" void kernel_launch(void* const* d_in, const int* in_sizes, int n_in,
                              void* d_out, int out_size)
{
    (void)in_sizes; (void)n_in; (void)out_size;
    const float* x1    = (const float*)d_in[0];
    const float* x2    = (const float*)d_in[1];
    const float* Wqkv  = (const float*)d_in[2];
    const float* bqkv  = (const float*)d_in[3];
    const float* Wproj = (const float*)d_in[4];
    const float* bproj = (const float*)d_in[5];
    float* out = (float*)d_out;

    split_all<<<8448, 256>>>(x1, x2, Wqkv, Wproj);

    const int qkv_smem = 68608;
    cudaFuncSetAttribute(qkv_gemm, cudaFuncAttributeMaxDynamicSharedMemorySize, qkv_smem);
    qkv_gemm<<<dim3(18, 32, 2), 128, qkv_smem>>>(bqkv);

    const int attn_smem = 131072;
    cudaFuncSetAttribute(attn_mma, cudaFuncAttributeMaxDynamicSharedMemorySize, attn_smem);
    attn_mma<<<dim3(8, 48), 256, attn_smem>>>();

    const int proj_smem = 41984;
    cudaFuncSetAttribute(proj_gemm, cudaFuncAttributeMaxDynamicSharedMemorySize, proj_smem);
    proj_gemm<<<dim3(6, 64, 2), 128, proj_smem>>>(bproj, out);
}

// round 13
// speedup vs baseline: 2.0508x; 1.2712x over previous
#include <cuda_runtime.h>
#include <cuda_fp16.h>
#include <cstdint>

#define B_ 4
#define N_ 1024
#define C_ 768
#define H_ 12
#define BN 4096
#define SCALE 0.125f

// ---------------- scratch (static device globals; no allocations) ----------
__device__ __align__(16) __half g_Qh[(size_t)B_*H_*N_*128];  // SCALE folded
__device__ __align__(16) __half g_Kh[(size_t)B_*H_*N_*128];
__device__ __align__(16) __half g_Vh[(size_t)B_*H_*N_*128];

__device__ __align__(16) __half g_Xh[(size_t)2*BN*C_];
__device__ __align__(16) __half g_Wqh[(size_t)3*C_*C_];
__device__ __align__(16) __half g_Wql[(size_t)3*C_*C_];
__device__ __align__(16) __half g_Wph[(size_t)C_*C_];
__device__ __align__(16) __half g_Wpl[(size_t)C_*C_];
__device__ __align__(16) __half g_Oh[(size_t)2*BN*C_];

// ---------------- helpers ---------------------------------------------------
__device__ __forceinline__ uint32_t smem_u32(const void* p) {
    uint32_t a;
    asm("{ .reg .u64 t; cvta.to.shared.u64 t, %1; cvt.u32.u64 %0, t; }"
        : "=r"(a) : "l"(p));
    return a;
}
__device__ __forceinline__ uint32_t swz(uint32_t o) {   // 128B-row swizzle
    return o ^ ((o >> 3) & 0x70);
}
__device__ __forceinline__ uint32_t swz64(uint32_t o) { // 64B-row swizzle
    return o ^ ((o >> 3) & 0x30);
}
__device__ __forceinline__ void cpa16(uint32_t dst, const void* src) {
    asm volatile("cp.async.cg.shared.global [%0], [%1], 16;" :: "r"(dst), "l"(src));
}
__device__ __forceinline__ void cpa_commit() {
    asm volatile("cp.async.commit_group;" ::: "memory");
}
template<int N>
__device__ __forceinline__ void cpa_wait() {
    asm volatile("cp.async.wait_group %0;" :: "n"(N) : "memory");
}
__device__ __forceinline__ void ldsm_x4(uint32_t* r, uint32_t addr) {
    asm volatile("ldmatrix.sync.aligned.m8n8.x4.shared.b16 {%0,%1,%2,%3}, [%4];"
                 : "=r"(r[0]), "=r"(r[1]), "=r"(r[2]), "=r"(r[3]) : "r"(addr));
}
__device__ __forceinline__ void ldsm_x4_t(uint32_t* r, uint32_t addr) {
    asm volatile("ldmatrix.sync.aligned.m8n8.x4.trans.shared.b16 {%0,%1,%2,%3}, [%4];"
                 : "=r"(r[0]), "=r"(r[1]), "=r"(r[2]), "=r"(r[3]) : "r"(addr));
}
__device__ __forceinline__ void mma16816(float* d, const uint32_t* a, const uint32_t* b) {
    asm volatile(
        "mma.sync.aligned.m16n8k16.row.col.f32.f16.f16.f32 "
        "{%0,%1,%2,%3}, {%4,%5,%6,%7}, {%8,%9}, {%0,%1,%2,%3};"
        : "+f"(d[0]), "+f"(d[1]), "+f"(d[2]), "+f"(d[3])
        : "r"(a[0]), "r"(a[1]), "r"(a[2]), "r"(a[3]), "r"(b[0]), "r"(b[1]));
}
__device__ __forceinline__ uint32_t pack_h2(float a, float b) {
    __half2 t = __floats2half2_rn(a, b);
    return *(uint32_t*)&t;
}

// ---------------------------------------------------------------------------
// fused split kernel: x1,x2 -> fp16 hi only; Wqkv,Wproj -> fp16 hi/lo
// ---------------------------------------------------------------------------
#define NX4  (BN * C_ / 4)          // 786432 -> 3072 blocks

__global__ __launch_bounds__(256) void split_all(
    const float* __restrict__ x1, const float* __restrict__ x2,
    const float* __restrict__ Wq, const float* __restrict__ Wp)
{
    int bid = blockIdx.x;
    const float* src;
    __half *hi, *lo;
    size_t off4;
    int i;
    bool wantLo = true;
    if (bid < 3072) {
        src = x1; hi = g_Xh; lo = nullptr; off4 = 0; wantLo = false;
        i = bid * 256 + threadIdx.x;
    } else if (bid < 6144) {
        src = x2; hi = g_Xh; lo = nullptr; off4 = NX4; wantLo = false;
        i = (bid - 3072) * 256 + threadIdx.x;
    } else if (bid < 7872) {
        src = Wq; hi = g_Wqh; lo = g_Wql; off4 = 0;
        i = (bid - 6144) * 256 + threadIdx.x;
    } else {
        src = Wp; hi = g_Wph; lo = g_Wpl; off4 = 0;
        i = (bid - 7872) * 256 + threadIdx.x;
    }
    float4 v = ((const float4*)src)[i];
    size_t o = off4 + (size_t)i;
    ((uint32_t*)hi)[o*2 + 0] = pack_h2(v.x, v.y);
    ((uint32_t*)hi)[o*2 + 1] = pack_h2(v.z, v.w);
    if (wantLo) {
        __half h0 = __float2half(v.x);
        __half h1 = __float2half(v.y);
        __half h2 = __float2half(v.z);
        __half h3 = __float2half(v.w);
        ((uint32_t*)lo)[o*2 + 0] = pack_h2(v.x - __half2float(h0), v.y - __half2float(h1));
        ((uint32_t*)lo)[o*2 + 1] = pack_h2(v.z - __half2float(h2), v.w - __half2float(h3));
    }
}

// ---------------------------------------------------------------------------
// qkv GEMM: 128x128 CTA tile, 128 threads (4 warps, 64x64), K-chunk 32,
// 2-stage cp.async, uniform 2-term (Xh*Wh + Xh*Wl) for Q, K and V.
// Epilogue: single fp16 plane for all of Q (SCALE folded), K, V.
// smem stage = A(8KB)+Bh(8KB)+Bl(8KB) = 24KB; alloc 68608 (Osm reuse).
// ---------------------------------------------------------------------------
__device__ __forceinline__ void gemm_issue_chunk(
    uint32_t sbase, const __half* Ah, const __half* Bh, const __half* Bl,
    int m0, int c0, int kc, int tid)
{
#pragma unroll
    for (int it = 0; it < 4; it++) {
        int u = tid + it * 128;
        int r = u >> 2, ch = u & 3;
        uint32_t so = swz64((uint32_t)(r * 64 + ch * 16));
        const size_t aoff = (size_t)(m0 + r) * C_ + kc + ch * 8;
        const size_t boff = (size_t)(c0 + r) * C_ + kc + ch * 8;
        cpa16(sbase +     0 + so, Ah + aoff);
        cpa16(sbase +  8192 + so, Bh + boff);
        cpa16(sbase + 16384 + so, Bl + boff);
    }
    cpa_commit();
}

__global__ __launch_bounds__(128, 2) void qkv_gemm(const float* __restrict__ bias)
{
    extern __shared__ char sm[];
    const uint32_t sb = smem_u32(sm) + 1024;
    const int tid = threadIdx.x;
    const int lane = tid & 31, wid = tid >> 5;
    const int wm = wid & 1, wn = wid >> 1;
    const int stream = blockIdx.z;
    const int m0 = blockIdx.y * 128;
    const int c0 = blockIdx.x * 128;
    const int s_tile = c0 / C_;                 // uniform per CTA

    const __half* __restrict__ Ah = g_Xh + (size_t)stream * BN * C_;
    const __half* __restrict__ Bh = g_Wqh;
    const __half* __restrict__ Bl = g_Wql;

    float acc[4][8][4];
#pragma unroll
    for (int i = 0; i < 4; i++)
#pragma unroll
        for (int j = 0; j < 8; j++)
#pragma unroll
            for (int k = 0; k < 4; k++) acc[i][j][k] = 0.f;

    const int a_r  = wm*64 + (lane & 15);
    const int a_cb = (lane >> 4) * 16;
    const int b_r  = wn*64 + (lane & 7) + ((lane >> 4) & 1)*8;
    const int b_cb = ((lane >> 3) & 1) * 16;

    const int NCH = C_ / 32;   // 24
    gemm_issue_chunk(sb, Ah, Bh, Bl, m0, c0, 0, tid);

    for (int ch = 0; ch < NCH; ch++) {
        const uint32_t stb = (uint32_t)(ch & 1) * 24576u;
        cpa_wait<0>();
        __syncthreads();
        if (ch + 1 < NCH)
            gemm_issue_chunk(sb + ((ch + 1) & 1) * 24576u,
                             Ah, Bh, Bl, m0, c0, (ch + 1) * 32, tid);

#pragma unroll
        for (int kk = 0; kk < 2; kk++) {
            uint32_t bfh[16], bfl[16];
#pragma unroll
            for (int p = 0; p < 4; p++) {
                uint32_t bo = swz64((uint32_t)((b_r + p*16) * 64 + kk*32 + b_cb));
                ldsm_x4(&bfh[p*4], sb + stb +  8192 + bo);
                ldsm_x4(&bfl[p*4], sb + stb + 16384 + bo);
            }
#pragma unroll
            for (int mf = 0; mf < 4; mf++) {
                uint32_t ao = swz64((uint32_t)((a_r + mf*16) * 64 + kk*32 + a_cb));
                uint32_t ah[4];
                ldsm_x4(ah, sb + stb + ao);
#pragma unroll
                for (int p = 0; p < 4; p++) {
                    mma16816(acc[mf][2*p],   ah, &bfh[4*p]);
                    mma16816(acc[mf][2*p+1], ah, &bfh[4*p+2]);
                }
#pragma unroll
                for (int p = 0; p < 4; p++) {
                    mma16816(acc[mf][2*p],   ah, &bfl[4*p]);
                    mma16816(acc[mf][2*p+1], ah, &bfl[4*p+2]);
                }
            }
        }
    }
    __syncthreads();

    float* Osm = (float*)(sm + 1024);      // [128][132]
#pragma unroll
    for (int mf = 0; mf < 4; mf++) {
#pragma unroll
        for (int nf = 0; nf < 8; nf++) {
            int row = wm*64 + mf*16 + (lane >> 2);
            int col = wn*64 + nf*8 + (lane & 3)*2;
            Osm[row       * 132 + col    ] = acc[mf][nf][0];
            Osm[row       * 132 + col + 1] = acc[mf][nf][1];
            Osm[(row + 8) * 132 + col    ] = acc[mf][nf][2];
            Osm[(row + 8) * 132 + col + 1] = acc[mf][nf][3];
        }
    }
    __syncthreads();

#pragma unroll
    for (int it = 0; it < 32; it++) {
        int idx = tid + it * 128;
        int r = idx >> 5, j4 = idx & 31;
        float4 v = *(float4*)&Osm[r * 132 + j4 * 4];
        float4 bb = *(const float4*)&bias[c0 + j4 * 4];
        v.x += bb.x; v.y += bb.y; v.z += bb.z; v.w += bb.w;
        int m = m0 + r;
        int cg = c0 + j4 * 4;
        int rem = cg - s_tile * C_;
        int h = rem >> 6, d = rem & 63;
        if (s_tile == 0) { v.x *= SCALE; v.y *= SCALE; v.z *= SCALE; v.w *= SCALE; }
        uint2 hv;
        hv.x = pack_h2(v.x, v.y); hv.y = pack_h2(v.z, v.w);
        int b = m >> 10, n = m & 1023;
        size_t base = ((size_t)(b * H_ + h) * N_ + n) * 128 + stream * 64 + d;
        __half* buf = (s_tile == 0) ? g_Qh : (s_tile == 1) ? g_Kh : g_Vh;
        *(uint2*)&buf[base] = hv;
    }
}

// ---------------------------------------------------------------------------
// proj GEMM: 64x128 CTA tile, 128 threads (4 warps, 32x64 each), K-chunk 32,
// 2-stage cp.async, 2-term (Oh*Wh + Oh*Wl).
// ---------------------------------------------------------------------------
__device__ __forceinline__ void proj_issue_chunk(
    uint32_t sbase, const __half* Ah, const __half* Bh, const __half* Bl,
    int m0, int c0, int kc, int tid)
{
#pragma unroll
    for (int it = 0; it < 2; it++) {
        int u = tid + it * 128;
        int r = u >> 2, ch = u & 3;
        uint32_t so = swz64((uint32_t)(r * 64 + ch * 16));
        cpa16(sbase + so, Ah + (size_t)(m0 + r) * C_ + kc + ch * 8);
    }
#pragma unroll
    for (int it = 0; it < 4; it++) {
        int u = tid + it * 128;
        int r = u >> 2, ch = u & 3;
        uint32_t so = swz64((uint32_t)(r * 64 + ch * 16));
        const size_t boff = (size_t)(c0 + r) * C_ + kc + ch * 8;
        cpa16(sbase +  4096 + so, Bh + boff);
        cpa16(sbase + 12288 + so, Bl + boff);
    }
    cpa_commit();
}

__global__ __launch_bounds__(128, 3) void proj_gemm(const float* __restrict__ bias,
                                                    float* __restrict__ outp)
{
    extern __shared__ char sm[];
    const uint32_t sb = smem_u32(sm) + 1024;
    const int tid = threadIdx.x;
    const int lane = tid & 31, wid = tid >> 5;
    const int wm = wid & 1, wn = wid >> 1;
    const int stream = blockIdx.z;
    const int m0 = blockIdx.y * 64;
    const int c0 = blockIdx.x * 128;

    const __half* __restrict__ Ah = g_Oh + (size_t)stream * BN * C_;
    const __half* __restrict__ Bh = g_Wph;
    const __half* __restrict__ Bl = g_Wpl;

    float acc[2][8][4];
#pragma unroll
    for (int i = 0; i < 2; i++)
#pragma unroll
        for (int j = 0; j < 8; j++)
#pragma unroll
            for (int k = 0; k < 4; k++) acc[i][j][k] = 0.f;

    const int a_r  = wm*32 + (lane & 15);
    const int a_cb = (lane >> 4) * 16;
    const int b_r  = wn*64 + (lane & 7) + ((lane >> 4) & 1)*8;
    const int b_cb = ((lane >> 3) & 1) * 16;

    const int NCH = C_ / 32;   // 24
    proj_issue_chunk(sb, Ah, Bh, Bl, m0, c0, 0, tid);

    for (int ch = 0; ch < NCH; ch++) {
        const uint32_t stb = (uint32_t)(ch & 1) * 20480u;
        cpa_wait<0>();
        __syncthreads();
        if (ch + 1 < NCH)
            proj_issue_chunk(sb + ((ch + 1) & 1) * 20480u,
                             Ah, Bh, Bl, m0, c0, (ch + 1) * 32, tid);

#pragma unroll
        for (int kk = 0; kk < 2; kk++) {
            uint32_t bfh[16], bfl[16];
#pragma unroll
            for (int p = 0; p < 4; p++) {
                uint32_t bo = swz64((uint32_t)((b_r + p*16) * 64 + kk*32 + b_cb));
                ldsm_x4(&bfh[p*4], sb + stb +  4096 + bo);
                ldsm_x4(&bfl[p*4], sb + stb + 12288 + bo);
            }
#pragma unroll
            for (int mf = 0; mf < 2; mf++) {
                uint32_t ao = swz64((uint32_t)((a_r + mf*16) * 64 + kk*32 + a_cb));
                uint32_t ah[4];
                ldsm_x4(ah, sb + stb + ao);
#pragma unroll
                for (int p = 0; p < 4; p++) {
                    mma16816(acc[mf][2*p],   ah, &bfh[4*p]);
                    mma16816(acc[mf][2*p+1], ah, &bfh[4*p+2]);
                }
#pragma unroll
                for (int p = 0; p < 4; p++) {
                    mma16816(acc[mf][2*p],   ah, &bfl[4*p]);
                    mma16816(acc[mf][2*p+1], ah, &bfl[4*p+2]);
                }
            }
        }
    }
    __syncthreads();

    float* Osm = (float*)(sm + 1024);      // [64][132]
#pragma unroll
    for (int mf = 0; mf < 2; mf++) {
#pragma unroll
        for (int nf = 0; nf < 8; nf++) {
            int row = wm*32 + mf*16 + (lane >> 2);
            int col = wn*64 + nf*8 + (lane & 3)*2;
            Osm[row       * 132 + col    ] = acc[mf][nf][0];
            Osm[row       * 132 + col + 1] = acc[mf][nf][1];
            Osm[(row + 8) * 132 + col    ] = acc[mf][nf][2];
            Osm[(row + 8) * 132 + col + 1] = acc[mf][nf][3];
        }
    }
    __syncthreads();

    float* Y = outp + (size_t)stream * BN * C_;
#pragma unroll
    for (int it = 0; it < 16; it++) {
        int idx = tid + it * 128;
        int r = idx >> 5, j4 = idx & 31;
        float4 v = *(float4*)&Osm[r * 132 + j4 * 4];
        float4 bb = *(const float4*)&bias[c0 + j4 * 4];
        v.x += bb.x; v.y += bb.y; v.z += bb.z; v.w += bb.w;
        *(float4*)&Y[(size_t)(m0 + r) * C_ + c0 + j4 * 4] = v;
    }
}

// ---------------------------------------------------------------------------
// flash attention: HMMA fp16, 128 q-rows/CTA, 8 warps x 16 rows x 64 kv-cols.
// S = Qh*Kh (1-term).  PV 1-term.  Warp-local softmax, register P,
// cp.async 2-stage K/V, 1 barrier/tile.
// smem: 2 stages x 32KB (Kh,Vh) + Q 32KB = 98304 B
// ---------------------------------------------------------------------------
#define ASTG_ 32768u
#define AKH_ 0u
#define AVH_ 16384u
#define AQH_ 65536u

__device__ __forceinline__ void attn_issue_kv(
    uint32_t sb, uint32_t stb,
    const __half* kh_g, const __half* vh_g, int tid)
{
#pragma unroll
    for (int it = 0; it < 4; it++) {
        int idx = tid + it * 256;          // 0..1023: 64 rows x 16 16B-chunks
        int row = idx >> 4, ch = idx & 15;
        int src = row * 128 + ch * 8;
        uint32_t dst = stb + (uint32_t)(ch >> 3) * 8192 + swz((uint32_t)(row * 128 + (ch & 7) * 16));
        cpa16(sb + AKH_ + dst, kh_g + src);
        cpa16(sb + AVH_ + dst, vh_g + src);
    }
    cpa_commit();
}

__global__ __launch_bounds__(256, 1) void attn_mma()
{
    extern __shared__ char sm[];
    const uint32_t sb = smem_u32(sm);

    const int tid = threadIdx.x;
    const int lane = tid & 31, wr = tid >> 5;
    const int qt = blockIdx.x, bh = blockIdx.y;
    const int b = bh / H_, h = bh - b * H_;
    const size_t kvb = (size_t)bh * N_ * 128;

    const __half* kh_g = g_Kh + kvb;
    const __half* vh_g = g_Vh + kvb;

    attn_issue_kv(sb, 0, kh_g, vh_g, tid);

    {
        const __half* qh_g = g_Qh + kvb + (size_t)qt * 128 * 128;
#pragma unroll
        for (int it = 0; it < 8; it++) {
            int idx = tid + it * 256;              // 0..2047 16B chunks
            int row = idx >> 4, ch = idx & 15;
            uint32_t dst = (uint32_t)(ch >> 3) * 16384 + swz((uint32_t)(row * 128 + (ch & 7) * 16));
            *(uint4*)(sm + AQH_ + dst) = *(const uint4*)(qh_g + row * 128 + ch * 8);
        }
    }

    float m0r = -1e30f, m1r = -1e30f, l0r = 0.f, l1r = 0.f;
    float o[16][4];
#pragma unroll
    for (int i = 0; i < 16; i++)
#pragma unroll
        for (int j = 0; j < 4; j++) o[i][j] = 0.f;

    const int qrow = wr * 16 + (lane & 15);
    const int k_r  = (lane & 7) + ((lane >> 4) & 1) * 8;
    const int k_cb = ((lane >> 3) & 1) * 16;

    for (int kt = 0; kt < 16; kt++) {
        const uint32_t stb = (uint32_t)(kt & 1) * ASTG_;
        cpa_wait<0>();
        __syncthreads();
        if (kt < 15)
            attn_issue_kv(sb, (uint32_t)((kt + 1) & 1) * ASTG_,
                          kh_g + (size_t)(kt + 1) * 64 * 128,
                          vh_g + (size_t)(kt + 1) * 64 * 128, tid);

        // ---- S = Q K^T : 16 rows x 64 cols per warp, k=128, 1-term ----
        float sacc[8][4];
#pragma unroll
        for (int i = 0; i < 8; i++)
#pragma unroll
            for (int j = 0; j < 4; j++) sacc[i][j] = 0.f;

#pragma unroll
        for (int k16 = 0; k16 < 8; k16++) {
            uint32_t qo = (uint32_t)(k16 >> 2) * 16384 +
                          swz((uint32_t)(qrow * 128 + (k16 & 3) * 32 + (lane >> 4) * 16));
            uint32_t ah[4];
            ldsm_x4(ah, sb + AQH_ + qo);
            uint32_t kpl = stb + (uint32_t)(k16 >> 2) * 8192;
            uint32_t kcb = (uint32_t)((k16 & 3) * 32) + k_cb;
            uint32_t kfh[16];
#pragma unroll
            for (int p = 0; p < 4; p++) {
                uint32_t ko = kpl + swz((uint32_t)((k_r + p*16) * 128) + kcb);
                ldsm_x4(&kfh[4*p], sb + AKH_ + ko);
            }
#pragma unroll
            for (int p = 0; p < 4; p++) {
                mma16816(sacc[2*p],   ah, &kfh[4*p]);
                mma16816(sacc[2*p+1], ah, &kfh[4*p+2]);
            }
        }

        // ---- warp-local online softmax ----
        float pm0 = -1e30f, pm1 = -1e30f;
#pragma unroll
        for (int nf = 0; nf < 8; nf++) {
            pm0 = fmaxf(pm0, fmaxf(sacc[nf][0], sacc[nf][1]));
            pm1 = fmaxf(pm1, fmaxf(sacc[nf][2], sacc[nf][3]));
        }
        pm0 = fmaxf(pm0, __shfl_xor_sync(0xffffffffu, pm0, 1));
        pm0 = fmaxf(pm0, __shfl_xor_sync(0xffffffffu, pm0, 2));
        pm1 = fmaxf(pm1, __shfl_xor_sync(0xffffffffu, pm1, 1));
        pm1 = fmaxf(pm1, __shfl_xor_sync(0xffffffffu, pm1, 2));
        float mn0 = fmaxf(m0r, pm0);
        float mn1 = fmaxf(m1r, pm1);
        float f0 = __expf(m0r - mn0);
        float f1 = __expf(m1r - mn1);
        m0r = mn0; m1r = mn1;

        uint32_t ph[4][4];
        float sum0 = 0.f, sum1 = 0.f;
#pragma unroll
        for (int g = 0; g < 4; g++) {
            float q0 = __expf(sacc[2*g][0]   - mn0);
            float q1 = __expf(sacc[2*g][1]   - mn0);
            float q2 = __expf(sacc[2*g][2]   - mn1);
            float q3 = __expf(sacc[2*g][3]   - mn1);
            float s0 = __expf(sacc[2*g+1][0] - mn0);
            float s1 = __expf(sacc[2*g+1][1] - mn0);
            float s2 = __expf(sacc[2*g+1][2] - mn1);
            float s3 = __expf(sacc[2*g+1][3] - mn1);
            sum0 += (q0 + q1) + (s0 + s1);
            sum1 += (q2 + q3) + (s2 + s3);
            ph[g][0] = pack_h2(q0, q1);
            ph[g][1] = pack_h2(q2, q3);
            ph[g][2] = pack_h2(s0, s1);
            ph[g][3] = pack_h2(s2, s3);
        }
        sum0 += __shfl_xor_sync(0xffffffffu, sum0, 1);
        sum0 += __shfl_xor_sync(0xffffffffu, sum0, 2);
        sum1 += __shfl_xor_sync(0xffffffffu, sum1, 1);
        sum1 += __shfl_xor_sync(0xffffffffu, sum1, 2);
        l0r = l0r * f0 + sum0;
        l1r = l1r * f1 + sum1;

        // ---- O = O*fac + P V : 16 rows x 128 d per warp, 1-term ----
#pragma unroll
        for (int nf = 0; nf < 16; nf++) {
            o[nf][0] *= f0; o[nf][1] *= f0;
            o[nf][2] *= f1; o[nf][3] *= f1;
        }
#pragma unroll
        for (int g = 0; g < 4; g++) {
            uint32_t vrow = (uint32_t)((g * 16 + (lane & 15)) * 128);
            uint32_t vcb  = (uint32_t)(lane >> 4) * 16;
#pragma unroll
            for (int p = 0; p < 8; p++) {
                uint32_t vo = stb + (uint32_t)(p >> 2) * 8192 +
                              swz(vrow + (uint32_t)((2*p) & 7) * 16 + vcb);
                uint32_t vh4[4];
                ldsm_x4_t(vh4, sb + AVH_ + vo);
                mma16816(o[2*p],   ph[g], &vh4[0]);
                mma16816(o[2*p+1], ph[g], &vh4[2]);
            }
        }
    }

    // ---- epilogue: normalize, write O as single fp16 (stream = nf>>3) ----
    float li0 = 1.f / l0r, li1 = 1.f / l1r;
    const int rr = wr * 16 + (lane >> 2);
#pragma unroll
    for (int nf = 0; nf < 16; nf++) {
        int strm = nf >> 3;
        int dcol = (nf & 7) * 8 + (lane & 3) * 2;
        size_t base = (size_t)strm * BN * C_
                    + ((size_t)(b * N_ + qt * 128 + rr)) * C_ + h * 64 + dcol;
        *(uint32_t*)&g_Oh[base] = pack_h2(o[nf][0] * li0, o[nf][1] * li0);
        *(uint32_t*)&g_Oh[base + 8 * C_] = pack_h2(o[nf][2] * li1, o[nf][3] * li1);
    }
}

// ---------------------------------------------------------------------------
extern "C" void kernel_launch(void* const* d_in, const int* in_sizes, int n_in,
                              void* d_out, int out_size)
{
    (void)in_sizes; (void)n_in; (void)out_size;
    const float* x1    = (const float*)d_in[0];
    const float* x2    = (const float*)d_in[1];
    const float* Wqkv  = (const float*)d_in[2];
    const float* bqkv  = (const float*)d_in[3];
    const float* Wproj = (const float*)d_in[4];
    const float* bproj = (const float*)d_in[5];
    float* out = (float*)d_out;

    split_all<<<8448, 256>>>(x1, x2, Wqkv, Wproj);

    const int qkv_smem = 68608;   // 1024 + max(2x24576 stages, 128x132x4 Osm)
    cudaFuncSetAttribute(qkv_gemm, cudaFuncAttributeMaxDynamicSharedMemorySize, qkv_smem);
    qkv_gemm<<<dim3(18, 32, 2), 128, qkv_smem>>>(bqkv);

    const int attn_smem = 98304;
    cudaFuncSetAttribute(attn_mma, cudaFuncAttributeMaxDynamicSharedMemorySize, attn_smem);
    attn_mma<<<dim3(8, 48), 256, attn_smem>>>();

    const int proj_smem = 41984;
    cudaFuncSetAttribute(proj_gemm, cudaFuncAttributeMaxDynamicSharedMemorySize, proj_smem);
    proj_gemm<<<dim3(6, 64, 2), 128, proj_smem>>>(bproj, out);
}

// round 14
// speedup vs baseline: 2.1972x; 1.0714x over previous
#include <cuda_runtime.h>
#include <cuda_fp16.h>
#include <cstdint>

#define B_ 4
#define N_ 1024
#define C_ 768
#define H_ 12
#define BN 4096
#define SCALE 0.125f

// ---------------- scratch (static device globals; no allocations) ----------
__device__ __align__(16) __half g_Qh[(size_t)B_*H_*N_*128];  // SCALE folded
__device__ __align__(16) __half g_Kh[(size_t)B_*H_*N_*128];
__device__ __align__(16) __half g_Vh[(size_t)B_*H_*N_*128];

__device__ __align__(16) __half g_Xh[(size_t)2*BN*C_];
__device__ __align__(16) __half g_Wqh[(size_t)3*C_*C_];
__device__ __align__(16) __half g_Wql[(size_t)3*C_*C_];
__device__ __align__(16) __half g_Wph[(size_t)C_*C_];
__device__ __align__(16) __half g_Oh[(size_t)2*BN*C_];

// ---------------- helpers ---------------------------------------------------
__device__ __forceinline__ uint32_t smem_u32(const void* p) {
    uint32_t a;
    asm("{ .reg .u64 t; cvta.to.shared.u64 t, %1; cvt.u32.u64 %0, t; }"
        : "=r"(a) : "l"(p));
    return a;
}
__device__ __forceinline__ uint32_t swz(uint32_t o) {   // 128B-row swizzle
    return o ^ ((o >> 3) & 0x70);
}
__device__ __forceinline__ uint32_t swz64(uint32_t o) { // 64B-row swizzle
    return o ^ ((o >> 3) & 0x30);
}
__device__ __forceinline__ void cpa16(uint32_t dst, const void* src) {
    asm volatile("cp.async.cg.shared.global [%0], [%1], 16;" :: "r"(dst), "l"(src));
}
__device__ __forceinline__ void cpa_commit() {
    asm volatile("cp.async.commit_group;" ::: "memory");
}
template<int N>
__device__ __forceinline__ void cpa_wait() {
    asm volatile("cp.async.wait_group %0;" :: "n"(N) : "memory");
}
__device__ __forceinline__ void ldsm_x4(uint32_t* r, uint32_t addr) {
    asm volatile("ldmatrix.sync.aligned.m8n8.x4.shared.b16 {%0,%1,%2,%3}, [%4];"
                 : "=r"(r[0]), "=r"(r[1]), "=r"(r[2]), "=r"(r[3]) : "r"(addr));
}
__device__ __forceinline__ void ldsm_x4_t(uint32_t* r, uint32_t addr) {
    asm volatile("ldmatrix.sync.aligned.m8n8.x4.trans.shared.b16 {%0,%1,%2,%3}, [%4];"
                 : "=r"(r[0]), "=r"(r[1]), "=r"(r[2]), "=r"(r[3]) : "r"(addr));
}
__device__ __forceinline__ void mma16816(float* d, const uint32_t* a, const uint32_t* b) {
    asm volatile(
        "mma.sync.aligned.m16n8k16.row.col.f32.f16.f16.f32 "
        "{%0,%1,%2,%3}, {%4,%5,%6,%7}, {%8,%9}, {%0,%1,%2,%3};"
        : "+f"(d[0]), "+f"(d[1]), "+f"(d[2]), "+f"(d[3])
        : "r"(a[0]), "r"(a[1]), "r"(a[2]), "r"(a[3]), "r"(b[0]), "r"(b[1]));
}
__device__ __forceinline__ uint32_t pack_h2(float a, float b) {
    __half2 t = __floats2half2_rn(a, b);
    return *(uint32_t*)&t;
}

// ---------------------------------------------------------------------------
// fused split kernel: x1,x2,Wproj -> fp16 hi only; Wqkv -> fp16 hi/lo
// ---------------------------------------------------------------------------
#define NX4  (BN * C_ / 4)          // 786432 -> 3072 blocks

__global__ __launch_bounds__(256) void split_all(
    const float* __restrict__ x1, const float* __restrict__ x2,
    const float* __restrict__ Wq, const float* __restrict__ Wp)
{
    int bid = blockIdx.x;
    const float* src;
    __half *hi, *lo;
    size_t off4;
    int i;
    bool wantLo = false;
    if (bid < 3072) {
        src = x1; hi = g_Xh; lo = nullptr; off4 = 0;
        i = bid * 256 + threadIdx.x;
    } else if (bid < 6144) {
        src = x2; hi = g_Xh; lo = nullptr; off4 = NX4;
        i = (bid - 3072) * 256 + threadIdx.x;
    } else if (bid < 7872) {
        src = Wq; hi = g_Wqh; lo = g_Wql; off4 = 0; wantLo = true;
        i = (bid - 6144) * 256 + threadIdx.x;
    } else {
        src = Wp; hi = g_Wph; lo = nullptr; off4 = 0;
        i = (bid - 7872) * 256 + threadIdx.x;
    }
    float4 v = ((const float4*)src)[i];
    size_t o = off4 + (size_t)i;
    ((uint32_t*)hi)[o*2 + 0] = pack_h2(v.x, v.y);
    ((uint32_t*)hi)[o*2 + 1] = pack_h2(v.z, v.w);
    if (wantLo) {
        __half h0 = __float2half(v.x);
        __half h1 = __float2half(v.y);
        __half h2 = __float2half(v.z);
        __half h3 = __float2half(v.w);
        ((uint32_t*)lo)[o*2 + 0] = pack_h2(v.x - __half2float(h0), v.y - __half2float(h1));
        ((uint32_t*)lo)[o*2 + 1] = pack_h2(v.z - __half2float(h2), v.w - __half2float(h3));
    }
}

// ---------------------------------------------------------------------------
// qkv GEMM: 128x128 CTA tile, 128 threads (4 warps, 64x64), K-chunk 32,
// 2-stage cp.async.  Q,K tiles: 2-term (Xh*Wh + Xh*Wl).  V tiles: 1-term.
// Epilogue: single fp16 plane for Q (SCALE folded), K, V.
// ---------------------------------------------------------------------------
__device__ __forceinline__ void gemm_issue_chunk(
    uint32_t sbase, const __half* Ah, const __half* Bh, const __half* Bl,
    int m0, int c0, int kc, int tid, bool loadBl)
{
#pragma unroll
    for (int it = 0; it < 4; it++) {
        int u = tid + it * 128;
        int r = u >> 2, ch = u & 3;
        uint32_t so = swz64((uint32_t)(r * 64 + ch * 16));
        const size_t aoff = (size_t)(m0 + r) * C_ + kc + ch * 8;
        const size_t boff = (size_t)(c0 + r) * C_ + kc + ch * 8;
        cpa16(sbase +     0 + so, Ah + aoff);
        cpa16(sbase +  8192 + so, Bh + boff);
        if (loadBl) cpa16(sbase + 16384 + so, Bl + boff);
    }
    cpa_commit();
}

__global__ __launch_bounds__(128, 2) void qkv_gemm(const float* __restrict__ bias)
{
    extern __shared__ char sm[];
    const uint32_t sb = smem_u32(sm) + 1024;
    const int tid = threadIdx.x;
    const int lane = tid & 31, wid = tid >> 5;
    const int wm = wid & 1, wn = wid >> 1;
    const int stream = blockIdx.z;
    const int m0 = blockIdx.y * 128;
    const int c0 = blockIdx.x * 128;
    const int s_tile = c0 / C_;                 // uniform per CTA
    const bool useBl = (s_tile < 2);            // Q,K 2-term; V 1-term

    const __half* __restrict__ Ah = g_Xh + (size_t)stream * BN * C_;
    const __half* __restrict__ Bh = g_Wqh;
    const __half* __restrict__ Bl = g_Wql;

    float acc[4][8][4];
#pragma unroll
    for (int i = 0; i < 4; i++)
#pragma unroll
        for (int j = 0; j < 8; j++)
#pragma unroll
            for (int k = 0; k < 4; k++) acc[i][j][k] = 0.f;

    const int a_r  = wm*64 + (lane & 15);
    const int a_cb = (lane >> 4) * 16;
    const int b_r  = wn*64 + (lane & 7) + ((lane >> 4) & 1)*8;
    const int b_cb = ((lane >> 3) & 1) * 16;

    const int NCH = C_ / 32;   // 24
    gemm_issue_chunk(sb, Ah, Bh, Bl, m0, c0, 0, tid, useBl);

    for (int ch = 0; ch < NCH; ch++) {
        const uint32_t stb = (uint32_t)(ch & 1) * 24576u;
        cpa_wait<0>();
        __syncthreads();
        if (ch + 1 < NCH)
            gemm_issue_chunk(sb + ((ch + 1) & 1) * 24576u,
                             Ah, Bh, Bl, m0, c0, (ch + 1) * 32, tid, useBl);

#pragma unroll
        for (int kk = 0; kk < 2; kk++) {
            uint32_t bfh[16], bfl[16];
#pragma unroll
            for (int p = 0; p < 4; p++) {
                uint32_t bo = swz64((uint32_t)((b_r + p*16) * 64 + kk*32 + b_cb));
                ldsm_x4(&bfh[p*4], sb + stb +  8192 + bo);
                if (useBl) ldsm_x4(&bfl[p*4], sb + stb + 16384 + bo);
            }
#pragma unroll
            for (int mf = 0; mf < 4; mf++) {
                uint32_t ao = swz64((uint32_t)((a_r + mf*16) * 64 + kk*32 + a_cb));
                uint32_t ah[4];
                ldsm_x4(ah, sb + stb + ao);
#pragma unroll
                for (int p = 0; p < 4; p++) {
                    mma16816(acc[mf][2*p],   ah, &bfh[4*p]);
                    mma16816(acc[mf][2*p+1], ah, &bfh[4*p+2]);
                }
                if (useBl) {
#pragma unroll
                    for (int p = 0; p < 4; p++) {
                        mma16816(acc[mf][2*p],   ah, &bfl[4*p]);
                        mma16816(acc[mf][2*p+1], ah, &bfl[4*p+2]);
                    }
                }
            }
        }
    }
    __syncthreads();

    float* Osm = (float*)(sm + 1024);      // [128][132]
#pragma unroll
    for (int mf = 0; mf < 4; mf++) {
#pragma unroll
        for (int nf = 0; nf < 8; nf++) {
            int row = wm*64 + mf*16 + (lane >> 2);
            int col = wn*64 + nf*8 + (lane & 3)*2;
            Osm[row       * 132 + col    ] = acc[mf][nf][0];
            Osm[row       * 132 + col + 1] = acc[mf][nf][1];
            Osm[(row + 8) * 132 + col    ] = acc[mf][nf][2];
            Osm[(row + 8) * 132 + col + 1] = acc[mf][nf][3];
        }
    }
    __syncthreads();

#pragma unroll
    for (int it = 0; it < 32; it++) {
        int idx = tid + it * 128;
        int r = idx >> 5, j4 = idx & 31;
        float4 v = *(float4*)&Osm[r * 132 + j4 * 4];
        float4 bb = *(const float4*)&bias[c0 + j4 * 4];
        v.x += bb.x; v.y += bb.y; v.z += bb.z; v.w += bb.w;
        int m = m0 + r;
        int cg = c0 + j4 * 4;
        int rem = cg - s_tile * C_;
        int h = rem >> 6, d = rem & 63;
        if (s_tile == 0) { v.x *= SCALE; v.y *= SCALE; v.z *= SCALE; v.w *= SCALE; }
        uint2 hv;
        hv.x = pack_h2(v.x, v.y); hv.y = pack_h2(v.z, v.w);
        int b = m >> 10, n = m & 1023;
        size_t base = ((size_t)(b * H_ + h) * N_ + n) * 128 + stream * 64 + d;
        __half* buf = (s_tile == 0) ? g_Qh : (s_tile == 1) ? g_Kh : g_Vh;
        *(uint2*)&buf[base] = hv;
    }
}

// ---------------------------------------------------------------------------
// proj GEMM: 64x128 CTA tile, 128 threads (4 warps, 32x64 each), K-chunk 32,
// 2-stage cp.async, 1-term (Oh*Wh).  stage = A 4KB + Bh 8KB = 12KB.
// smem alloc = 1024 + max(2x12288, 64x132x4) = 34816 B -> 4+ CTAs/SM.
// ---------------------------------------------------------------------------
__device__ __forceinline__ void proj_issue_chunk(
    uint32_t sbase, const __half* Ah, const __half* Bh,
    int m0, int c0, int kc, int tid)
{
#pragma unroll
    for (int it = 0; it < 2; it++) {       // A: 64 rows x 4 chunks = 256
        int u = tid + it * 128;
        int r = u >> 2, ch = u & 3;
        uint32_t so = swz64((uint32_t)(r * 64 + ch * 16));
        cpa16(sbase + so, Ah + (size_t)(m0 + r) * C_ + kc + ch * 8);
    }
#pragma unroll
    for (int it = 0; it < 4; it++) {       // Bh: 128 rows x 4 chunks = 512
        int u = tid + it * 128;
        int r = u >> 2, ch = u & 3;
        uint32_t so = swz64((uint32_t)(r * 64 + ch * 16));
        cpa16(sbase + 4096 + so, Bh + (size_t)(c0 + r) * C_ + kc + ch * 8);
    }
    cpa_commit();
}

__global__ __launch_bounds__(128, 3) void proj_gemm(const float* __restrict__ bias,
                                                    float* __restrict__ outp)
{
    extern __shared__ char sm[];
    const uint32_t sb = smem_u32(sm) + 1024;
    const int tid = threadIdx.x;
    const int lane = tid & 31, wid = tid >> 5;
    const int wm = wid & 1, wn = wid >> 1;
    const int stream = blockIdx.z;
    const int m0 = blockIdx.y * 64;
    const int c0 = blockIdx.x * 128;

    const __half* __restrict__ Ah = g_Oh + (size_t)stream * BN * C_;
    const __half* __restrict__ Bh = g_Wph;

    float acc[2][8][4];
#pragma unroll
    for (int i = 0; i < 2; i++)
#pragma unroll
        for (int j = 0; j < 8; j++)
#pragma unroll
            for (int k = 0; k < 4; k++) acc[i][j][k] = 0.f;

    const int a_r  = wm*32 + (lane & 15);
    const int a_cb = (lane >> 4) * 16;
    const int b_r  = wn*64 + (lane & 7) + ((lane >> 4) & 1)*8;
    const int b_cb = ((lane >> 3) & 1) * 16;

    const int NCH = C_ / 32;   // 24
    proj_issue_chunk(sb, Ah, Bh, m0, c0, 0, tid);

    for (int ch = 0; ch < NCH; ch++) {
        const uint32_t stb = (uint32_t)(ch & 1) * 12288u;
        cpa_wait<0>();
        __syncthreads();
        if (ch + 1 < NCH)
            proj_issue_chunk(sb + ((ch + 1) & 1) * 12288u,
                             Ah, Bh, m0, c0, (ch + 1) * 32, tid);

#pragma unroll
        for (int kk = 0; kk < 2; kk++) {
            uint32_t bfh[16];
#pragma unroll
            for (int p = 0; p < 4; p++) {
                uint32_t bo = swz64((uint32_t)((b_r + p*16) * 64 + kk*32 + b_cb));
                ldsm_x4(&bfh[p*4], sb + stb + 4096 + bo);
            }
#pragma unroll
            for (int mf = 0; mf < 2; mf++) {
                uint32_t ao = swz64((uint32_t)((a_r + mf*16) * 64 + kk*32 + a_cb));
                uint32_t ah[4];
                ldsm_x4(ah, sb + stb + ao);
#pragma unroll
                for (int p = 0; p < 4; p++) {
                    mma16816(acc[mf][2*p],   ah, &bfh[4*p]);
                    mma16816(acc[mf][2*p+1], ah, &bfh[4*p+2]);
                }
            }
        }
    }
    __syncthreads();

    float* Osm = (float*)(sm + 1024);      // [64][132]
#pragma unroll
    for (int mf = 0; mf < 2; mf++) {
#pragma unroll
        for (int nf = 0; nf < 8; nf++) {
            int row = wm*32 + mf*16 + (lane >> 2);
            int col = wn*64 + nf*8 + (lane & 3)*2;
            Osm[row       * 132 + col    ] = acc[mf][nf][0];
            Osm[row       * 132 + col + 1] = acc[mf][nf][1];
            Osm[(row + 8) * 132 + col    ] = acc[mf][nf][2];
            Osm[(row + 8) * 132 + col + 1] = acc[mf][nf][3];
        }
    }
    __syncthreads();

    float* Y = outp + (size_t)stream * BN * C_;
#pragma unroll
    for (int it = 0; it < 16; it++) {
        int idx = tid + it * 128;
        int r = idx >> 5, j4 = idx & 31;
        float4 v = *(float4*)&Osm[r * 132 + j4 * 4];
        float4 bb = *(const float4*)&bias[c0 + j4 * 4];
        v.x += bb.x; v.y += bb.y; v.z += bb.z; v.w += bb.w;
        *(float4*)&Y[(size_t)(m0 + r) * C_ + c0 + j4 * 4] = v;
    }
}

// ---------------------------------------------------------------------------
// flash attention (r13 proven): HMMA fp16, 128 q-rows/CTA, 8 warps x 16 rows.
// S = Qh*Kh (1-term).  PV 1-term.  Warp-local softmax, register P,
// cp.async 2-stage K/V, 1 barrier/tile.  smem 98304 B.
// ---------------------------------------------------------------------------
#define ASTG_ 32768u
#define AKH_ 0u
#define AVH_ 16384u
#define AQH_ 65536u

__device__ __forceinline__ void attn_issue_kv(
    uint32_t sb, uint32_t stb,
    const __half* kh_g, const __half* vh_g, int tid)
{
#pragma unroll
    for (int it = 0; it < 4; it++) {
        int idx = tid + it * 256;          // 0..1023: 64 rows x 16 16B-chunks
        int row = idx >> 4, ch = idx & 15;
        int src = row * 128 + ch * 8;
        uint32_t dst = stb + (uint32_t)(ch >> 3) * 8192 + swz((uint32_t)(row * 128 + (ch & 7) * 16));
        cpa16(sb + AKH_ + dst, kh_g + src);
        cpa16(sb + AVH_ + dst, vh_g + src);
    }
    cpa_commit();
}

__global__ __launch_bounds__(256, 1) void attn_mma()
{
    extern __shared__ char sm[];
    const uint32_t sb = smem_u32(sm);

    const int tid = threadIdx.x;
    const int lane = tid & 31, wr = tid >> 5;
    const int qt = blockIdx.x, bh = blockIdx.y;
    const int b = bh / H_, h = bh - b * H_;
    const size_t kvb = (size_t)bh * N_ * 128;

    const __half* kh_g = g_Kh + kvb;
    const __half* vh_g = g_Vh + kvb;

    attn_issue_kv(sb, 0, kh_g, vh_g, tid);

    {
        const __half* qh_g = g_Qh + kvb + (size_t)qt * 128 * 128;
#pragma unroll
        for (int it = 0; it < 8; it++) {
            int idx = tid + it * 256;
            int row = idx >> 4, ch = idx & 15;
            uint32_t dst = (uint32_t)(ch >> 3) * 16384 + swz((uint32_t)(row * 128 + (ch & 7) * 16));
            *(uint4*)(sm + AQH_ + dst) = *(const uint4*)(qh_g + row * 128 + ch * 8);
        }
    }

    float m0r = -1e30f, m1r = -1e30f, l0r = 0.f, l1r = 0.f;
    float o[16][4];
#pragma unroll
    for (int i = 0; i < 16; i++)
#pragma unroll
        for (int j = 0; j < 4; j++) o[i][j] = 0.f;

    const int qrow = wr * 16 + (lane & 15);
    const int k_r  = (lane & 7) + ((lane >> 4) & 1) * 8;
    const int k_cb = ((lane >> 3) & 1) * 16;

    for (int kt = 0; kt < 16; kt++) {
        const uint32_t stb = (uint32_t)(kt & 1) * ASTG_;
        cpa_wait<0>();
        __syncthreads();
        if (kt < 15)
            attn_issue_kv(sb, (uint32_t)((kt + 1) & 1) * ASTG_,
                          kh_g + (size_t)(kt + 1) * 64 * 128,
                          vh_g + (size_t)(kt + 1) * 64 * 128, tid);

        // ---- S = Q K^T : 16 rows x 64 cols per warp, k=128, 1-term ----
        float sacc[8][4];
#pragma unroll
        for (int i = 0; i < 8; i++)
#pragma unroll
            for (int j = 0; j < 4; j++) sacc[i][j] = 0.f;

#pragma unroll
        for (int k16 = 0; k16 < 8; k16++) {
            uint32_t qo = (uint32_t)(k16 >> 2) * 16384 +
                          swz((uint32_t)(qrow * 128 + (k16 & 3) * 32 + (lane >> 4) * 16));
            uint32_t ah[4];
            ldsm_x4(ah, sb + AQH_ + qo);
            uint32_t kpl = stb + (uint32_t)(k16 >> 2) * 8192;
            uint32_t kcb = (uint32_t)((k16 & 3) * 32) + k_cb;
            uint32_t kfh[16];
#pragma unroll
            for (int p = 0; p < 4; p++) {
                uint32_t ko = kpl + swz((uint32_t)((k_r + p*16) * 128) + kcb);
                ldsm_x4(&kfh[4*p], sb + AKH_ + ko);
            }
#pragma unroll
            for (int p = 0; p < 4; p++) {
                mma16816(sacc[2*p],   ah, &kfh[4*p]);
                mma16816(sacc[2*p+1], ah, &kfh[4*p+2]);
            }
        }

        // ---- warp-local online softmax ----
        float pm0 = -1e30f, pm1 = -1e30f;
#pragma unroll
        for (int nf = 0; nf < 8; nf++) {
            pm0 = fmaxf(pm0, fmaxf(sacc[nf][0], sacc[nf][1]));
            pm1 = fmaxf(pm1, fmaxf(sacc[nf][2], sacc[nf][3]));
        }
        pm0 = fmaxf(pm0, __shfl_xor_sync(0xffffffffu, pm0, 1));
        pm0 = fmaxf(pm0, __shfl_xor_sync(0xffffffffu, pm0, 2));
        pm1 = fmaxf(pm1, __shfl_xor_sync(0xffffffffu, pm1, 1));
        pm1 = fmaxf(pm1, __shfl_xor_sync(0xffffffffu, pm1, 2));
        float mn0 = fmaxf(m0r, pm0);
        float mn1 = fmaxf(m1r, pm1);
        float f0 = __expf(m0r - mn0);
        float f1 = __expf(m1r - mn1);
        m0r = mn0; m1r = mn1;

        uint32_t ph[4][4];
        float sum0 = 0.f, sum1 = 0.f;
#pragma unroll
        for (int g = 0; g < 4; g++) {
            float q0 = __expf(sacc[2*g][0]   - mn0);
            float q1 = __expf(sacc[2*g][1]   - mn0);
            float q2 = __expf(sacc[2*g][2]   - mn1);
            float q3 = __expf(sacc[2*g][3]   - mn1);
            float s0 = __expf(sacc[2*g+1][0] - mn0);
            float s1 = __expf(sacc[2*g+1][1] - mn0);
            float s2 = __expf(sacc[2*g+1][2] - mn1);
            float s3 = __expf(sacc[2*g+1][3] - mn1);
            sum0 += (q0 + q1) + (s0 + s1);
            sum1 += (q2 + q3) + (s2 + s3);
            ph[g][0] = pack_h2(q0, q1);
            ph[g][1] = pack_h2(q2, q3);
            ph[g][2] = pack_h2(s0, s1);
            ph[g][3] = pack_h2(s2, s3);
        }
        sum0 += __shfl_xor_sync(0xffffffffu, sum0, 1);
        sum0 += __shfl_xor_sync(0xffffffffu, sum0, 2);
        sum1 += __shfl_xor_sync(0xffffffffu, sum1, 1);
        sum1 += __shfl_xor_sync(0xffffffffu, sum1, 2);
        l0r = l0r * f0 + sum0;
        l1r = l1r * f1 + sum1;

        // ---- O = O*fac + P V : 16 rows x 128 d per warp, 1-term ----
#pragma unroll
        for (int nf = 0; nf < 16; nf++) {
            o[nf][0] *= f0; o[nf][1] *= f0;
            o[nf][2] *= f1; o[nf][3] *= f1;
        }
#pragma unroll
        for (int g = 0; g < 4; g++) {
            uint32_t vrow = (uint32_t)((g * 16 + (lane & 15)) * 128);
            uint32_t vcb  = (uint32_t)(lane >> 4) * 16;
#pragma unroll
            for (int p = 0; p < 8; p++) {
                uint32_t vo = stb + (uint32_t)(p >> 2) * 8192 +
                              swz(vrow + (uint32_t)((2*p) & 7) * 16 + vcb);
                uint32_t vh4[4];
                ldsm_x4_t(vh4, sb + AVH_ + vo);
                mma16816(o[2*p],   ph[g], &vh4[0]);
                mma16816(o[2*p+1], ph[g], &vh4[2]);
            }
        }
    }

    // ---- epilogue: normalize, write O as single fp16 (stream = nf>>3) ----
    float li0 = 1.f / l0r, li1 = 1.f / l1r;
    const int rr = wr * 16 + (lane >> 2);
#pragma unroll
    for (int nf = 0; nf < 16; nf++) {
        int strm = nf >> 3;
        int dcol = (nf & 7) * 8 + (lane & 3) * 2;
        size_t base = (size_t)strm * BN * C_
                    + ((size_t)(b * N_ + qt * 128 + rr)) * C_ + h * 64 + dcol;
        *(uint32_t*)&g_Oh[base] = pack_h2(o[nf][0] * li0, o[nf][1] * li0);
        *(uint32_t*)&g_Oh[base + 8 * C_] = pack_h2(o[nf][2] * li1, o[nf][3] * li1);
    }
}

// ---------------------------------------------------------------------------
extern "C" void kernel_launch(void* const* d_in, const int* in_sizes, int n_in,
                              void* d_out, int out_size)
{
    (void)in_sizes; (void)n_in; (void)out_size;
    const float* x1    = (const float*)d_in[0];
    const float* x2    = (const float*)d_in[1];
    const float* Wqkv  = (const float*)d_in[2];
    const float* bqkv  = (const float*)d_in[3];
    const float* Wproj = (const float*)d_in[4];
    const float* bproj = (const float*)d_in[5];
    float* out = (float*)d_out;

    split_all<<<8448, 256>>>(x1, x2, Wqkv, Wproj);

    const int qkv_smem = 68608;   // 1024 + max(2x24576 stages, Osm 128x132x4)
    cudaFuncSetAttribute(qkv_gemm, cudaFuncAttributeMaxDynamicSharedMemorySize, qkv_smem);
    qkv_gemm<<<dim3(18, 32, 2), 128, qkv_smem>>>(bqkv);

    const int attn_smem = 98304;
    cudaFuncSetAttribute(attn_mma, cudaFuncAttributeMaxDynamicSharedMemorySize, attn_smem);
    attn_mma<<<dim3(8, 48), 256, attn_smem>>>();

    const int proj_smem = 34816;  // 1024 + max(2x12288 stages, Osm 64x132x4)
    cudaFuncSetAttribute(proj_gemm, cudaFuncAttributeMaxDynamicSharedMemorySize, proj_smem);
    proj_gemm<<<dim3(6, 64, 2), 128, proj_smem>>>(bproj, out);
}

// round 15
// speedup vs baseline: 2.3409x; 1.0654x over previous
#include <cuda_runtime.h>
#include <cuda_fp16.h>
#include <cstdint>

#define B_ 4
#define N_ 1024
#define C_ 768
#define H_ 12
#define BN 4096
#define SCALE 0.125f

// ---------------- scratch (static device globals; no allocations) ----------
__device__ __align__(16) __half g_Qh[(size_t)B_*H_*N_*128];  // SCALE folded
__device__ __align__(16) __half g_Kh[(size_t)B_*H_*N_*128];
__device__ __align__(16) __half g_Vh[(size_t)B_*H_*N_*128];

__device__ __align__(16) __half g_Xh[(size_t)2*BN*C_];
__device__ __align__(16) __half g_Wqh[(size_t)3*C_*C_];
__device__ __align__(16) __half g_Wql[(size_t)3*C_*C_];
__device__ __align__(16) __half g_Wph[(size_t)C_*C_];
__device__ __align__(16) __half g_Oh[(size_t)2*BN*C_];

// ---------------- helpers ---------------------------------------------------
__device__ __forceinline__ uint32_t smem_u32(const void* p) {
    uint32_t a;
    asm("{ .reg .u64 t; cvta.to.shared.u64 t, %1; cvt.u32.u64 %0, t; }"
        : "=r"(a) : "l"(p));
    return a;
}
__device__ __forceinline__ uint32_t swz(uint32_t o) {   // 128B-row swizzle
    return o ^ ((o >> 3) & 0x70);
}
__device__ __forceinline__ void cpa16(uint32_t dst, const void* src) {
    asm volatile("cp.async.cg.shared.global [%0], [%1], 16;" :: "r"(dst), "l"(src));
}
__device__ __forceinline__ void cpa_commit() {
    asm volatile("cp.async.commit_group;" ::: "memory");
}
template<int N>
__device__ __forceinline__ void cpa_wait() {
    asm volatile("cp.async.wait_group %0;" :: "n"(N) : "memory");
}
__device__ __forceinline__ void ldsm_x4(uint32_t* r, uint32_t addr) {
    asm volatile("ldmatrix.sync.aligned.m8n8.x4.shared.b16 {%0,%1,%2,%3}, [%4];"
                 : "=r"(r[0]), "=r"(r[1]), "=r"(r[2]), "=r"(r[3]) : "r"(addr));
}
__device__ __forceinline__ void ldsm_x4_t(uint32_t* r, uint32_t addr) {
    asm volatile("ldmatrix.sync.aligned.m8n8.x4.trans.shared.b16 {%0,%1,%2,%3}, [%4];"
                 : "=r"(r[0]), "=r"(r[1]), "=r"(r[2]), "=r"(r[3]) : "r"(addr));
}
__device__ __forceinline__ void mma16816(float* d, const uint32_t* a, const uint32_t* b) {
    asm volatile(
        "mma.sync.aligned.m16n8k16.row.col.f32.f16.f16.f32 "
        "{%0,%1,%2,%3}, {%4,%5,%6,%7}, {%8,%9}, {%0,%1,%2,%3};"
        : "+f"(d[0]), "+f"(d[1]), "+f"(d[2]), "+f"(d[3])
        : "r"(a[0]), "r"(a[1]), "r"(a[2]), "r"(a[3]), "r"(b[0]), "r"(b[1]));
}
__device__ __forceinline__ uint32_t pack_h2(float a, float b) {
    __half2 t = __floats2half2_rn(a, b);
    return *(uint32_t*)&t;
}

// ---------------------------------------------------------------------------
// fused split kernel: x1,x2,Wproj -> fp16 hi only; Wqkv -> fp16 hi/lo
// ---------------------------------------------------------------------------
#define NX4  (BN * C_ / 4)          // 786432 -> 3072 blocks

__global__ __launch_bounds__(256) void split_all(
    const float* __restrict__ x1, const float* __restrict__ x2,
    const float* __restrict__ Wq, const float* __restrict__ Wp)
{
    int bid = blockIdx.x;
    const float* src;
    __half *hi, *lo;
    size_t off4;
    int i;
    bool wantLo = false;
    if (bid < 3072) {
        src = x1; hi = g_Xh; lo = nullptr; off4 = 0;
        i = bid * 256 + threadIdx.x;
    } else if (bid < 6144) {
        src = x2; hi = g_Xh; lo = nullptr; off4 = NX4;
        i = (bid - 3072) * 256 + threadIdx.x;
    } else if (bid < 7872) {
        src = Wq; hi = g_Wqh; lo = g_Wql; off4 = 0; wantLo = true;
        i = (bid - 6144) * 256 + threadIdx.x;
    } else {
        src = Wp; hi = g_Wph; lo = nullptr; off4 = 0;
        i = (bid - 7872) * 256 + threadIdx.x;
    }
    float4 v = ((const float4*)src)[i];
    size_t o = off4 + (size_t)i;
    ((uint32_t*)hi)[o*2 + 0] = pack_h2(v.x, v.y);
    ((uint32_t*)hi)[o*2 + 1] = pack_h2(v.z, v.w);
    if (wantLo) {
        __half h0 = __float2half(v.x);
        __half h1 = __float2half(v.y);
        __half h2 = __float2half(v.z);
        __half h3 = __float2half(v.w);
        ((uint32_t*)lo)[o*2 + 0] = pack_h2(v.x - __half2float(h0), v.y - __half2float(h1));
        ((uint32_t*)lo)[o*2 + 1] = pack_h2(v.z - __half2float(h2), v.w - __half2float(h3));
    }
}

// ---------------------------------------------------------------------------
// qkv GEMM: 128x128 CTA tile, 128 threads (4 warps, 64x64), K-chunk 64
// (128B-row stages), 2-stage cp.async, 12 iterations.
// Q,K tiles: 2-term (Xh*Wh + Xh*Wl).  V tiles: 1-term.
// stage = A 16KB + Bh 16KB + Bl 16KB = 48KB; alloc 1024 + 2x48KB = 99328.
// ---------------------------------------------------------------------------
__device__ __forceinline__ void gemm_issue_chunk(
    uint32_t sbase, const __half* Ah, const __half* Bh, const __half* Bl,
    int m0, int c0, int kc, int tid, bool loadBl)
{
#pragma unroll
    for (int it = 0; it < 8; it++) {
        int idx = tid + it * 128;          // 0..1023: 128 rows x 8 16B-chunks
        int r = idx >> 3, ch8 = idx & 7;
        uint32_t so = swz((uint32_t)(r * 128 + ch8 * 16));
        const size_t aoff = (size_t)(m0 + r) * C_ + kc + ch8 * 8;
        const size_t boff = (size_t)(c0 + r) * C_ + kc + ch8 * 8;
        cpa16(sbase +     0 + so, Ah + aoff);
        cpa16(sbase + 16384 + so, Bh + boff);
        if (loadBl) cpa16(sbase + 32768 + so, Bl + boff);
    }
    cpa_commit();
}

__global__ __launch_bounds__(128, 2) void qkv_gemm(const float* __restrict__ bias)
{
    extern __shared__ char sm[];
    const uint32_t sb = smem_u32(sm) + 1024;
    const int tid = threadIdx.x;
    const int lane = tid & 31, wid = tid >> 5;
    const int wm = wid & 1, wn = wid >> 1;
    const int stream = blockIdx.z;
    const int m0 = blockIdx.y * 128;
    const int c0 = blockIdx.x * 128;
    const int s_tile = c0 / C_;                 // uniform per CTA
    const bool useBl = (s_tile < 2);            // Q,K 2-term; V 1-term

    const __half* __restrict__ Ah = g_Xh + (size_t)stream * BN * C_;
    const __half* __restrict__ Bh = g_Wqh;
    const __half* __restrict__ Bl = g_Wql;

    float acc[4][8][4];
#pragma unroll
    for (int i = 0; i < 4; i++)
#pragma unroll
        for (int j = 0; j < 8; j++)
#pragma unroll
            for (int k = 0; k < 4; k++) acc[i][j][k] = 0.f;

    const int a_r  = wm*64 + (lane & 15);
    const int a_cb = (lane >> 4) * 16;
    const int b_r  = wn*64 + (lane & 7) + ((lane >> 4) & 1)*8;
    const int b_cb = ((lane >> 3) & 1) * 16;

    const int NCH = C_ / 64;   // 12
    gemm_issue_chunk(sb, Ah, Bh, Bl, m0, c0, 0, tid, useBl);

    for (int ch = 0; ch < NCH; ch++) {
        const uint32_t stb = (uint32_t)(ch & 1) * 49152u;
        cpa_wait<0>();
        __syncthreads();
        if (ch + 1 < NCH)
            gemm_issue_chunk(sb + ((ch + 1) & 1) * 49152u,
                             Ah, Bh, Bl, m0, c0, (ch + 1) * 64, tid, useBl);

#pragma unroll
        for (int kk = 0; kk < 4; kk++) {
            uint32_t bfh[16], bfl[16];
#pragma unroll
            for (int p = 0; p < 4; p++) {
                uint32_t bo = swz((uint32_t)((b_r + p*16) * 128 + kk*32 + b_cb));
                ldsm_x4(&bfh[p*4], sb + stb + 16384 + bo);
                if (useBl) ldsm_x4(&bfl[p*4], sb + stb + 32768 + bo);
            }
#pragma unroll
            for (int mf = 0; mf < 4; mf++) {
                uint32_t ao = swz((uint32_t)((a_r + mf*16) * 128 + kk*32 + a_cb));
                uint32_t ah[4];
                ldsm_x4(ah, sb + stb + ao);
#pragma unroll
                for (int p = 0; p < 4; p++) {
                    mma16816(acc[mf][2*p],   ah, &bfh[4*p]);
                    mma16816(acc[mf][2*p+1], ah, &bfh[4*p+2]);
                }
                if (useBl) {
#pragma unroll
                    for (int p = 0; p < 4; p++) {
                        mma16816(acc[mf][2*p],   ah, &bfl[4*p]);
                        mma16816(acc[mf][2*p+1], ah, &bfl[4*p+2]);
                    }
                }
            }
        }
    }
    __syncthreads();

    float* Osm = (float*)(sm + 1024);      // [128][132]
#pragma unroll
    for (int mf = 0; mf < 4; mf++) {
#pragma unroll
        for (int nf = 0; nf < 8; nf++) {
            int row = wm*64 + mf*16 + (lane >> 2);
            int col = wn*64 + nf*8 + (lane & 3)*2;
            Osm[row       * 132 + col    ] = acc[mf][nf][0];
            Osm[row       * 132 + col + 1] = acc[mf][nf][1];
            Osm[(row + 8) * 132 + col    ] = acc[mf][nf][2];
            Osm[(row + 8) * 132 + col + 1] = acc[mf][nf][3];
        }
    }
    __syncthreads();

#pragma unroll
    for (int it = 0; it < 32; it++) {
        int idx = tid + it * 128;
        int r = idx >> 5, j4 = idx & 31;
        float4 v = *(float4*)&Osm[r * 132 + j4 * 4];
        float4 bb = *(const float4*)&bias[c0 + j4 * 4];
        v.x += bb.x; v.y += bb.y; v.z += bb.z; v.w += bb.w;
        int m = m0 + r;
        int cg = c0 + j4 * 4;
        int rem = cg - s_tile * C_;
        int h = rem >> 6, d = rem & 63;
        if (s_tile == 0) { v.x *= SCALE; v.y *= SCALE; v.z *= SCALE; v.w *= SCALE; }
        uint2 hv;
        hv.x = pack_h2(v.x, v.y); hv.y = pack_h2(v.z, v.w);
        int b = m >> 10, n = m & 1023;
        size_t base = ((size_t)(b * H_ + h) * N_ + n) * 128 + stream * 64 + d;
        __half* buf = (s_tile == 0) ? g_Qh : (s_tile == 1) ? g_Kh : g_Vh;
        *(uint2*)&buf[base] = hv;
    }
}

// ---------------------------------------------------------------------------
// proj GEMM: 64x128 CTA tile, 128 threads (4 warps, 32x64 each), K-chunk 64,
// 2-stage cp.async, 1-term (Oh*Wh).  stage = A 8KB + Bh 16KB = 24KB.
// alloc = 1024 + 2x24KB = 50176 -> 3 CTAs/SM.
// ---------------------------------------------------------------------------
__device__ __forceinline__ void proj_issue_chunk(
    uint32_t sbase, const __half* Ah, const __half* Bh,
    int m0, int c0, int kc, int tid)
{
#pragma unroll
    for (int it = 0; it < 4; it++) {       // A: 64 rows x 8 16B-chunks = 512
        int idx = tid + it * 128;
        int r = idx >> 3, ch8 = idx & 7;
        uint32_t so = swz((uint32_t)(r * 128 + ch8 * 16));
        cpa16(sbase + so, Ah + (size_t)(m0 + r) * C_ + kc + ch8 * 8);
    }
#pragma unroll
    for (int it = 0; it < 8; it++) {       // Bh: 128 rows x 8 = 1024
        int idx = tid + it * 128;
        int r = idx >> 3, ch8 = idx & 7;
        uint32_t so = swz((uint32_t)(r * 128 + ch8 * 16));
        cpa16(sbase + 8192 + so, Bh + (size_t)(c0 + r) * C_ + kc + ch8 * 8);
    }
    cpa_commit();
}

__global__ __launch_bounds__(128, 3) void proj_gemm(const float* __restrict__ bias,
                                                    float* __restrict__ outp)
{
    extern __shared__ char sm[];
    const uint32_t sb = smem_u32(sm) + 1024;
    const int tid = threadIdx.x;
    const int lane = tid & 31, wid = tid >> 5;
    const int wm = wid & 1, wn = wid >> 1;
    const int stream = blockIdx.z;
    const int m0 = blockIdx.y * 64;
    const int c0 = blockIdx.x * 128;

    const __half* __restrict__ Ah = g_Oh + (size_t)stream * BN * C_;
    const __half* __restrict__ Bh = g_Wph;

    float acc[2][8][4];
#pragma unroll
    for (int i = 0; i < 2; i++)
#pragma unroll
        for (int j = 0; j < 8; j++)
#pragma unroll
            for (int k = 0; k < 4; k++) acc[i][j][k] = 0.f;

    const int a_r  = wm*32 + (lane & 15);
    const int a_cb = (lane >> 4) * 16;
    const int b_r  = wn*64 + (lane & 7) + ((lane >> 4) & 1)*8;
    const int b_cb = ((lane >> 3) & 1) * 16;

    const int NCH = C_ / 64;   // 12
    proj_issue_chunk(sb, Ah, Bh, m0, c0, 0, tid);

    for (int ch = 0; ch < NCH; ch++) {
        const uint32_t stb = (uint32_t)(ch & 1) * 24576u;
        cpa_wait<0>();
        __syncthreads();
        if (ch + 1 < NCH)
            proj_issue_chunk(sb + ((ch + 1) & 1) * 24576u,
                             Ah, Bh, m0, c0, (ch + 1) * 64, tid);

#pragma unroll
        for (int kk = 0; kk < 4; kk++) {
            uint32_t bfh[16];
#pragma unroll
            for (int p = 0; p < 4; p++) {
                uint32_t bo = swz((uint32_t)((b_r + p*16) * 128 + kk*32 + b_cb));
                ldsm_x4(&bfh[p*4], sb + stb + 8192 + bo);
            }
#pragma unroll
            for (int mf = 0; mf < 2; mf++) {
                uint32_t ao = swz((uint32_t)((a_r + mf*16) * 128 + kk*32 + a_cb));
                uint32_t ah[4];
                ldsm_x4(ah, sb + stb + ao);
#pragma unroll
                for (int p = 0; p < 4; p++) {
                    mma16816(acc[mf][2*p],   ah, &bfh[4*p]);
                    mma16816(acc[mf][2*p+1], ah, &bfh[4*p+2]);
                }
            }
        }
    }
    __syncthreads();

    float* Osm = (float*)(sm + 1024);      // [64][132]
#pragma unroll
    for (int mf = 0; mf < 2; mf++) {
#pragma unroll
        for (int nf = 0; nf < 8; nf++) {
            int row = wm*32 + mf*16 + (lane >> 2);
            int col = wn*64 + nf*8 + (lane & 3)*2;
            Osm[row       * 132 + col    ] = acc[mf][nf][0];
            Osm[row       * 132 + col + 1] = acc[mf][nf][1];
            Osm[(row + 8) * 132 + col    ] = acc[mf][nf][2];
            Osm[(row + 8) * 132 + col + 1] = acc[mf][nf][3];
        }
    }
    __syncthreads();

    float* Y = outp + (size_t)stream * BN * C_;
#pragma unroll
    for (int it = 0; it < 16; it++) {
        int idx = tid + it * 128;
        int r = idx >> 5, j4 = idx & 31;
        float4 v = *(float4*)&Osm[r * 132 + j4 * 4];
        float4 bb = *(const float4*)&bias[c0 + j4 * 4];
        v.x += bb.x; v.y += bb.y; v.z += bb.z; v.w += bb.w;
        *(float4*)&Y[(size_t)(m0 + r) * C_ + c0 + j4 * 4] = v;
    }
}

// ---------------------------------------------------------------------------
// flash attention (r13 proven): HMMA fp16, 128 q-rows/CTA, 8 warps x 16 rows.
// S = Qh*Kh (1-term).  PV 1-term.  Warp-local softmax, register P,
// cp.async 2-stage K/V, 1 barrier/tile.  smem 98304 B.
// ---------------------------------------------------------------------------
#define ASTG_ 32768u
#define AKH_ 0u
#define AVH_ 16384u
#define AQH_ 65536u

__device__ __forceinline__ void attn_issue_kv(
    uint32_t sb, uint32_t stb,
    const __half* kh_g, const __half* vh_g, int tid)
{
#pragma unroll
    for (int it = 0; it < 4; it++) {
        int idx = tid + it * 256;          // 0..1023: 64 rows x 16 16B-chunks
        int row = idx >> 4, ch = idx & 15;
        int src = row * 128 + ch * 8;
        uint32_t dst = stb + (uint32_t)(ch >> 3) * 8192 + swz((uint32_t)(row * 128 + (ch & 7) * 16));
        cpa16(sb + AKH_ + dst, kh_g + src);
        cpa16(sb + AVH_ + dst, vh_g + src);
    }
    cpa_commit();
}

__global__ __launch_bounds__(256, 1) void attn_mma()
{
    extern __shared__ char sm[];
    const uint32_t sb = smem_u32(sm);

    const int tid = threadIdx.x;
    const int lane = tid & 31, wr = tid >> 5;
    const int qt = blockIdx.x, bh = blockIdx.y;
    const int b = bh / H_, h = bh - b * H_;
    const size_t kvb = (size_t)bh * N_ * 128;

    const __half* kh_g = g_Kh + kvb;
    const __half* vh_g = g_Vh + kvb;

    attn_issue_kv(sb, 0, kh_g, vh_g, tid);

    {
        const __half* qh_g = g_Qh + kvb + (size_t)qt * 128 * 128;
#pragma unroll
        for (int it = 0; it < 8; it++) {
            int idx = tid + it * 256;
            int row = idx >> 4, ch = idx & 15;
            uint32_t dst = (uint32_t)(ch >> 3) * 16384 + swz((uint32_t)(row * 128 + (ch & 7) * 16));
            *(uint4*)(sm + AQH_ + dst) = *(const uint4*)(qh_g + row * 128 + ch * 8);
        }
    }

    float m0r = -1e30f, m1r = -1e30f, l0r = 0.f, l1r = 0.f;
    float o[16][4];
#pragma unroll
    for (int i = 0; i < 16; i++)
#pragma unroll
        for (int j = 0; j < 4; j++) o[i][j] = 0.f;

    const int qrow = wr * 16 + (lane & 15);
    const int k_r  = (lane & 7) + ((lane >> 4) & 1) * 8;
    const int k_cb = ((lane >> 3) & 1) * 16;

    for (int kt = 0; kt < 16; kt++) {
        const uint32_t stb = (uint32_t)(kt & 1) * ASTG_;
        cpa_wait<0>();
        __syncthreads();
        if (kt < 15)
            attn_issue_kv(sb, (uint32_t)((kt + 1) & 1) * ASTG_,
                          kh_g + (size_t)(kt + 1) * 64 * 128,
                          vh_g + (size_t)(kt + 1) * 64 * 128, tid);

        // ---- S = Q K^T : 16 rows x 64 cols per warp, k=128, 1-term ----
        float sacc[8][4];
#pragma unroll
        for (int i = 0; i < 8; i++)
#pragma unroll
            for (int j = 0; j < 4; j++) sacc[i][j] = 0.f;

#pragma unroll
        for (int k16 = 0; k16 < 8; k16++) {
            uint32_t qo = (uint32_t)(k16 >> 2) * 16384 +
                          swz((uint32_t)(qrow * 128 + (k16 & 3) * 32 + (lane >> 4) * 16));
            uint32_t ah[4];
            ldsm_x4(ah, sb + AQH_ + qo);
            uint32_t kpl = stb + (uint32_t)(k16 >> 2) * 8192;
            uint32_t kcb = (uint32_t)((k16 & 3) * 32) + k_cb;
            uint32_t kfh[16];
#pragma unroll
            for (int p = 0; p < 4; p++) {
                uint32_t ko = kpl + swz((uint32_t)((k_r + p*16) * 128) + kcb);
                ldsm_x4(&kfh[4*p], sb + AKH_ + ko);
            }
#pragma unroll
            for (int p = 0; p < 4; p++) {
                mma16816(sacc[2*p],   ah, &kfh[4*p]);
                mma16816(sacc[2*p+1], ah, &kfh[4*p+2]);
            }
        }

        // ---- warp-local online softmax ----
        float pm0 = -1e30f, pm1 = -1e30f;
#pragma unroll
        for (int nf = 0; nf < 8; nf++) {
            pm0 = fmaxf(pm0, fmaxf(sacc[nf][0], sacc[nf][1]));
            pm1 = fmaxf(pm1, fmaxf(sacc[nf][2], sacc[nf][3]));
        }
        pm0 = fmaxf(pm0, __shfl_xor_sync(0xffffffffu, pm0, 1));
        pm0 = fmaxf(pm0, __shfl_xor_sync(0xffffffffu, pm0, 2));
        pm1 = fmaxf(pm1, __shfl_xor_sync(0xffffffffu, pm1, 1));
        pm1 = fmaxf(pm1, __shfl_xor_sync(0xffffffffu, pm1, 2));
        float mn0 = fmaxf(m0r, pm0);
        float mn1 = fmaxf(m1r, pm1);
        float f0 = __expf(m0r - mn0);
        float f1 = __expf(m1r - mn1);
        m0r = mn0; m1r = mn1;

        uint32_t ph[4][4];
        float sum0 = 0.f, sum1 = 0.f;
#pragma unroll
        for (int g = 0; g < 4; g++) {
            float q0 = __expf(sacc[2*g][0]   - mn0);
            float q1 = __expf(sacc[2*g][1]   - mn0);
            float q2 = __expf(sacc[2*g][2]   - mn1);
            float q3 = __expf(sacc[2*g][3]   - mn1);
            float s0 = __expf(sacc[2*g+1][0] - mn0);
            float s1 = __expf(sacc[2*g+1][1] - mn0);
            float s2 = __expf(sacc[2*g+1][2] - mn1);
            float s3 = __expf(sacc[2*g+1][3] - mn1);
            sum0 += (q0 + q1) + (s0 + s1);
            sum1 += (q2 + q3) + (s2 + s3);
            ph[g][0] = pack_h2(q0, q1);
            ph[g][1] = pack_h2(q2, q3);
            ph[g][2] = pack_h2(s0, s1);
            ph[g][3] = pack_h2(s2, s3);
        }
        sum0 += __shfl_xor_sync(0xffffffffu, sum0, 1);
        sum0 += __shfl_xor_sync(0xffffffffu, sum0, 2);
        sum1 += __shfl_xor_sync(0xffffffffu, sum1, 1);
        sum1 += __shfl_xor_sync(0xffffffffu, sum1, 2);
        l0r = l0r * f0 + sum0;
        l1r = l1r * f1 + sum1;

        // ---- O = O*fac + P V : 16 rows x 128 d per warp, 1-term ----
#pragma unroll
        for (int nf = 0; nf < 16; nf++) {
            o[nf][0] *= f0; o[nf][1] *= f0;
            o[nf][2] *= f1; o[nf][3] *= f1;
        }
#pragma unroll
        for (int g = 0; g < 4; g++) {
            uint32_t vrow = (uint32_t)((g * 16 + (lane & 15)) * 128);
            uint32_t vcb  = (uint32_t)(lane >> 4) * 16;
#pragma unroll
            for (int p = 0; p < 8; p++) {
                uint32_t vo = stb + (uint32_t)(p >> 2) * 8192 +
                              swz(vrow + (uint32_t)((2*p) & 7) * 16 + vcb);
                uint32_t vh4[4];
                ldsm_x4_t(vh4, sb + AVH_ + vo);
                mma16816(o[2*p],   ph[g], &vh4[0]);
                mma16816(o[2*p+1], ph[g], &vh4[2]);
            }
        }
    }

    // ---- epilogue: normalize, write O as single fp16 (stream = nf>>3) ----
    float li0 = 1.f / l0r, li1 = 1.f / l1r;
    const int rr = wr * 16 + (lane >> 2);
#pragma unroll
    for (int nf = 0; nf < 16; nf++) {
        int strm = nf >> 3;
        int dcol = (nf & 7) * 8 + (lane & 3) * 2;
        size_t base = (size_t)strm * BN * C_
                    + ((size_t)(b * N_ + qt * 128 + rr)) * C_ + h * 64 + dcol;
        *(uint32_t*)&g_Oh[base] = pack_h2(o[nf][0] * li0, o[nf][1] * li0);
        *(uint32_t*)&g_Oh[base + 8 * C_] = pack_h2(o[nf][2] * li1, o[nf][3] * li1);
    }
}

// ---------------------------------------------------------------------------
extern "C" void kernel_launch(void* const* d_in, const int* in_sizes, int n_in,
                              void* d_out, int out_size)
{
    (void)in_sizes; (void)n_in; (void)out_size;
    const float* x1    = (const float*)d_in[0];
    const float* x2    = (const float*)d_in[1];
    const float* Wqkv  = (const float*)d_in[2];
    const float* bqkv  = (const float*)d_in[3];
    const float* Wproj = (const float*)d_in[4];
    const float* bproj = (const float*)d_in[5];
    float* out = (float*)d_out;

    split_all<<<8448, 256>>>(x1, x2, Wqkv, Wproj);

    const int qkv_smem = 99328;   // 1024 + 2x49152 stages (Osm 67584 fits)
    cudaFuncSetAttribute(qkv_gemm, cudaFuncAttributeMaxDynamicSharedMemorySize, qkv_smem);
    qkv_gemm<<<dim3(18, 32, 2), 128, qkv_smem>>>(bqkv);

    const int attn_smem = 98304;
    cudaFuncSetAttribute(attn_mma, cudaFuncAttributeMaxDynamicSharedMemorySize, attn_smem);
    attn_mma<<<dim3(8, 48), 256, attn_smem>>>();

    const int proj_smem = 50176;  // 1024 + 2x24576 stages (Osm 33792 fits)
    cudaFuncSetAttribute(proj_gemm, cudaFuncAttributeMaxDynamicSharedMemorySize, proj_smem);
    proj_gemm<<<dim3(6, 64, 2), 128, proj_smem>>>(bproj, out);
}